// round 3
// baseline (speedup 1.0000x reference)
#include <cuda_runtime.h>
#include <math.h>

#define Nn   50000
#define Ee   800000
#define INC  128
#define Hd   256
#define Gg   128
#define NEG  0.2f

// ---------------- scratch (device globals; no allocations allowed) ----------
__device__ float g_xp[(size_t)Nn * Hd];        // 51.2 MB  W-projected features
__device__ float g_h [(size_t)Nn * Hd];        // 51.2 MB  GAT output / layer IO
__device__ float g_gi[(size_t)Nn * 3 * Hd];    // 153.6 MB GRU pre-gates
__device__ float g_ssrc[Nn];
__device__ float g_sdst[Nn];
__device__ int   g_src[Ee];
__device__ int   g_dst[Ee];
__device__ int   g_batch[Nn];
__device__ int   g_cnt[Nn];
__device__ int   g_cur[Nn];
__device__ int   g_offs[Nn + 1];
__device__ int   g_adj[Ee];                    // CSR: src ids grouped by dst
__device__ int   g_is64;

// ---------------- index dtype detection + decode ----------------------------
// If the index buffers are int64 (values < 50000, non-negative), every high
// 32-bit word is zero. For int32 data those words are random node ids.
__global__ void k_detect(const int* __restrict__ ei32)
{
    int is64 = 1;
    for (int i = 0; i < 64; i++)
        if (ei32[2 * i + 1] != 0) { is64 = 0; break; }
    g_is64 = is64;
}

__global__ void k_decode_edges(const int* __restrict__ ei32)
{
    int e = blockIdx.x * blockDim.x + threadIdx.x;
    if (e >= Ee) return;
    if (g_is64) {
        g_src[e] = ei32[2 * e];
        g_dst[e] = ei32[2 * (Ee + e)];
    } else {
        g_src[e] = ei32[e];
        g_dst[e] = ei32[Ee + e];
    }
}

__global__ void k_decode_batch(const int* __restrict__ b32)
{
    int n = blockIdx.x * blockDim.x + threadIdx.x;
    if (n >= Nn) return;
    g_batch[n] = g_is64 ? b32[2 * n] : b32[n];
}

// ---------------- GEMM: C[M,Ncols] = (reluA? relu(A) : A) @ B ----------------
// BT=false: B is [K, Ncols] row-major (NN).  BT=true: B is [Ncols, K] (NT).
// Tiles: BM=128, BN=64, BK=16; 256 threads; 8x4 microtile per thread.
template<bool BT, bool RELUA>
__global__ __launch_bounds__(256) void k_gemm(const float* __restrict__ A,
                                              const float* __restrict__ B,
                                              float* __restrict__ C,
                                              int M, int Ncols, int K)
{
    __shared__ float As[16][132];   // [k][m], padded
    __shared__ float Bs[16][68];    // [k][n], padded

    const int tid = threadIdx.x;
    const int tx = tid & 15;        // 16 col-groups of 4
    const int ty = tid >> 4;        // 16 row-groups of 8
    const int row0 = blockIdx.y * 128;
    const int col0 = blockIdx.x * 64;

    float acc[8][4] = {};

    for (int kt = 0; kt < K; kt += 16) {
        #pragma unroll
        for (int i = 0; i < 2; i++) {
            int lin = tid + i * 256;          // 0..511
            int m   = lin >> 2;               // 0..127
            int k4  = lin & 3;                // 0..3
            int gm  = row0 + m;
            float4 v = make_float4(0.f, 0.f, 0.f, 0.f);
            if (gm < M)
                v = *(const float4*)(A + (size_t)gm * K + kt + k4 * 4);
            if (RELUA) {
                v.x = fmaxf(v.x, 0.f); v.y = fmaxf(v.y, 0.f);
                v.z = fmaxf(v.z, 0.f); v.w = fmaxf(v.w, 0.f);
            }
            As[k4 * 4 + 0][m] = v.x; As[k4 * 4 + 1][m] = v.y;
            As[k4 * 4 + 2][m] = v.z; As[k4 * 4 + 3][m] = v.w;
        }
        if (!BT) {
            int k  = tid >> 4;                // 0..15
            int n4 = tid & 15;                // 0..15
            float4 v = *(const float4*)(B + (size_t)(kt + k) * Ncols + col0 + n4 * 4);
            *(float4*)&Bs[k][n4 * 4] = v;
        } else {
            int n  = tid >> 2;                // 0..63
            int kq = tid & 3;                 // 0..3
            float4 v = *(const float4*)(B + (size_t)(col0 + n) * K + kt + kq * 4);
            Bs[kq * 4 + 0][n] = v.x; Bs[kq * 4 + 1][n] = v.y;
            Bs[kq * 4 + 2][n] = v.z; Bs[kq * 4 + 3][n] = v.w;
        }
        __syncthreads();

        #pragma unroll
        for (int k = 0; k < 16; k++) {
            float a[8], b[4];
            #pragma unroll
            for (int i = 0; i < 8; i++) a[i] = As[k][ty * 8 + i];
            #pragma unroll
            for (int j = 0; j < 4; j++) b[j] = Bs[k][tx * 4 + j];
            #pragma unroll
            for (int i = 0; i < 8; i++)
                #pragma unroll
                for (int j = 0; j < 4; j++)
                    acc[i][j] = fmaf(a[i], b[j], acc[i][j]);
        }
        __syncthreads();
    }

    #pragma unroll
    for (int i = 0; i < 8; i++) {
        int gm = row0 + ty * 8 + i;
        if (gm < M) {
            float4 v = make_float4(acc[i][0], acc[i][1], acc[i][2], acc[i][3]);
            *(float4*)(C + (size_t)gm * Ncols + col0 + tx * 4) = v;
        }
    }
}

// ------------------------------ CSR build -----------------------------------
__global__ void k_zero_int(void)
{
    int t = blockIdx.x * blockDim.x + threadIdx.x;
    if (t < Nn) { g_cnt[t] = 0; g_cur[t] = 0; }
}

__global__ void k_count(void)
{
    int e = blockIdx.x * blockDim.x + threadIdx.x;
    if (e >= Ee) return;
    atomicAdd(&g_cnt[g_dst[e]], 1);
}

// single-block exclusive scan of g_cnt -> g_offs (Nn+1 entries)
__global__ __launch_bounds__(1024) void k_scan(void)
{
    __shared__ int ssum[1024];
    const int CH = (Nn + 1023) / 1024;       // 49
    int tid = threadIdx.x;
    int base = tid * CH;
    int s = 0;
    for (int j = 0; j < CH; j++) {
        int idx = base + j;
        if (idx < Nn) s += g_cnt[idx];
    }
    ssum[tid] = s;
    __syncthreads();
    for (int off = 1; off < 1024; off <<= 1) {
        int v = (tid >= off) ? ssum[tid - off] : 0;
        __syncthreads();
        ssum[tid] += v;
        __syncthreads();
    }
    int run = (tid > 0) ? ssum[tid - 1] : 0;
    for (int j = 0; j < CH; j++) {
        int idx = base + j;
        if (idx < Nn) { g_offs[idx] = run; run += g_cnt[idx]; }
    }
    if (tid == 1023) g_offs[Nn] = ssum[1023];
}

__global__ void k_fill(void)
{
    int e = blockIdx.x * blockDim.x + threadIdx.x;
    if (e >= Ee) return;
    int d = g_dst[e];
    int pos = atomicAdd(&g_cur[d], 1);
    g_adj[g_offs[d] + pos] = g_src[e];
}

// ------------- per-node prep: s_src/s_dst attention dots ---------------------
__global__ __launch_bounds__(256) void k_node_prep(const float* __restrict__ xp,
                                                   const float* __restrict__ avs,
                                                   const float* __restrict__ avd)
{
    int w = (blockIdx.x * blockDim.x + threadIdx.x) >> 5;
    int lane = threadIdx.x & 31;
    if (w >= Nn) return;
    const float4* row = (const float4*)(xp + (size_t)w * Hd);
    float ss = 0.f, sd = 0.f;
    #pragma unroll
    for (int it = 0; it < 2; it++) {
        int i4 = lane + it * 32;                 // 64 float4 per row
        float4 v  = row[i4];
        float4 as = ((const float4*)avs)[i4];
        float4 ad = ((const float4*)avd)[i4];
        ss += v.x * as.x + v.y * as.y + v.z * as.z + v.w * as.w;
        sd += v.x * ad.x + v.y * ad.y + v.z * ad.z + v.w * ad.w;
    }
    #pragma unroll
    for (int o = 16; o > 0; o >>= 1) {
        ss += __shfl_down_sync(0xffffffffu, ss, o);
        sd += __shfl_down_sync(0xffffffffu, sd, o);
    }
    if (lane == 0) { g_ssrc[w] = ss; g_sdst[w] = sd; }
}

// ---------- GAT aggregation as a gather: one warp per destination node -------
__global__ __launch_bounds__(256) void k_gather(const float* __restrict__ xp,
                                                const float* __restrict__ bias,
                                                float* __restrict__ hout)
{
    int w = (blockIdx.x * blockDim.x + threadIdx.x) >> 5;
    int lane = threadIdx.x & 31;
    if (w >= Nn) return;
    int beg = g_offs[w], end = g_offs[w + 1];
    float sd = g_sdst[w];

    // ---- denominator: sum over in-edges + self loop (no max-shift; invariant)
    float part = 0.f;
    for (int i = beg + lane; i < end; i += 32) {
        float v = g_ssrc[g_adj[i]] + sd;
        v = v > 0.f ? v : NEG * v;
        part += expf(v);
    }
    #pragma unroll
    for (int o = 16; o > 0; o >>= 1) part += __shfl_xor_sync(0xffffffffu, part, o);
    float vs = g_ssrc[w] + sd;
    vs = vs > 0.f ? vs : NEG * vs;
    float ps = expf(vs);
    float invden = 1.f / (part + ps);

    // ---- accumulate: bias + self + in-edges
    float c0 = ps * invden;
    const float4* srow = (const float4*)(xp + (size_t)w * Hd);
    float4 b0 = ((const float4*)bias)[lane];
    float4 b1 = ((const float4*)bias)[lane + 32];
    float4 x0 = srow[lane], x1 = srow[lane + 32];
    float4 acc0, acc1;
    acc0.x = fmaf(c0, x0.x, b0.x); acc0.y = fmaf(c0, x0.y, b0.y);
    acc0.z = fmaf(c0, x0.z, b0.z); acc0.w = fmaf(c0, x0.w, b0.w);
    acc1.x = fmaf(c0, x1.x, b1.x); acc1.y = fmaf(c0, x1.y, b1.y);
    acc1.z = fmaf(c0, x1.z, b1.z); acc1.w = fmaf(c0, x1.w, b1.w);

    for (int i = beg; i < end; i++) {
        int s = g_adj[i];                         // same addr all lanes: broadcast
        float v = g_ssrc[s] + sd;
        v = v > 0.f ? v : NEG * v;
        float coef = expf(v) * invden;
        const float4* r = (const float4*)(xp + (size_t)s * Hd);
        float4 r0 = r[lane], r1 = r[lane + 32];
        acc0.x = fmaf(coef, r0.x, acc0.x); acc0.y = fmaf(coef, r0.y, acc0.y);
        acc0.z = fmaf(coef, r0.z, acc0.z); acc0.w = fmaf(coef, r0.w, acc0.w);
        acc1.x = fmaf(coef, r1.x, acc1.x); acc1.y = fmaf(coef, r1.y, acc1.y);
        acc1.z = fmaf(coef, r1.z, acc1.z); acc1.w = fmaf(coef, r1.w, acc1.w);
    }
    float4* od = (float4*)(hout + (size_t)w * Hd);
    od[lane] = acc0;
    od[lane + 32] = acc1;
}

// ------------------------------ GRU gates -----------------------------------
__global__ __launch_bounds__(256) void k_gru(const float* __restrict__ gi,
                                             const float* __restrict__ b_ih,
                                             const float* __restrict__ b_hh,
                                             float* __restrict__ out)
{
    int t = blockIdx.x * blockDim.x + threadIdx.x;
    if (t >= Nn * Hd) return;
    int n = t / Hd, c = t - n * Hd;
    const float* grow = gi + (size_t)n * 3 * Hd;
    float r  = 1.f / (1.f + expf(-(grow[c]          + b_ih[c]          + b_hh[c])));
    float z  = 1.f / (1.f + expf(-(grow[Hd + c]     + b_ih[Hd + c]     + b_hh[Hd + c])));
    float nv = tanhf(grow[2 * Hd + c] + b_ih[2 * Hd + c] + r * b_hh[2 * Hd + c]);
    out[t] = (1.f - z) * nv;   // + z*h0 with h0=0
}

// ------------------------------ pooling -------------------------------------
__global__ void k_zero_out(float* out, int n)
{
    int t = blockIdx.x * blockDim.x + threadIdx.x;
    if (t < n) out[t] = 0.f;
}

__global__ __launch_bounds__(256) void k_pool(const float* __restrict__ hg,
                                              float* __restrict__ out)
{
    int t = blockIdx.x * blockDim.x + threadIdx.x;
    if (t >= Nn * Hd) return;
    int n = t / Hd, c = t - n * Hd;
    int g = g_batch[n];
    atomicAdd(&out[(size_t)g * (2 * Hd) + c], hg[t]);
}

// ----------------- super node: mean -> FC -> relu -> broadcast --------------
__global__ __launch_bounds__(256) void k_super(const float* __restrict__ Wf,
                                               const float* __restrict__ bf,
                                               float* __restrict__ out)
{
    __shared__ float s[Hd];
    int j = threadIdx.x;
    float sum = 0.f;
    for (int g = 0; g < Gg; g++) sum += out[(size_t)g * (2 * Hd) + j];
    s[j] = sum / (float)Gg;
    __syncthreads();
    float v = bf[j];
    #pragma unroll 8
    for (int c = 0; c < Hd; c++) v = fmaf(s[c], Wf[(size_t)j * Hd + c], v);
    v = fmaxf(v, 0.f);
    for (int g = 0; g < Gg; g++) out[(size_t)g * (2 * Hd) + Hd + j] = v;
}

// ------------------------------ launch --------------------------------------
extern "C" void kernel_launch(void* const* d_in, const int* in_sizes, int n_in,
                              void* d_out, int out_size)
{
    const float* x      = (const float*)d_in[0];
    const int*   ei32   = (const int*)d_in[1];     // int32 or int64 (detected)
    const int*   b32    = (const int*)d_in[2];
    const float* W0     = (const float*)d_in[3];
    const float* a_src0 = (const float*)d_in[4];
    const float* a_dst0 = (const float*)d_in[5];
    const float* b0     = (const float*)d_in[6];
    const float* W1     = (const float*)d_in[7];
    const float* a_src1 = (const float*)d_in[8];
    const float* a_dst1 = (const float*)d_in[9];
    const float* b1     = (const float*)d_in[10];
    const float* W_ih   = (const float*)d_in[11];
    /* d_in[12] = W_hh: unused (h0 = 0 -> hidden gates reduce to b_hh) */
    const float* b_ih   = (const float*)d_in[13];
    const float* b_hh   = (const float*)d_in[14];
    const float* Wf     = (const float*)d_in[15];
    const float* bf     = (const float*)d_in[16];
    float*       out    = (float*)d_out;

    float *xp, *h, *gi;
    cudaGetSymbolAddress((void**)&xp, g_xp);
    cudaGetSymbolAddress((void**)&h,  g_h);
    cudaGetSymbolAddress((void**)&gi, g_gi);

    const int MT = (Nn + 127) / 128;
    dim3 blk(256);

    // ---- decode indices (handles int32 or int64 storage) ----
    k_detect<<<1, 1>>>(ei32);
    k_decode_edges<<<(Ee + 255) / 256, blk>>>(ei32);
    k_decode_batch<<<(Nn + 255) / 256, blk>>>(b32);

    // ---- CSR build (dst -> list of src) ----
    k_zero_int<<<(Nn + 255) / 256, blk>>>();
    k_count<<<(Ee + 255) / 256, blk>>>();
    k_scan<<<1, 1024>>>();
    k_fill<<<(Ee + 255) / 256, blk>>>();

    // ---- GAT layer 0 ----
    k_gemm<false, false><<<dim3(Hd / 64, MT), blk>>>(x, W0, xp, Nn, Hd, INC);
    k_node_prep<<<(Nn * 32 + 255) / 256, blk>>>(xp, a_src0, a_dst0);
    k_gather<<<(Nn * 32 + 255) / 256, blk>>>(xp, b0, h);

    // ---- GAT layer 1 (relu fused into A load) ----
    k_gemm<false, true><<<dim3(Hd / 64, MT), blk>>>(h, W1, xp, Nn, Hd, Hd);
    k_node_prep<<<(Nn * 32 + 255) / 256, blk>>>(xp, a_src1, a_dst1);
    k_gather<<<(Nn * 32 + 255) / 256, blk>>>(xp, b1, h);

    // ---- GRU: gi = relu(h) @ W_ih^T ; gates -> xp (reused as GRU output) ----
    k_gemm<true, true><<<dim3(3 * Hd / 64, MT), blk>>>(h, W_ih, gi, Nn, 3 * Hd, Hd);
    k_gru<<<(Nn * Hd + 255) / 256, blk>>>(gi, b_ih, b_hh, xp);

    // ---- pooling + super node ----
    k_zero_out<<<(Gg * 2 * Hd + 255) / 256, blk>>>(out, Gg * 2 * Hd);
    k_pool<<<(Nn * Hd + 255) / 256, blk>>>(xp, out);
    k_super<<<1, Hd>>>(Wf, bf, out);
}

// round 5
// speedup vs baseline: 1.2176x; 1.2176x over previous
#include <cuda_runtime.h>
#include <cuda_bf16.h>
#include <math.h>
#include <stdint.h>

#define Nn   50000
#define Ee   800000
#define INC  128
#define Hd   256
#define Gg   128
#define NEG  0.2f

// ---------------- scratch (device globals; no allocations allowed) ----------
__device__ float g_xp[(size_t)Nn * Hd];
__device__ float g_h [(size_t)Nn * Hd];
__device__ float g_gi[(size_t)Nn * 3 * Hd];
__device__ float g_ssrc[Nn];
__device__ float g_sdst[Nn];
__device__ int   g_src[Ee];
__device__ int   g_dst[Ee];
__device__ int   g_batch[Nn];
__device__ int   g_cnt[Nn];
__device__ int   g_cur[Nn];
__device__ int   g_offs[Nn + 1];
__device__ int   g_adj[Ee];
__device__ int   g_is64;
// bf16-split weights, stored [N][K] (B^T layout, K contiguous -> mma row.col)
__device__ __nv_bfloat16 g_bt0h[256 * 128], g_bt0l[256 * 128];
__device__ __nv_bfloat16 g_bt1h[256 * 256], g_bt1l[256 * 256];
__device__ __nv_bfloat16 g_bihh[768 * 256], g_bihl[768 * 256];

// ---------------------------- PTX helpers -----------------------------------
__device__ __forceinline__ uint32_t smem_u32(const void* p) {
    uint32_t a;
    asm("{ .reg .u64 t; cvta.to.shared.u64 t, %1; cvt.u32.u64 %0, t; }" : "=r"(a) : "l"(p));
    return a;
}
__device__ __forceinline__ void ldsm4(uint32_t& r0, uint32_t& r1, uint32_t& r2, uint32_t& r3,
                                      uint32_t addr) {
    asm volatile("ldmatrix.sync.aligned.m8n8.x4.shared.b16 {%0,%1,%2,%3}, [%4];"
                 : "=r"(r0), "=r"(r1), "=r"(r2), "=r"(r3) : "r"(addr));
}
__device__ __forceinline__ void mma16816(float* d, const uint32_t* a, const uint32_t* b) {
    asm volatile("mma.sync.aligned.m16n8k16.row.col.f32.bf16.bf16.f32 "
                 "{%0,%1,%2,%3}, {%4,%5,%6,%7}, {%8,%9}, {%0,%1,%2,%3};"
                 : "+f"(d[0]), "+f"(d[1]), "+f"(d[2]), "+f"(d[3])
                 : "r"(a[0]), "r"(a[1]), "r"(a[2]), "r"(a[3]), "r"(b[0]), "r"(b[1]));
}

// ---------------- index dtype detection + decode ----------------------------
__global__ void k_detect(const int* __restrict__ ei32)
{
    int is64 = 1;
    for (int i = 0; i < 64; i++)
        if (ei32[2 * i + 1] != 0) { is64 = 0; break; }
    g_is64 = is64;
}
__global__ void k_decode_edges(const int* __restrict__ ei32)
{
    int e = blockIdx.x * blockDim.x + threadIdx.x;
    if (e >= Ee) return;
    if (g_is64) { g_src[e] = ei32[2 * e]; g_dst[e] = ei32[2 * (Ee + e)]; }
    else        { g_src[e] = ei32[e];     g_dst[e] = ei32[Ee + e]; }
}
__global__ void k_decode_batch(const int* __restrict__ b32)
{
    int n = blockIdx.x * blockDim.x + threadIdx.x;
    if (n >= Nn) return;
    g_batch[n] = g_is64 ? b32[2 * n] : b32[n];
}

// ---------------- weight prep: transpose + bf16 hi/lo split -----------------
__device__ __forceinline__ void bf16split(float w, __nv_bfloat16& h, __nv_bfloat16& l) {
    h = __float2bfloat16(w);
    l = __float2bfloat16(w - __bfloat162float(h));
}
__global__ void k_prep_w(const float* __restrict__ W0, const float* __restrict__ W1,
                         const float* __restrict__ Wih)
{
    int t = blockIdx.x * blockDim.x + threadIdx.x;
    if (t < 256 * 128) {                       // Bt0[n][k] = W0[k][n]
        int n = t >> 7, k = t & 127;
        bf16split(W0[k * 256 + n], g_bt0h[t], g_bt0l[t]);
    }
    if (t < 256 * 256) {                       // Bt1[n][k] = W1[k][n]
        int n = t >> 8, k = t & 255;
        bf16split(W1[k * 256 + n], g_bt1h[t], g_bt1l[t]);
    }
    if (t < 768 * 256) {                       // Bih[n][k] = W_ih[n][k]
        bf16split(Wih[t], g_bihh[t], g_bihl[t]);
    }
}

// -------- mma.sync bf16 3-term GEMM: C[M,Nc] = op(A)[M,K] @ Bt[Nc,K]^T -------
// CTA tile 128x128, BK=32, 256 threads, 8 warps (2 M-groups x 4 N-groups).
// A split hi/lo in-kernel; error of dropped lo*lo term ~2^-16 relative.
#define SSTRIDE 40   // bf16 elements per SMEM row (80 B): conflict-free ldmatrix
__global__ __launch_bounds__(256) void k_mm_bf16(const float* __restrict__ A,
                                                 const __nv_bfloat16* __restrict__ BtH,
                                                 const __nv_bfloat16* __restrict__ BtL,
                                                 float* __restrict__ C,
                                                 int M, int Nc, int K, int relua)
{
    __shared__ __align__(16) __nv_bfloat16 sAh[128 * SSTRIDE];
    __shared__ __align__(16) __nv_bfloat16 sAl[128 * SSTRIDE];
    __shared__ __align__(16) __nv_bfloat16 sBh[128 * SSTRIDE];
    __shared__ __align__(16) __nv_bfloat16 sBl[128 * SSTRIDE];

    const int tid  = threadIdx.x;
    const int wid  = tid >> 5, lane = tid & 31;
    const int wm   = wid & 1, wn = wid >> 1;          // warp 64-row group, 32-col group
    const int row0 = blockIdx.y * 128, col0 = blockIdx.x * 128;

    const uint32_t uAh = smem_u32(sAh), uAl = smem_u32(sAl);
    const uint32_t uBh = smem_u32(sBh), uBl = smem_u32(sBl);

    // staging: thread handles row r = tid/2, 16-element half h = tid&1
    const int lr = tid >> 1, lh = tid & 1;
    const int agm  = row0 + lr;                       // A global row
    const bool aok = agm < M;
    const int bgn  = col0 + lr;                       // B global row (always valid)

    // per-lane ldmatrix byte offsets (within a tile row-block)
    // A tiles mi: row = wm*64+mi*16 + (lane&7) + ((lane>>3)&1)*8 ; kbyte = (lane>>4)*16
    uint32_t aoff[4];
    #pragma unroll
    for (int mi = 0; mi < 4; mi++) {
        int r = wm * 64 + mi * 16 + (lane & 7) + ((lane >> 3) & 1) * 8;
        aoff[mi] = (uint32_t)(r * (SSTRIDE * 2) + (lane >> 4) * 16);
    }
    // B tile-pairs jp: n = wn*32+jp*16 + (lane&7) + ((lane>>4)&1)*8 ; kbyte = ((lane>>3)&1)*16
    uint32_t boff[2];
    #pragma unroll
    for (int jp = 0; jp < 2; jp++) {
        int n = wn * 32 + jp * 16 + (lane & 7) + ((lane >> 4) & 1) * 8;
        boff[jp] = (uint32_t)(n * (SSTRIDE * 2) + ((lane >> 3) & 1) * 16);
    }

    float acc[4][4][4];
    #pragma unroll
    for (int i = 0; i < 4; i++)
        #pragma unroll
        for (int j = 0; j < 4; j++)
            #pragma unroll
            for (int q = 0; q < 4; q++) acc[i][j][q] = 0.f;

    const int nit = K >> 5;
    for (int kt = 0; kt < nit; kt++) {
        // ---- stage A (fp32 -> hi/lo bf16) ----
        {
            const float* ap = A + (size_t)agm * K + kt * 32 + lh * 16;
            __nv_bfloat16* dh = sAh + lr * SSTRIDE + lh * 16;
            __nv_bfloat16* dl = sAl + lr * SSTRIDE + lh * 16;
            #pragma unroll
            for (int q = 0; q < 4; q++) {
                float4 v = aok ? *(const float4*)(ap + q * 4) : make_float4(0.f, 0.f, 0.f, 0.f);
                if (relua) {
                    v.x = fmaxf(v.x, 0.f); v.y = fmaxf(v.y, 0.f);
                    v.z = fmaxf(v.z, 0.f); v.w = fmaxf(v.w, 0.f);
                }
                float f[4] = {v.x, v.y, v.z, v.w};
                #pragma unroll
                for (int e = 0; e < 4; e++) {
                    __nv_bfloat16 hb, lb;
                    bf16split(f[e], hb, lb);
                    dh[q * 4 + e] = hb;
                    dl[q * 4 + e] = lb;
                }
            }
        }
        // ---- stage B (bf16 copy) ----
        {
            const __nv_bfloat16* bh = BtH + (size_t)bgn * K + kt * 32 + lh * 16;
            const __nv_bfloat16* bl = BtL + (size_t)bgn * K + kt * 32 + lh * 16;
            *(float4*)(sBh + lr * SSTRIDE + lh * 16)     = *(const float4*)bh;
            *(float4*)(sBh + lr * SSTRIDE + lh * 16 + 8) = *(const float4*)(bh + 8);
            *(float4*)(sBl + lr * SSTRIDE + lh * 16)     = *(const float4*)bl;
            *(float4*)(sBl + lr * SSTRIDE + lh * 16 + 8) = *(const float4*)(bl + 8);
        }
        __syncthreads();

        #pragma unroll
        for (int ks = 0; ks < 2; ks++) {
            const uint32_t kb = (uint32_t)(ks * 32);
            uint32_t ah[4][4], al[4][4], bf[4][2];
            #pragma unroll
            for (int mi = 0; mi < 4; mi++) {
                ldsm4(ah[mi][0], ah[mi][1], ah[mi][2], ah[mi][3], uAh + aoff[mi] + kb);
                ldsm4(al[mi][0], al[mi][1], al[mi][2], al[mi][3], uAl + aoff[mi] + kb);
            }
            // B hi: terms Ahi*Bhi and Alo*Bhi
            #pragma unroll
            for (int jp = 0; jp < 2; jp++)
                ldsm4(bf[jp * 2][0], bf[jp * 2][1], bf[jp * 2 + 1][0], bf[jp * 2 + 1][1],
                      uBh + boff[jp] + kb);
            #pragma unroll
            for (int mi = 0; mi < 4; mi++)
                #pragma unroll
                for (int nj = 0; nj < 4; nj++) {
                    mma16816(acc[mi][nj], ah[mi], bf[nj]);
                    mma16816(acc[mi][nj], al[mi], bf[nj]);
                }
            // B lo: term Ahi*Blo
            #pragma unroll
            for (int jp = 0; jp < 2; jp++)
                ldsm4(bf[jp * 2][0], bf[jp * 2][1], bf[jp * 2 + 1][0], bf[jp * 2 + 1][1],
                      uBl + boff[jp] + kb);
            #pragma unroll
            for (int mi = 0; mi < 4; mi++)
                #pragma unroll
                for (int nj = 0; nj < 4; nj++)
                    mma16816(acc[mi][nj], ah[mi], bf[nj]);
        }
        __syncthreads();
    }

    // ---- epilogue: fragment -> global ----
    #pragma unroll
    for (int mi = 0; mi < 4; mi++) {
        int r0g = row0 + wm * 64 + mi * 16 + (lane >> 2);
        int cg  = col0 + wn * 32 + (lane & 3) * 2;
        #pragma unroll
        for (int nj = 0; nj < 4; nj++) {
            int c = cg + nj * 8;
            if (r0g < M)
                *(float2*)(C + (size_t)r0g * Nc + c) = make_float2(acc[mi][nj][0], acc[mi][nj][1]);
            if (r0g + 8 < M)
                *(float2*)(C + (size_t)(r0g + 8) * Nc + c) = make_float2(acc[mi][nj][2], acc[mi][nj][3]);
        }
    }
}

// ------------------------------ CSR build -----------------------------------
__global__ void k_zero_int(void)
{
    int t = blockIdx.x * blockDim.x + threadIdx.x;
    if (t < Nn) { g_cnt[t] = 0; g_cur[t] = 0; }
}
__global__ void k_count(void)
{
    int e = blockIdx.x * blockDim.x + threadIdx.x;
    if (e >= Ee) return;
    atomicAdd(&g_cnt[g_dst[e]], 1);
}
__global__ __launch_bounds__(1024) void k_scan(void)
{
    __shared__ int ssum[1024];
    const int CH = (Nn + 1023) / 1024;
    int tid = threadIdx.x;
    int base = tid * CH;
    int s = 0;
    for (int j = 0; j < CH; j++) {
        int idx = base + j;
        if (idx < Nn) s += g_cnt[idx];
    }
    ssum[tid] = s;
    __syncthreads();
    for (int off = 1; off < 1024; off <<= 1) {
        int v = (tid >= off) ? ssum[tid - off] : 0;
        __syncthreads();
        ssum[tid] += v;
        __syncthreads();
    }
    int run = (tid > 0) ? ssum[tid - 1] : 0;
    for (int j = 0; j < CH; j++) {
        int idx = base + j;
        if (idx < Nn) { g_offs[idx] = run; run += g_cnt[idx]; }
    }
    if (tid == 1023) g_offs[Nn] = ssum[1023];
}
__global__ void k_fill(void)
{
    int e = blockIdx.x * blockDim.x + threadIdx.x;
    if (e >= Ee) return;
    int d = g_dst[e];
    int pos = atomicAdd(&g_cur[d], 1);
    g_adj[g_offs[d] + pos] = g_src[e];
}

// ------------- per-node prep: s_src/s_dst attention dots ---------------------
__global__ __launch_bounds__(256) void k_node_prep(const float* __restrict__ xp,
                                                   const float* __restrict__ avs,
                                                   const float* __restrict__ avd)
{
    int w = (blockIdx.x * blockDim.x + threadIdx.x) >> 5;
    int lane = threadIdx.x & 31;
    if (w >= Nn) return;
    const float4* row = (const float4*)(xp + (size_t)w * Hd);
    float ss = 0.f, sd = 0.f;
    #pragma unroll
    for (int it = 0; it < 2; it++) {
        int i4 = lane + it * 32;
        float4 v  = row[i4];
        float4 as = ((const float4*)avs)[i4];
        float4 ad = ((const float4*)avd)[i4];
        ss += v.x * as.x + v.y * as.y + v.z * as.z + v.w * as.w;
        sd += v.x * ad.x + v.y * ad.y + v.z * ad.z + v.w * ad.w;
    }
    #pragma unroll
    for (int o = 16; o > 0; o >>= 1) {
        ss += __shfl_down_sync(0xffffffffu, ss, o);
        sd += __shfl_down_sync(0xffffffffu, sd, o);
    }
    if (lane == 0) { g_ssrc[w] = ss; g_sdst[w] = sd; }
}

// ---------- GAT aggregation as a gather: one warp per destination node -------
__global__ __launch_bounds__(256) void k_gather(const float* __restrict__ xp,
                                                const float* __restrict__ bias,
                                                float* __restrict__ hout)
{
    int w = (blockIdx.x * blockDim.x + threadIdx.x) >> 5;
    int lane = threadIdx.x & 31;
    if (w >= Nn) return;
    int beg = g_offs[w], end = g_offs[w + 1];
    float sd = g_sdst[w];

    float part = 0.f;
    for (int i = beg + lane; i < end; i += 32) {
        float v = g_ssrc[g_adj[i]] + sd;
        v = v > 0.f ? v : NEG * v;
        part += expf(v);
    }
    #pragma unroll
    for (int o = 16; o > 0; o >>= 1) part += __shfl_xor_sync(0xffffffffu, part, o);
    float vs = g_ssrc[w] + sd;
    vs = vs > 0.f ? vs : NEG * vs;
    float ps = expf(vs);
    float invden = 1.f / (part + ps);

    float c0 = ps * invden;
    const float4* srow = (const float4*)(xp + (size_t)w * Hd);
    float4 b0 = ((const float4*)bias)[lane];
    float4 b1 = ((const float4*)bias)[lane + 32];
    float4 x0 = srow[lane], x1 = srow[lane + 32];
    float4 acc0, acc1;
    acc0.x = fmaf(c0, x0.x, b0.x); acc0.y = fmaf(c0, x0.y, b0.y);
    acc0.z = fmaf(c0, x0.z, b0.z); acc0.w = fmaf(c0, x0.w, b0.w);
    acc1.x = fmaf(c0, x1.x, b1.x); acc1.y = fmaf(c0, x1.y, b1.y);
    acc1.z = fmaf(c0, x1.z, b1.z); acc1.w = fmaf(c0, x1.w, b1.w);

    for (int i = beg; i < end; i++) {
        int s = g_adj[i];
        float v = g_ssrc[s] + sd;
        v = v > 0.f ? v : NEG * v;
        float coef = expf(v) * invden;
        const float4* r = (const float4*)(xp + (size_t)s * Hd);
        float4 r0 = r[lane], r1 = r[lane + 32];
        acc0.x = fmaf(coef, r0.x, acc0.x); acc0.y = fmaf(coef, r0.y, acc0.y);
        acc0.z = fmaf(coef, r0.z, acc0.z); acc0.w = fmaf(coef, r0.w, acc0.w);
        acc1.x = fmaf(coef, r1.x, acc1.x); acc1.y = fmaf(coef, r1.y, acc1.y);
        acc1.z = fmaf(coef, r1.z, acc1.z); acc1.w = fmaf(coef, r1.w, acc1.w);
    }
    float4* od = (float4*)(hout + (size_t)w * Hd);
    od[lane] = acc0;
    od[lane + 32] = acc1;
}

// ------------------------------ GRU gates -----------------------------------
__global__ __launch_bounds__(256) void k_gru(const float* __restrict__ gi,
                                             const float* __restrict__ b_ih,
                                             const float* __restrict__ b_hh,
                                             float* __restrict__ out)
{
    int t = blockIdx.x * blockDim.x + threadIdx.x;
    if (t >= Nn * Hd) return;
    int n = t / Hd, c = t - n * Hd;
    const float* grow = gi + (size_t)n * 3 * Hd;
    float r  = 1.f / (1.f + expf(-(grow[c]          + b_ih[c]          + b_hh[c])));
    float z  = 1.f / (1.f + expf(-(grow[Hd + c]     + b_ih[Hd + c]     + b_hh[Hd + c])));
    float nv = tanhf(grow[2 * Hd + c] + b_ih[2 * Hd + c] + r * b_hh[2 * Hd + c]);
    out[t] = (1.f - z) * nv;
}

// ------------------------------ pooling -------------------------------------
__global__ void k_zero_out(float* out, int n)
{
    int t = blockIdx.x * blockDim.x + threadIdx.x;
    if (t < n) out[t] = 0.f;
}
__global__ __launch_bounds__(256) void k_pool(const float* __restrict__ hg,
                                              float* __restrict__ out)
{
    int t = blockIdx.x * blockDim.x + threadIdx.x;
    if (t >= Nn * Hd) return;
    int n = t / Hd, c = t - n * Hd;
    int g = g_batch[n];
    atomicAdd(&out[(size_t)g * (2 * Hd) + c], hg[t]);
}
__global__ __launch_bounds__(256) void k_super(const float* __restrict__ Wf,
                                               const float* __restrict__ bf,
                                               float* __restrict__ out)
{
    __shared__ float s[Hd];
    int j = threadIdx.x;
    float sum = 0.f;
    for (int g = 0; g < Gg; g++) sum += out[(size_t)g * (2 * Hd) + j];
    s[j] = sum / (float)Gg;
    __syncthreads();
    float v = bf[j];
    #pragma unroll 8
    for (int c = 0; c < Hd; c++) v = fmaf(s[c], Wf[(size_t)j * Hd + c], v);
    v = fmaxf(v, 0.f);
    for (int g = 0; g < Gg; g++) out[(size_t)g * (2 * Hd) + Hd + j] = v;
}

// ------------------------------ launch --------------------------------------
extern "C" void kernel_launch(void* const* d_in, const int* in_sizes, int n_in,
                              void* d_out, int out_size)
{
    const float* x      = (const float*)d_in[0];
    const int*   ei32   = (const int*)d_in[1];
    const int*   b32    = (const int*)d_in[2];
    const float* W0     = (const float*)d_in[3];
    const float* a_src0 = (const float*)d_in[4];
    const float* a_dst0 = (const float*)d_in[5];
    const float* b0     = (const float*)d_in[6];
    const float* W1     = (const float*)d_in[7];
    const float* a_src1 = (const float*)d_in[8];
    const float* a_dst1 = (const float*)d_in[9];
    const float* b1     = (const float*)d_in[10];
    const float* W_ih   = (const float*)d_in[11];
    /* d_in[12] = W_hh: unused (h0 = 0) */
    const float* b_ih   = (const float*)d_in[13];
    const float* b_hh   = (const float*)d_in[14];
    const float* Wf     = (const float*)d_in[15];
    const float* bf     = (const float*)d_in[16];
    float*       out    = (float*)d_out;

    float *xp, *h, *gi;
    __nv_bfloat16 *bt0h, *bt0l, *bt1h, *bt1l, *bihh, *bihl;
    cudaGetSymbolAddress((void**)&xp, g_xp);
    cudaGetSymbolAddress((void**)&h,  g_h);
    cudaGetSymbolAddress((void**)&gi, g_gi);
    cudaGetSymbolAddress((void**)&bt0h, g_bt0h);
    cudaGetSymbolAddress((void**)&bt0l, g_bt0l);
    cudaGetSymbolAddress((void**)&bt1h, g_bt1h);
    cudaGetSymbolAddress((void**)&bt1l, g_bt1l);
    cudaGetSymbolAddress((void**)&bihh, g_bihh);
    cudaGetSymbolAddress((void**)&bihl, g_bihl);

    const int MT = (Nn + 127) / 128;   // 391
    dim3 blk(256);

    // launches 1..5 (profiled slot 6 = GEMM L0)
    k_detect<<<1, 1>>>(ei32);
    k_decode_edges<<<(Ee + 255) / 256, blk>>>(ei32);
    k_decode_batch<<<(Nn + 255) / 256, blk>>>(b32);
    k_zero_int<<<(Nn + 255) / 256, blk>>>();
    k_prep_w<<<(768 * 256 + 255) / 256, blk>>>(W0, W1, W_ih);

    // ---- GAT layer 0 GEMM: xp = x @ W0 ----
    k_mm_bf16<<<dim3(2, MT), blk>>>(x, bt0h, bt0l, xp, Nn, Hd, INC, 0);

    // ---- CSR build (independent of GEMM) ----
    k_count<<<(Ee + 255) / 256, blk>>>();
    k_scan<<<1, 1024>>>();
    k_fill<<<(Ee + 255) / 256, blk>>>();

    // ---- GAT layer 0 attention + aggregate ----
    k_node_prep<<<(Nn * 32 + 255) / 256, blk>>>(xp, a_src0, a_dst0);
    k_gather<<<(Nn * 32 + 255) / 256, blk>>>(xp, b0, h);

    // ---- GAT layer 1 (relu fused into GEMM A load) ----
    k_mm_bf16<<<dim3(2, MT), blk>>>(h, bt1h, bt1l, xp, Nn, Hd, Hd, 1);
    k_node_prep<<<(Nn * 32 + 255) / 256, blk>>>(xp, a_src1, a_dst1);
    k_gather<<<(Nn * 32 + 255) / 256, blk>>>(xp, b1, h);

    // ---- GRU ----
    k_mm_bf16<<<dim3(6, MT), blk>>>(h, bihh, bihl, gi, Nn, 3 * Hd, Hd, 1);
    k_gru<<<(Nn * Hd + 255) / 256, blk>>>(gi, b_ih, b_hh, xp);

    // ---- pooling + super node ----
    k_zero_out<<<(Gg * 2 * Hd + 255) / 256, blk>>>(out, Gg * 2 * Hd);
    k_pool<<<(Nn * Hd + 255) / 256, blk>>>(xp, out);
    k_super<<<1, Hd>>>(Wf, bf, out);
}

// round 7
// speedup vs baseline: 1.5258x; 1.2531x over previous
#include <cuda_runtime.h>
#include <cuda_bf16.h>
#include <math.h>
#include <stdint.h>

#define Nn   50000
#define Ee   800000
#define INC  128
#define Hd   256
#define Gg   128
#define NEG  0.2f

// ---------------- scratch (device globals; no allocations allowed) ----------
__device__ float g_xp[(size_t)Nn * Hd];
__device__ float g_h [(size_t)Nn * Hd];
__device__ float g_gi[(size_t)Nn * 3 * Hd];
__device__ float g_ssrc[Nn];
__device__ float g_sdst[Nn];
__device__ int   g_src[Ee];
__device__ int   g_dst[Ee];
__device__ int   g_batch[Nn];
__device__ int   g_cnt[Nn];
__device__ int   g_cur[Nn];
__device__ int   g_offs[Nn + 1];
__device__ int   g_adj[Ee];
__device__ int   g_gstart[Gg + 1];
__device__ int   g_is64;
// bf16-split A (reused across the three GEMMs)
__device__ __nv_bfloat16 g_ah[(size_t)Nn * Hd], g_al[(size_t)Nn * Hd];
// bf16-split weights, stored [N][K] (B^T layout, K contiguous -> mma row.col)
__device__ __nv_bfloat16 g_bt0h[256 * 128], g_bt0l[256 * 128];
__device__ __nv_bfloat16 g_bt1h[256 * 256], g_bt1l[256 * 256];
__device__ __nv_bfloat16 g_bihh[768 * 256], g_bihl[768 * 256];

// ---------------------------- PTX helpers -----------------------------------
__device__ __forceinline__ uint32_t smem_u32(const void* p) {
    uint32_t a;
    asm("{ .reg .u64 t; cvta.to.shared.u64 t, %1; cvt.u32.u64 %0, t; }" : "=r"(a) : "l"(p));
    return a;
}
__device__ __forceinline__ void ldsm4(uint32_t& r0, uint32_t& r1, uint32_t& r2, uint32_t& r3,
                                      uint32_t addr) {
    asm volatile("ldmatrix.sync.aligned.m8n8.x4.shared.b16 {%0,%1,%2,%3}, [%4];"
                 : "=r"(r0), "=r"(r1), "=r"(r2), "=r"(r3) : "r"(addr));
}
__device__ __forceinline__ void mma16816(float* d, const uint32_t* a, const uint32_t* b) {
    asm volatile("mma.sync.aligned.m16n8k16.row.col.f32.bf16.bf16.f32 "
                 "{%0,%1,%2,%3}, {%4,%5,%6,%7}, {%8,%9}, {%0,%1,%2,%3};"
                 : "+f"(d[0]), "+f"(d[1]), "+f"(d[2]), "+f"(d[3])
                 : "r"(a[0]), "r"(a[1]), "r"(a[2]), "r"(a[3]), "r"(b[0]), "r"(b[1]));
}
__device__ __forceinline__ void cpa16(uint32_t dst, const void* src, uint32_t sz) {
    asm volatile("cp.async.cg.shared.global [%0], [%1], 16, %2;"
                 :: "r"(dst), "l"(src), "r"(sz) : "memory");
}
__device__ __forceinline__ void cpa_commit() {
    asm volatile("cp.async.commit_group;" ::: "memory");
}
template<int N> __device__ __forceinline__ void cpa_wait() {
    asm volatile("cp.async.wait_group %0;" :: "n"(N) : "memory");
}

// ---------------- index dtype detection + decode ----------------------------
__global__ void k_detect(const int* __restrict__ ei32)
{
    int is64 = 1;
    for (int i = 0; i < 64; i++)
        if (ei32[2 * i + 1] != 0) { is64 = 0; break; }
    g_is64 = is64;
}
__global__ void k_decode_edges(const int* __restrict__ ei32)
{
    int e = blockIdx.x * blockDim.x + threadIdx.x;
    if (e >= Ee) return;
    if (g_is64) { g_src[e] = ei32[2 * e]; g_dst[e] = ei32[2 * (Ee + e)]; }
    else        { g_src[e] = ei32[e];     g_dst[e] = ei32[Ee + e]; }
}
__global__ void k_decode_batch(const int* __restrict__ b32)
{
    int n = blockIdx.x * blockDim.x + threadIdx.x;
    if (n >= Nn) return;
    g_batch[n] = g_is64 ? b32[2 * n] : b32[n];
}

// ---------------- weight prep: transpose + bf16 hi/lo split -----------------
__device__ __forceinline__ void bf16split(float w, __nv_bfloat16& h, __nv_bfloat16& l) {
    h = __float2bfloat16(w);
    l = __float2bfloat16(w - __bfloat162float(h));
}
__global__ void k_prep_w(const float* __restrict__ W0, const float* __restrict__ W1,
                         const float* __restrict__ Wih)
{
    int t = blockIdx.x * blockDim.x + threadIdx.x;
    if (t < 256 * 128) {                       // Bt0[n][k] = W0[k][n]
        int n = t >> 7, k = t & 127;
        bf16split(W0[k * 256 + n], g_bt0h[t], g_bt0l[t]);
    }
    if (t < 256 * 256) {                       // Bt1[n][k] = W1[k][n]
        int n = t >> 8, k = t & 255;
        bf16split(W1[k * 256 + n], g_bt1h[t], g_bt1l[t]);
    }
    if (t < 768 * 256) {                       // Bih[n][k] = W_ih[n][k]
        bf16split(Wih[t], g_bihh[t], g_bihl[t]);
    }
}

// ---------------- A split: fp32 (+optional relu) -> bf16 hi/lo --------------
__global__ __launch_bounds__(256) void k_split_a(const float* __restrict__ src,
                                                 int n4, int relua)
{
    int t = blockIdx.x * blockDim.x + threadIdx.x;
    if (t >= n4) return;
    float4 v = ((const float4*)src)[t];
    if (relua) {
        v.x = fmaxf(v.x, 0.f); v.y = fmaxf(v.y, 0.f);
        v.z = fmaxf(v.z, 0.f); v.w = fmaxf(v.w, 0.f);
    }
    float f[4] = {v.x, v.y, v.z, v.w};
    ushort4 hs, ls;
    __nv_bfloat16 hb, lb;
    bf16split(f[0], hb, lb); hs.x = __bfloat16_as_ushort(hb); ls.x = __bfloat16_as_ushort(lb);
    bf16split(f[1], hb, lb); hs.y = __bfloat16_as_ushort(hb); ls.y = __bfloat16_as_ushort(lb);
    bf16split(f[2], hb, lb); hs.z = __bfloat16_as_ushort(hb); ls.z = __bfloat16_as_ushort(lb);
    bf16split(f[3], hb, lb); hs.w = __bfloat16_as_ushort(hb); ls.w = __bfloat16_as_ushort(lb);
    ((ushort4*)g_ah)[t] = hs;
    ((ushort4*)g_al)[t] = ls;
}

// -------- pipelined bf16 3-term GEMM: C[M,Nc] = Asplit[M,K] @ Bt[Nc,K]^T -----
// CTA tile 128x128, BK=32, 256 threads, 8 warps (2 M-groups x 4 N-groups).
// cp.async 2-stage double buffer; A and B both pre-split bf16 hi/lo in global.
#define SSTRIDE 40                       // bf16 per SMEM row (80 B)
#define ABYTES  (128 * SSTRIDE * 2)      // 10240 B per array
#define BUFB    (4 * ABYTES)             // 40960 B per stage
__global__ __launch_bounds__(256, 2) void k_mm_bf16(const __nv_bfloat16* __restrict__ AH,
                                                    const __nv_bfloat16* __restrict__ AL,
                                                    const __nv_bfloat16* __restrict__ BtH,
                                                    const __nv_bfloat16* __restrict__ BtL,
                                                    float* __restrict__ C,
                                                    int M, int Nc, int K)
{
    extern __shared__ char smem[];
    const uint32_t sb = smem_u32(smem);

    const int tid  = threadIdx.x;
    const int wid  = tid >> 5, lane = tid & 31;
    const int wm   = wid & 1, wn = wid >> 1;
    const int row0 = blockIdx.y * 128, col0 = blockIdx.x * 128;

    // per-lane ldmatrix byte offsets within a stage
    uint32_t aoff[4];
    #pragma unroll
    for (int mi = 0; mi < 4; mi++) {
        int r = wm * 64 + mi * 16 + (lane & 7) + ((lane >> 3) & 1) * 8;
        aoff[mi] = (uint32_t)(r * (SSTRIDE * 2) + (lane >> 4) * 16);
    }
    uint32_t boff[2];
    #pragma unroll
    for (int jp = 0; jp < 2; jp++) {
        int n = wn * 32 + jp * 16 + (lane & 7) + ((lane >> 4) & 1) * 8;
        boff[jp] = (uint32_t)(n * (SSTRIDE * 2) + ((lane >> 3) & 1) * 16);
    }

    float acc[4][4][4];
    #pragma unroll
    for (int i = 0; i < 4; i++)
        #pragma unroll
        for (int j = 0; j < 4; j++)
            #pragma unroll
            for (int q = 0; q < 4; q++) acc[i][j][q] = 0.f;

    // cp.async staging: 512 16-B chunks per array; this thread owns chunks tid, tid+256
    const int nit = K >> 5;
    auto issue = [&](int kt, int p) {
        #pragma unroll
        for (int c = 0; c < 2; c++) {
            int lin = tid + c * 256;
            int row = lin >> 2, q = lin & 3;
            uint32_t sd = sb + (uint32_t)(p * BUFB + row * (SSTRIDE * 2) + q * 16);
            int ar = row0 + row;
            uint32_t asz = (ar < M) ? 16u : 0u;
            if (ar >= M) ar = 0;
            size_t aoffg = (size_t)ar * K + kt * 32 + q * 8;
            size_t boffg = (size_t)(col0 + row) * K + kt * 32 + q * 8;
            cpa16(sd,              AH + aoffg, asz);
            cpa16(sd + ABYTES,     AL + aoffg, asz);
            cpa16(sd + 2 * ABYTES, BtH + boffg, 16u);
            cpa16(sd + 3 * ABYTES, BtL + boffg, 16u);
        }
        cpa_commit();
    };

    issue(0, 0);
    for (int kt = 0; kt < nit; kt++) {
        const int p = kt & 1;
        if (kt + 1 < nit) { issue(kt + 1, p ^ 1); cpa_wait<1>(); }
        else              { cpa_wait<0>(); }
        __syncthreads();

        const uint32_t uAh = sb + p * BUFB;
        const uint32_t uAl = uAh + ABYTES;
        const uint32_t uBh = uAh + 2 * ABYTES;
        const uint32_t uBl = uAh + 3 * ABYTES;

        #pragma unroll
        for (int ks = 0; ks < 2; ks++) {
            const uint32_t kb = (uint32_t)(ks * 32);
            uint32_t ah[4][4], al[4][4], bf[4][2];
            #pragma unroll
            for (int mi = 0; mi < 4; mi++) {
                ldsm4(ah[mi][0], ah[mi][1], ah[mi][2], ah[mi][3], uAh + aoff[mi] + kb);
                ldsm4(al[mi][0], al[mi][1], al[mi][2], al[mi][3], uAl + aoff[mi] + kb);
            }
            #pragma unroll
            for (int jp = 0; jp < 2; jp++)
                ldsm4(bf[jp * 2][0], bf[jp * 2][1], bf[jp * 2 + 1][0], bf[jp * 2 + 1][1],
                      uBh + boff[jp] + kb);
            #pragma unroll
            for (int mi = 0; mi < 4; mi++)
                #pragma unroll
                for (int nj = 0; nj < 4; nj++) {
                    mma16816(acc[mi][nj], ah[mi], bf[nj]);
                    mma16816(acc[mi][nj], al[mi], bf[nj]);
                }
            #pragma unroll
            for (int jp = 0; jp < 2; jp++)
                ldsm4(bf[jp * 2][0], bf[jp * 2][1], bf[jp * 2 + 1][0], bf[jp * 2 + 1][1],
                      uBl + boff[jp] + kb);
            #pragma unroll
            for (int mi = 0; mi < 4; mi++)
                #pragma unroll
                for (int nj = 0; nj < 4; nj++)
                    mma16816(acc[mi][nj], ah[mi], bf[nj]);
        }
        __syncthreads();
    }

    // ---- epilogue: fragment -> global ----
    #pragma unroll
    for (int mi = 0; mi < 4; mi++) {
        int r0g = row0 + wm * 64 + mi * 16 + (lane >> 2);
        int cg  = col0 + wn * 32 + (lane & 3) * 2;
        #pragma unroll
        for (int nj = 0; nj < 4; nj++) {
            int c = cg + nj * 8;
            if (r0g < M)
                *(float2*)(C + (size_t)r0g * Nc + c) = make_float2(acc[mi][nj][0], acc[mi][nj][1]);
            if (r0g + 8 < M)
                *(float2*)(C + (size_t)(r0g + 8) * Nc + c) = make_float2(acc[mi][nj][2], acc[mi][nj][3]);
        }
    }
}

// ------------------------------ CSR build -----------------------------------
__global__ void k_zero_int(void)
{
    int t = blockIdx.x * blockDim.x + threadIdx.x;
    if (t < Nn) { g_cnt[t] = 0; g_cur[t] = 0; }
}
__global__ void k_count(void)
{
    int e = blockIdx.x * blockDim.x + threadIdx.x;
    if (e >= Ee) return;
    atomicAdd(&g_cnt[g_dst[e]], 1);
}
__global__ __launch_bounds__(1024) void k_scan(void)
{
    __shared__ int ssum[1024];
    const int CH = (Nn + 1023) / 1024;
    int tid = threadIdx.x;
    int base = tid * CH;
    int s = 0;
    for (int j = 0; j < CH; j++) {
        int idx = base + j;
        if (idx < Nn) s += g_cnt[idx];
    }
    ssum[tid] = s;
    __syncthreads();
    for (int off = 1; off < 1024; off <<= 1) {
        int v = (tid >= off) ? ssum[tid - off] : 0;
        __syncthreads();
        ssum[tid] += v;
        __syncthreads();
    }
    int run = (tid > 0) ? ssum[tid - 1] : 0;
    for (int j = 0; j < CH; j++) {
        int idx = base + j;
        if (idx < Nn) { g_offs[idx] = run; run += g_cnt[idx]; }
    }
    if (tid == 1023) g_offs[Nn] = ssum[1023];
}
__global__ void k_fill(void)
{
    int e = blockIdx.x * blockDim.x + threadIdx.x;
    if (e >= Ee) return;
    int d = g_dst[e];
    int pos = atomicAdd(&g_cur[d], 1);
    g_adj[g_offs[d] + pos] = g_src[e];
}

// -------- graph boundaries (batch is sorted): gstart[g] = lower_bound(g) ----
__global__ void k_gstart(void)
{
    int g = threadIdx.x;
    if (g > Gg) return;
    if (g == Gg) { g_gstart[g] = Nn; return; }
    int lo = 0, hi = Nn;
    while (lo < hi) {
        int mid = (lo + hi) >> 1;
        if (g_batch[mid] < g) lo = mid + 1; else hi = mid;
    }
    g_gstart[g] = lo;
}

// ------------- per-node prep: s_src/s_dst attention dots ---------------------
__global__ __launch_bounds__(256) void k_node_prep(const float* __restrict__ xp,
                                                   const float* __restrict__ avs,
                                                   const float* __restrict__ avd)
{
    int w = (blockIdx.x * blockDim.x + threadIdx.x) >> 5;
    int lane = threadIdx.x & 31;
    if (w >= Nn) return;
    const float4* row = (const float4*)(xp + (size_t)w * Hd);
    float ss = 0.f, sd = 0.f;
    #pragma unroll
    for (int it = 0; it < 2; it++) {
        int i4 = lane + it * 32;
        float4 v  = row[i4];
        float4 as = ((const float4*)avs)[i4];
        float4 ad = ((const float4*)avd)[i4];
        ss += v.x * as.x + v.y * as.y + v.z * as.z + v.w * as.w;
        sd += v.x * ad.x + v.y * ad.y + v.z * ad.z + v.w * ad.w;
    }
    #pragma unroll
    for (int o = 16; o > 0; o >>= 1) {
        ss += __shfl_down_sync(0xffffffffu, ss, o);
        sd += __shfl_down_sync(0xffffffffu, sd, o);
    }
    if (lane == 0) { g_ssrc[w] = ss; g_sdst[w] = sd; }
}

// ---------- GAT aggregation as a gather: one warp per destination node -------
__global__ __launch_bounds__(256) void k_gather(const float* __restrict__ xp,
                                                const float* __restrict__ bias,
                                                float* __restrict__ hout)
{
    int w = (blockIdx.x * blockDim.x + threadIdx.x) >> 5;
    int lane = threadIdx.x & 31;
    if (w >= Nn) return;
    int beg = g_offs[w], end = g_offs[w + 1];
    float sd = g_sdst[w];

    float part = 0.f;
    for (int i = beg + lane; i < end; i += 32) {
        float v = g_ssrc[g_adj[i]] + sd;
        v = v > 0.f ? v : NEG * v;
        part += expf(v);
    }
    #pragma unroll
    for (int o = 16; o > 0; o >>= 1) part += __shfl_xor_sync(0xffffffffu, part, o);
    float vs = g_ssrc[w] + sd;
    vs = vs > 0.f ? vs : NEG * vs;
    float ps = expf(vs);
    float invden = 1.f / (part + ps);

    float c0 = ps * invden;
    const float4* srow = (const float4*)(xp + (size_t)w * Hd);
    float4 b0 = ((const float4*)bias)[lane];
    float4 b1 = ((const float4*)bias)[lane + 32];
    float4 x0 = srow[lane], x1 = srow[lane + 32];
    float4 acc0, acc1;
    acc0.x = fmaf(c0, x0.x, b0.x); acc0.y = fmaf(c0, x0.y, b0.y);
    acc0.z = fmaf(c0, x0.z, b0.z); acc0.w = fmaf(c0, x0.w, b0.w);
    acc1.x = fmaf(c0, x1.x, b1.x); acc1.y = fmaf(c0, x1.y, b1.y);
    acc1.z = fmaf(c0, x1.z, b1.z); acc1.w = fmaf(c0, x1.w, b1.w);

    for (int i = beg; i < end; i++) {
        int s = g_adj[i];
        float v = g_ssrc[s] + sd;
        v = v > 0.f ? v : NEG * v;
        float coef = expf(v) * invden;
        const float4* r = (const float4*)(xp + (size_t)s * Hd);
        float4 r0 = r[lane], r1 = r[lane + 32];
        acc0.x = fmaf(coef, r0.x, acc0.x); acc0.y = fmaf(coef, r0.y, acc0.y);
        acc0.z = fmaf(coef, r0.z, acc0.z); acc0.w = fmaf(coef, r0.w, acc0.w);
        acc1.x = fmaf(coef, r1.x, acc1.x); acc1.y = fmaf(coef, r1.y, acc1.y);
        acc1.z = fmaf(coef, r1.z, acc1.z); acc1.w = fmaf(coef, r1.w, acc1.w);
    }
    float4* od = (float4*)(hout + (size_t)w * Hd);
    od[lane] = acc0;
    od[lane + 32] = acc1;
}

// ------------------------------ GRU gates -----------------------------------
__global__ __launch_bounds__(256) void k_gru(const float* __restrict__ gi,
                                             const float* __restrict__ b_ih,
                                             const float* __restrict__ b_hh,
                                             float* __restrict__ out)
{
    int t = blockIdx.x * blockDim.x + threadIdx.x;
    if (t >= Nn * Hd) return;
    int n = t / Hd, c = t - n * Hd;
    const float* grow = gi + (size_t)n * 3 * Hd;
    float r  = 1.f / (1.f + expf(-(grow[c]          + b_ih[c]          + b_hh[c])));
    float z  = 1.f / (1.f + expf(-(grow[Hd + c]     + b_ih[Hd + c]     + b_hh[Hd + c])));
    float nv = tanhf(grow[2 * Hd + c] + b_ih[2 * Hd + c] + r * b_hh[2 * Hd + c]);
    out[t] = (1.f - z) * nv;
}

// --------------- pooling: contiguous per-graph sum (batch sorted) -----------
__global__ __launch_bounds__(128) void k_pool_g(const float* __restrict__ hg,
                                                float* __restrict__ out)
{
    int g = blockIdx.x;
    int c = blockIdx.y * 128 + threadIdx.x;
    int beg = g_gstart[g], end = g_gstart[g + 1];
    float s = 0.f;
    for (int n = beg; n < end; n++) s += hg[(size_t)n * Hd + c];
    out[(size_t)g * (2 * Hd) + c] = s;
}

__global__ __launch_bounds__(256) void k_super(const float* __restrict__ Wf,
                                               const float* __restrict__ bf,
                                               float* __restrict__ out)
{
    __shared__ float s[Hd];
    int j = threadIdx.x;
    float sum = 0.f;
    for (int g = 0; g < Gg; g++) sum += out[(size_t)g * (2 * Hd) + j];
    s[j] = sum / (float)Gg;
    __syncthreads();
    float v = bf[j];
    #pragma unroll 8
    for (int c = 0; c < Hd; c++) v = fmaf(s[c], Wf[(size_t)j * Hd + c], v);
    v = fmaxf(v, 0.f);
    for (int g = 0; g < Gg; g++) out[(size_t)g * (2 * Hd) + Hd + j] = v;
}

// ------------------------------ launch --------------------------------------
extern "C" void kernel_launch(void* const* d_in, const int* in_sizes, int n_in,
                              void* d_out, int out_size)
{
    const float* x      = (const float*)d_in[0];
    const int*   ei32   = (const int*)d_in[1];
    const int*   b32    = (const int*)d_in[2];
    const float* W0     = (const float*)d_in[3];
    const float* a_src0 = (const float*)d_in[4];
    const float* a_dst0 = (const float*)d_in[5];
    const float* b0     = (const float*)d_in[6];
    const float* W1     = (const float*)d_in[7];
    const float* a_src1 = (const float*)d_in[8];
    const float* a_dst1 = (const float*)d_in[9];
    const float* b1     = (const float*)d_in[10];
    const float* W_ih   = (const float*)d_in[11];
    /* d_in[12] = W_hh: unused (h0 = 0) */
    const float* b_ih   = (const float*)d_in[13];
    const float* b_hh   = (const float*)d_in[14];
    const float* Wf     = (const float*)d_in[15];
    const float* bf     = (const float*)d_in[16];
    float*       out    = (float*)d_out;

    float *xp, *h, *gi;
    __nv_bfloat16 *ah, *al, *bt0h, *bt0l, *bt1h, *bt1l, *bihh, *bihl;
    cudaGetSymbolAddress((void**)&xp, g_xp);
    cudaGetSymbolAddress((void**)&h,  g_h);
    cudaGetSymbolAddress((void**)&gi, g_gi);
    cudaGetSymbolAddress((void**)&ah, g_ah);
    cudaGetSymbolAddress((void**)&al, g_al);
    cudaGetSymbolAddress((void**)&bt0h, g_bt0h);
    cudaGetSymbolAddress((void**)&bt0l, g_bt0l);
    cudaGetSymbolAddress((void**)&bt1h, g_bt1h);
    cudaGetSymbolAddress((void**)&bt1l, g_bt1l);
    cudaGetSymbolAddress((void**)&bihh, g_bihh);
    cudaGetSymbolAddress((void**)&bihl, g_bihl);

    const int SMEM = 2 * BUFB;   // 81920
    cudaFuncSetAttribute(k_mm_bf16, cudaFuncAttributeMaxDynamicSharedMemorySize, SMEM);

    const int MT = (Nn + 127) / 128;   // 391
    dim3 blk(256);

    k_detect<<<1, 1>>>(ei32);
    k_decode_edges<<<(Ee + 255) / 256, blk>>>(ei32);
    k_decode_batch<<<(Nn + 255) / 256, blk>>>(b32);
    k_zero_int<<<(Nn + 255) / 256, blk>>>();
    k_prep_w<<<(768 * 256 + 255) / 256, blk>>>(W0, W1, W_ih);

    // ---- GAT layer 0 GEMM: xp = x @ W0 ----
    k_split_a<<<(Nn * INC / 4 + 255) / 256, blk>>>(x, Nn * INC / 4, 0);
    k_mm_bf16<<<dim3(2, MT), blk, SMEM>>>(ah, al, bt0h, bt0l, xp, Nn, Hd, INC);

    // ---- CSR build + graph boundaries (independent of GEMM) ----
    k_count<<<(Ee + 255) / 256, blk>>>();
    k_scan<<<1, 1024>>>();
    k_fill<<<(Ee + 255) / 256, blk>>>();
    k_gstart<<<1, Gg + 1>>>();

    // ---- GAT layer 0 attention + aggregate ----
    k_node_prep<<<(Nn * 32 + 255) / 256, blk>>>(xp, a_src0, a_dst0);
    k_gather<<<(Nn * 32 + 255) / 256, blk>>>(xp, b0, h);

    // ---- GAT layer 1 (relu fused into split) ----
    k_split_a<<<(Nn * Hd / 4 + 255) / 256, blk>>>(h, Nn * Hd / 4, 1);
    k_mm_bf16<<<dim3(2, MT), blk, SMEM>>>(ah, al, bt1h, bt1l, xp, Nn, Hd, Hd);
    k_node_prep<<<(Nn * 32 + 255) / 256, blk>>>(xp, a_src1, a_dst1);
    k_gather<<<(Nn * 32 + 255) / 256, blk>>>(xp, b1, h);

    // ---- GRU ----
    k_split_a<<<(Nn * Hd / 4 + 255) / 256, blk>>>(h, Nn * Hd / 4, 1);
    k_mm_bf16<<<dim3(6, MT), blk, SMEM>>>(ah, al, bihh, bihl, gi, Nn, 3 * Hd, Hd);
    k_gru<<<(Nn * Hd + 255) / 256, blk>>>(gi, b_ih, b_hh, xp);

    // ---- pooling + super node ----
    k_pool_g<<<dim3(Gg, 2), 128>>>(xp, out);
    k_super<<<1, Hd>>>(Wf, bf, out);
}

// round 8
// speedup vs baseline: 1.7048x; 1.1173x over previous
#include <cuda_runtime.h>
#include <cuda_fp16.h>
#include <math.h>
#include <stdint.h>

#define Nn   50000
#define Ee   800000
#define INC  128
#define Hd   256
#define Gg   128
#define NEG  0.2f

// ---------------- scratch (device globals; no allocations allowed) ----------
__device__ float g_xp[(size_t)Nn * Hd];
__device__ float g_gi[(size_t)Nn * 3 * Hd];
__device__ float g_ssrc[Nn];
__device__ float g_sdst[Nn];
__device__ int   g_src[Ee];
__device__ int   g_dst[Ee];
__device__ int   g_batch[Nn];
__device__ int   g_cnt[Nn];
__device__ int   g_cur[Nn];
__device__ int   g_offs[Nn + 1];
__device__ int   g_adj[Ee];
__device__ int   g_gstart[Gg + 1];
__device__ int   g_is64;
// fp16-split A (reused across the three GEMMs)
__device__ __half g_ah[(size_t)Nn * Hd], g_al[(size_t)Nn * Hd];
// fp16-split weights, stored [N][K] (B^T layout, K contiguous -> mma row.col)
__device__ __half g_bt0h[256 * 128], g_bt0l[256 * 128];
__device__ __half g_bt1h[256 * 256], g_bt1l[256 * 256];
__device__ __half g_bihh[768 * 256], g_bihl[768 * 256];

// ---------------------------- PTX helpers -----------------------------------
__device__ __forceinline__ uint32_t smem_u32(const void* p) {
    uint32_t a;
    asm("{ .reg .u64 t; cvta.to.shared.u64 t, %1; cvt.u32.u64 %0, t; }" : "=r"(a) : "l"(p));
    return a;
}
__device__ __forceinline__ void ldsm4(uint32_t& r0, uint32_t& r1, uint32_t& r2, uint32_t& r3,
                                      uint32_t addr) {
    asm volatile("ldmatrix.sync.aligned.m8n8.x4.shared.b16 {%0,%1,%2,%3}, [%4];"
                 : "=r"(r0), "=r"(r1), "=r"(r2), "=r"(r3) : "r"(addr));
}
__device__ __forceinline__ void mma16816(float* d, const uint32_t* a, const uint32_t* b) {
    asm volatile("mma.sync.aligned.m16n8k16.row.col.f32.f16.f16.f32 "
                 "{%0,%1,%2,%3}, {%4,%5,%6,%7}, {%8,%9}, {%0,%1,%2,%3};"
                 : "+f"(d[0]), "+f"(d[1]), "+f"(d[2]), "+f"(d[3])
                 : "r"(a[0]), "r"(a[1]), "r"(a[2]), "r"(a[3]), "r"(b[0]), "r"(b[1]));
}
__device__ __forceinline__ void cpa16(uint32_t dst, const void* src, uint32_t sz) {
    asm volatile("cp.async.cg.shared.global [%0], [%1], 16, %2;"
                 :: "r"(dst), "l"(src), "r"(sz) : "memory");
}
__device__ __forceinline__ void cpa_commit() {
    asm volatile("cp.async.commit_group;" ::: "memory");
}
template<int N> __device__ __forceinline__ void cpa_wait() {
    asm volatile("cp.async.wait_group %0;" :: "n"(N) : "memory");
}

// ---------------- fp16 hi/lo split helpers -----------------------------------
__device__ __forceinline__ void f16split(float w, __half& h, __half& l) {
    h = __float2half_rn(w);
    l = __float2half_rn(w - __half2float(h));
}
// relu + split a float4 into packed hi/lo (4 halves each as uint2)
__device__ __forceinline__ void relu_split4(float4 v, uint2& hs, uint2& ls) {
    float f[4] = {fmaxf(v.x, 0.f), fmaxf(v.y, 0.f), fmaxf(v.z, 0.f), fmaxf(v.w, 0.f)};
    ushort h[4], l[4];
    #pragma unroll
    for (int e = 0; e < 4; e++) {
        __half hb, lb;
        f16split(f[e], hb, lb);
        h[e] = __half_as_ushort(hb);
        l[e] = __half_as_ushort(lb);
    }
    hs.x = (uint32_t)h[0] | ((uint32_t)h[1] << 16);
    hs.y = (uint32_t)h[2] | ((uint32_t)h[3] << 16);
    ls.x = (uint32_t)l[0] | ((uint32_t)l[1] << 16);
    ls.y = (uint32_t)l[2] | ((uint32_t)l[3] << 16);
}

// ---------------- index dtype detection + decode ----------------------------
__global__ void k_detect(const int* __restrict__ ei32)
{
    int is64 = 1;
    for (int i = 0; i < 64; i++)
        if (ei32[2 * i + 1] != 0) { is64 = 0; break; }
    g_is64 = is64;
}
__global__ void k_decode_edges(const int* __restrict__ ei32)
{
    int e = blockIdx.x * blockDim.x + threadIdx.x;
    if (e >= Ee) return;
    if (g_is64) { g_src[e] = ei32[2 * e]; g_dst[e] = ei32[2 * (Ee + e)]; }
    else        { g_src[e] = ei32[e];     g_dst[e] = ei32[Ee + e]; }
}
__global__ void k_decode_batch(const int* __restrict__ b32)
{
    int n = blockIdx.x * blockDim.x + threadIdx.x;
    if (n >= Nn) return;
    g_batch[n] = g_is64 ? b32[2 * n] : b32[n];
}

// ---------------- weight prep: transpose + fp16 hi/lo split -----------------
__global__ void k_prep_w(const float* __restrict__ W0, const float* __restrict__ W1,
                         const float* __restrict__ Wih)
{
    int t = blockIdx.x * blockDim.x + threadIdx.x;
    if (t < 256 * 128) {                       // Bt0[n][k] = W0[k][n]
        int n = t >> 7, k = t & 127;
        f16split(W0[k * 256 + n], g_bt0h[t], g_bt0l[t]);
    }
    if (t < 256 * 256) {                       // Bt1[n][k] = W1[k][n]
        int n = t >> 8, k = t & 255;
        f16split(W1[k * 256 + n], g_bt1h[t], g_bt1l[t]);
    }
    if (t < 768 * 256) {                       // Bih[n][k] = W_ih[n][k]
        f16split(Wih[t], g_bihh[t], g_bihl[t]);
    }
}

// ---------------- A split for x: fp32 -> fp16 hi/lo --------------------------
__global__ __launch_bounds__(256) void k_split_x(const float* __restrict__ src, int n4)
{
    int t = blockIdx.x * blockDim.x + threadIdx.x;
    if (t >= n4) return;
    float4 v = ((const float4*)src)[t];
    float f[4] = {v.x, v.y, v.z, v.w};
    ushort4 hs, ls;
    __half hb, lb;
    f16split(f[0], hb, lb); hs.x = __half_as_ushort(hb); ls.x = __half_as_ushort(lb);
    f16split(f[1], hb, lb); hs.y = __half_as_ushort(hb); ls.y = __half_as_ushort(lb);
    f16split(f[2], hb, lb); hs.z = __half_as_ushort(hb); ls.z = __half_as_ushort(lb);
    f16split(f[3], hb, lb); hs.w = __half_as_ushort(hb); ls.w = __half_as_ushort(lb);
    ((ushort4*)g_ah)[t] = hs;
    ((ushort4*)g_al)[t] = ls;
}

// -------- pipelined fp16 GEMM: C[M,Nc] = Asplit[M,K] @ Bt[Nc,K]^T ------------
// NT=3: Ah*Bh + Al*Bh + Ah*Bl (error ~2^-22). NT=2: Ah*Bh + Al*Bh (~2^-11/sqrt3).
// CTA tile 128x128, BK=32, 256 threads, 8 warps (2 M-groups x 4 N-groups).
#define SSTRIDE 40                       // fp16 per SMEM row (80 B)
#define ABYTES  (128 * SSTRIDE * 2)      // 10240 B per array
#define BUFB    (4 * ABYTES)             // 40960 B per stage
template<int NT>
__global__ __launch_bounds__(256, 2) void k_mm_f16(const __half* __restrict__ AH,
                                                   const __half* __restrict__ AL,
                                                   const __half* __restrict__ BtH,
                                                   const __half* __restrict__ BtL,
                                                   float* __restrict__ C,
                                                   int M, int Nc, int K)
{
    extern __shared__ char smem[];
    const uint32_t sb = smem_u32(smem);

    const int tid  = threadIdx.x;
    const int wid  = tid >> 5, lane = tid & 31;
    const int wm   = wid & 1, wn = wid >> 1;
    const int row0 = blockIdx.y * 128, col0 = blockIdx.x * 128;

    uint32_t aoff[4];
    #pragma unroll
    for (int mi = 0; mi < 4; mi++) {
        int r = wm * 64 + mi * 16 + (lane & 7) + ((lane >> 3) & 1) * 8;
        aoff[mi] = (uint32_t)(r * (SSTRIDE * 2) + (lane >> 4) * 16);
    }
    uint32_t boff[2];
    #pragma unroll
    for (int jp = 0; jp < 2; jp++) {
        int n = wn * 32 + jp * 16 + (lane & 7) + ((lane >> 4) & 1) * 8;
        boff[jp] = (uint32_t)(n * (SSTRIDE * 2) + ((lane >> 3) & 1) * 16);
    }

    float acc[4][4][4];
    #pragma unroll
    for (int i = 0; i < 4; i++)
        #pragma unroll
        for (int j = 0; j < 4; j++)
            #pragma unroll
            for (int q = 0; q < 4; q++) acc[i][j][q] = 0.f;

    const int nit = K >> 5;
    auto issue = [&](int kt, int p) {
        #pragma unroll
        for (int c = 0; c < 2; c++) {
            int lin = tid + c * 256;
            int row = lin >> 2, q = lin & 3;
            uint32_t sd = sb + (uint32_t)(p * BUFB + row * (SSTRIDE * 2) + q * 16);
            int ar = row0 + row;
            uint32_t asz = (ar < M) ? 16u : 0u;
            if (ar >= M) ar = 0;
            size_t aoffg = (size_t)ar * K + kt * 32 + q * 8;
            size_t boffg = (size_t)(col0 + row) * K + kt * 32 + q * 8;
            cpa16(sd,              AH + aoffg, asz);
            cpa16(sd + ABYTES,     AL + aoffg, asz);
            cpa16(sd + 2 * ABYTES, BtH + boffg, 16u);
            if (NT == 3)
                cpa16(sd + 3 * ABYTES, BtL + boffg, 16u);
        }
        cpa_commit();
    };

    issue(0, 0);
    for (int kt = 0; kt < nit; kt++) {
        const int p = kt & 1;
        if (kt + 1 < nit) { issue(kt + 1, p ^ 1); cpa_wait<1>(); }
        else              { cpa_wait<0>(); }
        __syncthreads();

        const uint32_t uAh = sb + p * BUFB;
        const uint32_t uAl = uAh + ABYTES;
        const uint32_t uBh = uAh + 2 * ABYTES;
        const uint32_t uBl = uAh + 3 * ABYTES;

        #pragma unroll
        for (int ks = 0; ks < 2; ks++) {
            const uint32_t kb = (uint32_t)(ks * 32);
            uint32_t ah[4][4], al[4][4], bf[4][2];
            #pragma unroll
            for (int mi = 0; mi < 4; mi++) {
                ldsm4(ah[mi][0], ah[mi][1], ah[mi][2], ah[mi][3], uAh + aoff[mi] + kb);
                ldsm4(al[mi][0], al[mi][1], al[mi][2], al[mi][3], uAl + aoff[mi] + kb);
            }
            #pragma unroll
            for (int jp = 0; jp < 2; jp++)
                ldsm4(bf[jp * 2][0], bf[jp * 2][1], bf[jp * 2 + 1][0], bf[jp * 2 + 1][1],
                      uBh + boff[jp] + kb);
            #pragma unroll
            for (int mi = 0; mi < 4; mi++)
                #pragma unroll
                for (int nj = 0; nj < 4; nj++) {
                    mma16816(acc[mi][nj], ah[mi], bf[nj]);
                    mma16816(acc[mi][nj], al[mi], bf[nj]);
                }
            if (NT == 3) {
                #pragma unroll
                for (int jp = 0; jp < 2; jp++)
                    ldsm4(bf[jp * 2][0], bf[jp * 2][1], bf[jp * 2 + 1][0], bf[jp * 2 + 1][1],
                          uBl + boff[jp] + kb);
                #pragma unroll
                for (int mi = 0; mi < 4; mi++)
                    #pragma unroll
                    for (int nj = 0; nj < 4; nj++)
                        mma16816(acc[mi][nj], ah[mi], bf[nj]);
            }
        }
        __syncthreads();
    }

    #pragma unroll
    for (int mi = 0; mi < 4; mi++) {
        int r0g = row0 + wm * 64 + mi * 16 + (lane >> 2);
        int cg  = col0 + wn * 32 + (lane & 3) * 2;
        #pragma unroll
        for (int nj = 0; nj < 4; nj++) {
            int c = cg + nj * 8;
            if (r0g < M)
                *(float2*)(C + (size_t)r0g * Nc + c) = make_float2(acc[mi][nj][0], acc[mi][nj][1]);
            if (r0g + 8 < M)
                *(float2*)(C + (size_t)(r0g + 8) * Nc + c) = make_float2(acc[mi][nj][2], acc[mi][nj][3]);
        }
    }
}

// ------------------------------ CSR build -----------------------------------
__global__ void k_zero_int(void)
{
    int t = blockIdx.x * blockDim.x + threadIdx.x;
    if (t < Nn) { g_cnt[t] = 0; g_cur[t] = 0; }
}
__global__ void k_count(void)
{
    int e = blockIdx.x * blockDim.x + threadIdx.x;
    if (e >= Ee) return;
    atomicAdd(&g_cnt[g_dst[e]], 1);
}
__global__ __launch_bounds__(1024) void k_scan(void)
{
    __shared__ int ssum[1024];
    const int CH = (Nn + 1023) / 1024;
    int tid = threadIdx.x;
    int base = tid * CH;
    int s = 0;
    for (int j = 0; j < CH; j++) {
        int idx = base + j;
        if (idx < Nn) s += g_cnt[idx];
    }
    ssum[tid] = s;
    __syncthreads();
    for (int off = 1; off < 1024; off <<= 1) {
        int v = (tid >= off) ? ssum[tid - off] : 0;
        __syncthreads();
        ssum[tid] += v;
        __syncthreads();
    }
    int run = (tid > 0) ? ssum[tid - 1] : 0;
    for (int j = 0; j < CH; j++) {
        int idx = base + j;
        if (idx < Nn) { g_offs[idx] = run; run += g_cnt[idx]; }
    }
    if (tid == 1023) g_offs[Nn] = ssum[1023];
}
__global__ void k_fill(void)
{
    int e = blockIdx.x * blockDim.x + threadIdx.x;
    if (e >= Ee) return;
    int d = g_dst[e];
    int pos = atomicAdd(&g_cur[d], 1);
    g_adj[g_offs[d] + pos] = g_src[e];
}

// -------- graph boundaries (batch is sorted): gstart[g] = lower_bound(g) ----
__global__ void k_gstart(void)
{
    int g = threadIdx.x;
    if (g > Gg) return;
    if (g == Gg) { g_gstart[g] = Nn; return; }
    int lo = 0, hi = Nn;
    while (lo < hi) {
        int mid = (lo + hi) >> 1;
        if (g_batch[mid] < g) lo = mid + 1; else hi = mid;
    }
    g_gstart[g] = lo;
}

// ------------- per-node prep: s_src/s_dst attention dots ---------------------
__global__ __launch_bounds__(256) void k_node_prep(const float* __restrict__ xp,
                                                   const float* __restrict__ avs,
                                                   const float* __restrict__ avd)
{
    int w = (blockIdx.x * blockDim.x + threadIdx.x) >> 5;
    int lane = threadIdx.x & 31;
    if (w >= Nn) return;
    const float4* row = (const float4*)(xp + (size_t)w * Hd);
    float ss = 0.f, sd = 0.f;
    #pragma unroll
    for (int it = 0; it < 2; it++) {
        int i4 = lane + it * 32;
        float4 v  = row[i4];
        float4 as = ((const float4*)avs)[i4];
        float4 ad = ((const float4*)avd)[i4];
        ss += v.x * as.x + v.y * as.y + v.z * as.z + v.w * as.w;
        sd += v.x * ad.x + v.y * ad.y + v.z * ad.z + v.w * ad.w;
    }
    #pragma unroll
    for (int o = 16; o > 0; o >>= 1) {
        ss += __shfl_down_sync(0xffffffffu, ss, o);
        sd += __shfl_down_sync(0xffffffffu, sd, o);
    }
    if (lane == 0) { g_ssrc[w] = ss; g_sdst[w] = sd; }
}

// ---- GAT aggregation gather: one warp per dst; emits relu + fp16 hi/lo split
__global__ __launch_bounds__(256) void k_gather(const float* __restrict__ xp,
                                                const float* __restrict__ bias,
                                                __half* __restrict__ oh,
                                                __half* __restrict__ ol)
{
    int w = (blockIdx.x * blockDim.x + threadIdx.x) >> 5;
    int lane = threadIdx.x & 31;
    if (w >= Nn) return;
    int beg = g_offs[w], end = g_offs[w + 1];
    float sd = g_sdst[w];

    float part = 0.f;
    for (int i = beg + lane; i < end; i += 32) {
        float v = g_ssrc[g_adj[i]] + sd;
        v = v > 0.f ? v : NEG * v;
        part += expf(v);
    }
    #pragma unroll
    for (int o = 16; o > 0; o >>= 1) part += __shfl_xor_sync(0xffffffffu, part, o);
    float vs = g_ssrc[w] + sd;
    vs = vs > 0.f ? vs : NEG * vs;
    float ps = expf(vs);
    float invden = 1.f / (part + ps);

    float c0 = ps * invden;
    const float4* srow = (const float4*)(xp + (size_t)w * Hd);
    float4 b0 = ((const float4*)bias)[lane];
    float4 b1 = ((const float4*)bias)[lane + 32];
    float4 x0 = srow[lane], x1 = srow[lane + 32];
    float4 acc0, acc1;
    acc0.x = fmaf(c0, x0.x, b0.x); acc0.y = fmaf(c0, x0.y, b0.y);
    acc0.z = fmaf(c0, x0.z, b0.z); acc0.w = fmaf(c0, x0.w, b0.w);
    acc1.x = fmaf(c0, x1.x, b1.x); acc1.y = fmaf(c0, x1.y, b1.y);
    acc1.z = fmaf(c0, x1.z, b1.z); acc1.w = fmaf(c0, x1.w, b1.w);

    for (int i = beg; i < end; i++) {
        int s = g_adj[i];
        float v = g_ssrc[s] + sd;
        v = v > 0.f ? v : NEG * v;
        float coef = expf(v) * invden;
        const float4* r = (const float4*)(xp + (size_t)s * Hd);
        float4 r0 = r[lane], r1 = r[lane + 32];
        acc0.x = fmaf(coef, r0.x, acc0.x); acc0.y = fmaf(coef, r0.y, acc0.y);
        acc0.z = fmaf(coef, r0.z, acc0.z); acc0.w = fmaf(coef, r0.w, acc0.w);
        acc1.x = fmaf(coef, r1.x, acc1.x); acc1.y = fmaf(coef, r1.y, acc1.y);
        acc1.z = fmaf(coef, r1.z, acc1.z); acc1.w = fmaf(coef, r1.w, acc1.w);
    }
    // relu + fp16 hi/lo split, packed stores (8 B each)
    uint2 hs, ls;
    relu_split4(acc0, hs, ls);
    *(uint2*)(oh + (size_t)w * Hd + 4 * lane) = hs;
    *(uint2*)(ol + (size_t)w * Hd + 4 * lane) = ls;
    relu_split4(acc1, hs, ls);
    *(uint2*)(oh + (size_t)w * Hd + 128 + 4 * lane) = hs;
    *(uint2*)(ol + (size_t)w * Hd + 128 + 4 * lane) = ls;
}

// ------------------------------ GRU gates -----------------------------------
__global__ __launch_bounds__(256) void k_gru(const float* __restrict__ gi,
                                             const float* __restrict__ b_ih,
                                             const float* __restrict__ b_hh,
                                             float* __restrict__ out)
{
    int t = blockIdx.x * blockDim.x + threadIdx.x;
    if (t >= Nn * Hd) return;
    int n = t / Hd, c = t - n * Hd;
    const float* grow = gi + (size_t)n * 3 * Hd;
    float r  = 1.f / (1.f + expf(-(grow[c]          + b_ih[c]          + b_hh[c])));
    float z  = 1.f / (1.f + expf(-(grow[Hd + c]     + b_ih[Hd + c]     + b_hh[Hd + c])));
    float nv = tanhf(grow[2 * Hd + c] + b_ih[2 * Hd + c] + r * b_hh[2 * Hd + c]);
    out[t] = (1.f - z) * nv;
}

// --------------- pooling: contiguous per-graph sum (batch sorted) -----------
__global__ __launch_bounds__(128) void k_pool_g(const float* __restrict__ hg,
                                                float* __restrict__ out)
{
    int g = blockIdx.x;
    int c = blockIdx.y * 128 + threadIdx.x;
    int beg = g_gstart[g], end = g_gstart[g + 1];
    float s = 0.f;
    for (int n = beg; n < end; n++) s += hg[(size_t)n * Hd + c];
    out[(size_t)g * (2 * Hd) + c] = s;
}

__global__ __launch_bounds__(256) void k_super(const float* __restrict__ Wf,
                                               const float* __restrict__ bf,
                                               float* __restrict__ out)
{
    __shared__ float s[Hd];
    int j = threadIdx.x;
    float sum = 0.f;
    for (int g = 0; g < Gg; g++) sum += out[(size_t)g * (2 * Hd) + j];
    s[j] = sum / (float)Gg;
    __syncthreads();
    float v = bf[j];
    #pragma unroll 8
    for (int c = 0; c < Hd; c++) v = fmaf(s[c], Wf[(size_t)j * Hd + c], v);
    v = fmaxf(v, 0.f);
    for (int g = 0; g < Gg; g++) out[(size_t)g * (2 * Hd) + Hd + j] = v;
}

// ------------------------------ launch --------------------------------------
extern "C" void kernel_launch(void* const* d_in, const int* in_sizes, int n_in,
                              void* d_out, int out_size)
{
    const float* x      = (const float*)d_in[0];
    const int*   ei32   = (const int*)d_in[1];
    const int*   b32    = (const int*)d_in[2];
    const float* W0     = (const float*)d_in[3];
    const float* a_src0 = (const float*)d_in[4];
    const float* a_dst0 = (const float*)d_in[5];
    const float* b0     = (const float*)d_in[6];
    const float* W1     = (const float*)d_in[7];
    const float* a_src1 = (const float*)d_in[8];
    const float* a_dst1 = (const float*)d_in[9];
    const float* b1     = (const float*)d_in[10];
    const float* W_ih   = (const float*)d_in[11];
    /* d_in[12] = W_hh: unused (h0 = 0) */
    const float* b_ih   = (const float*)d_in[13];
    const float* b_hh   = (const float*)d_in[14];
    const float* Wf     = (const float*)d_in[15];
    const float* bf     = (const float*)d_in[16];
    float*       out    = (float*)d_out;

    float *xp, *gi;
    __half *ah, *al, *bt0h, *bt0l, *bt1h, *bt1l, *bihh, *bihl;
    cudaGetSymbolAddress((void**)&xp, g_xp);
    cudaGetSymbolAddress((void**)&gi, g_gi);
    cudaGetSymbolAddress((void**)&ah, g_ah);
    cudaGetSymbolAddress((void**)&al, g_al);
    cudaGetSymbolAddress((void**)&bt0h, g_bt0h);
    cudaGetSymbolAddress((void**)&bt0l, g_bt0l);
    cudaGetSymbolAddress((void**)&bt1h, g_bt1h);
    cudaGetSymbolAddress((void**)&bt1l, g_bt1l);
    cudaGetSymbolAddress((void**)&bihh, g_bihh);
    cudaGetSymbolAddress((void**)&bihl, g_bihl);

    const int SMEM = 2 * BUFB;   // 81920
    cudaFuncSetAttribute(k_mm_f16<3>, cudaFuncAttributeMaxDynamicSharedMemorySize, SMEM);
    cudaFuncSetAttribute(k_mm_f16<2>, cudaFuncAttributeMaxDynamicSharedMemorySize, SMEM);

    const int MT = (Nn + 127) / 128;   // 391
    dim3 blk(256);

    k_detect<<<1, 1>>>(ei32);
    k_decode_edges<<<(Ee + 255) / 256, blk>>>(ei32);
    k_decode_batch<<<(Nn + 255) / 256, blk>>>(b32);
    k_zero_int<<<(Nn + 255) / 256, blk>>>();
    k_prep_w<<<(768 * 256 + 255) / 256, blk>>>(W0, W1, W_ih);

    // ---- GAT layer 0 GEMM: xp = x @ W0 (3-term fp16) ----
    k_split_x<<<(Nn * INC / 4 + 255) / 256, blk>>>(x, Nn * INC / 4);
    k_mm_f16<3><<<dim3(2, MT), blk, SMEM>>>(ah, al, bt0h, bt0l, xp, Nn, Hd, INC);

    // ---- CSR build + graph boundaries ----
    k_count<<<(Ee + 255) / 256, blk>>>();
    k_scan<<<1, 1024>>>();
    k_fill<<<(Ee + 255) / 256, blk>>>();
    k_gstart<<<1, Gg + 1>>>();

    // ---- GAT layer 0 attention + aggregate (emits relu-split fp16) ----
    k_node_prep<<<(Nn * 32 + 255) / 256, blk>>>(xp, a_src0, a_dst0);
    k_gather<<<(Nn * 32 + 255) / 256, blk>>>(xp, b0, ah, al);

    // ---- GAT layer 1 (3-term fp16) ----
    k_mm_f16<3><<<dim3(2, MT), blk, SMEM>>>(ah, al, bt1h, bt1l, xp, Nn, Hd, Hd);
    k_node_prep<<<(Nn * 32 + 255) / 256, blk>>>(xp, a_src1, a_dst1);
    k_gather<<<(Nn * 32 + 255) / 256, blk>>>(xp, b1, ah, al);

    // ---- GRU (2-term fp16) ----
    k_mm_f16<2><<<dim3(6, MT), blk, SMEM>>>(ah, al, bihh, bihl, gi, Nn, 3 * Hd, Hd);
    k_gru<<<(Nn * Hd + 255) / 256, blk>>>(gi, b_ih, b_hh, xp);

    // ---- pooling + super node ----
    k_pool_g<<<dim3(Gg, 2), 128>>>(xp, out);
    k_super<<<1, Hd>>>(Wf, bf, out);
}

// round 9
// speedup vs baseline: 1.7458x; 1.0241x over previous
#include <cuda_runtime.h>
#include <cuda_fp16.h>
#include <math.h>
#include <stdint.h>

#define Nn   50000
#define Ee   800000
#define INC  128
#define Hd   256
#define Gg   128
#define NEG  0.2f

// ---------------- scratch (device globals; no allocations allowed) ----------
__device__ float g_xp[(size_t)Nn * Hd];
__device__ float g_ssrc[Nn];
__device__ float g_sdst[Nn];
__device__ int   g_src[Ee];
__device__ int   g_dst[Ee];
__device__ int   g_batch[Nn];
__device__ int   g_cnt[Nn];
__device__ int   g_cur[Nn];
__device__ int   g_offs[Nn + 1];
__device__ int   g_adj[Ee];
__device__ int   g_gstart[Gg + 1];
__device__ int   g_is64;
// fp16-split A (reused across the three GEMMs)
__device__ __half g_ah[(size_t)Nn * Hd], g_al[(size_t)Nn * Hd];
// fp16-split weights, stored [N][K] (B^T layout, K contiguous -> mma row.col)
__device__ __half g_bt0h[256 * 128], g_bt0l[256 * 128];
__device__ __half g_bt1h[256 * 256];
__device__ __half g_bihh[768 * 256];

// ---------------------------- PTX helpers -----------------------------------
__device__ __forceinline__ uint32_t smem_u32(const void* p) {
    uint32_t a;
    asm("{ .reg .u64 t; cvta.to.shared.u64 t, %1; cvt.u32.u64 %0, t; }" : "=r"(a) : "l"(p));
    return a;
}
__device__ __forceinline__ void ldsm4(uint32_t& r0, uint32_t& r1, uint32_t& r2, uint32_t& r3,
                                      uint32_t addr) {
    asm volatile("ldmatrix.sync.aligned.m8n8.x4.shared.b16 {%0,%1,%2,%3}, [%4];"
                 : "=r"(r0), "=r"(r1), "=r"(r2), "=r"(r3) : "r"(addr));
}
__device__ __forceinline__ void mma16816(float* d, const uint32_t* a, const uint32_t* b) {
    asm volatile("mma.sync.aligned.m16n8k16.row.col.f32.f16.f16.f32 "
                 "{%0,%1,%2,%3}, {%4,%5,%6,%7}, {%8,%9}, {%0,%1,%2,%3};"
                 : "+f"(d[0]), "+f"(d[1]), "+f"(d[2]), "+f"(d[3])
                 : "r"(a[0]), "r"(a[1]), "r"(a[2]), "r"(a[3]), "r"(b[0]), "r"(b[1]));
}
__device__ __forceinline__ void cpa16(uint32_t dst, const void* src, uint32_t sz) {
    asm volatile("cp.async.cg.shared.global [%0], [%1], 16, %2;"
                 :: "r"(dst), "l"(src), "r"(sz) : "memory");
}
__device__ __forceinline__ void cpa_commit() {
    asm volatile("cp.async.commit_group;" ::: "memory");
}
template<int N> __device__ __forceinline__ void cpa_wait() {
    asm volatile("cp.async.wait_group %0;" :: "n"(N) : "memory");
}

// ---------------- fp16 hi/lo split helpers -----------------------------------
__device__ __forceinline__ void f16split(float w, __half& h, __half& l) {
    h = __float2half_rn(w);
    l = __float2half_rn(w - __half2float(h));
}
__device__ __forceinline__ void relu_split4(float4 v, uint2& hs, uint2& ls) {
    float f[4] = {fmaxf(v.x, 0.f), fmaxf(v.y, 0.f), fmaxf(v.z, 0.f), fmaxf(v.w, 0.f)};
    ushort h[4], l[4];
    #pragma unroll
    for (int e = 0; e < 4; e++) {
        __half hb, lb;
        f16split(f[e], hb, lb);
        h[e] = __half_as_ushort(hb);
        l[e] = __half_as_ushort(lb);
    }
    hs.x = (uint32_t)h[0] | ((uint32_t)h[1] << 16);
    hs.y = (uint32_t)h[2] | ((uint32_t)h[3] << 16);
    ls.x = (uint32_t)l[0] | ((uint32_t)l[1] << 16);
    ls.y = (uint32_t)l[2] | ((uint32_t)l[3] << 16);
}

// ---------------- index dtype detection + decode ----------------------------
__global__ void k_detect(const int* __restrict__ ei32)
{
    int is64 = 1;
    for (int i = 0; i < 64; i++)
        if (ei32[2 * i + 1] != 0) { is64 = 0; break; }
    g_is64 = is64;
}
// batch decode + zero cnt/cur
__global__ void k_decode_batch(const int* __restrict__ b32)
{
    int n = blockIdx.x * blockDim.x + threadIdx.x;
    if (n >= Nn) return;
    g_batch[n] = g_is64 ? b32[2 * n] : b32[n];
    g_cnt[n] = 0;
    g_cur[n] = 0;
}
// edge decode + degree count
__global__ void k_decode_count(const int* __restrict__ ei32)
{
    int e = blockIdx.x * blockDim.x + threadIdx.x;
    if (e >= Ee) return;
    int s, d;
    if (g_is64) { s = ei32[2 * e]; d = ei32[2 * (Ee + e)]; }
    else        { s = ei32[e];     d = ei32[Ee + e]; }
    g_src[e] = s;
    g_dst[e] = d;
    atomicAdd(&g_cnt[d], 1);
}

// ---------------- weight prep: transpose + fp16 hi/lo split -----------------
__global__ void k_prep_w(const float* __restrict__ W0, const float* __restrict__ W1,
                         const float* __restrict__ Wih)
{
    int t = blockIdx.x * blockDim.x + threadIdx.x;
    if (t < 256 * 128) {                       // Bt0[n][k] = W0[k][n]
        int n = t >> 7, k = t & 127;
        f16split(W0[k * 256 + n], g_bt0h[t], g_bt0l[t]);
    }
    if (t < 256 * 256) {                       // Bt1[n][k] = W1[k][n]  (hi only, 2-term)
        int n = t >> 8, k = t & 255;
        g_bt1h[t] = __float2half_rn(W1[k * 256 + n]);
    }
    if (t < 768 * 256) {                       // Bih[n][k] = W_ih[n][k] (hi only)
        g_bihh[t] = __float2half_rn(Wih[t]);
    }
}

// ---------------- A split for x: fp32 -> fp16 hi/lo --------------------------
__global__ __launch_bounds__(256) void k_split_x(const float* __restrict__ src, int n4)
{
    int t = blockIdx.x * blockDim.x + threadIdx.x;
    if (t >= n4) return;
    float4 v = ((const float4*)src)[t];
    float f[4] = {v.x, v.y, v.z, v.w};
    ushort4 hs, ls;
    __half hb, lb;
    f16split(f[0], hb, lb); hs.x = __half_as_ushort(hb); ls.x = __half_as_ushort(lb);
    f16split(f[1], hb, lb); hs.y = __half_as_ushort(hb); ls.y = __half_as_ushort(lb);
    f16split(f[2], hb, lb); hs.z = __half_as_ushort(hb); ls.z = __half_as_ushort(lb);
    f16split(f[3], hb, lb); hs.w = __half_as_ushort(hb); ls.w = __half_as_ushort(lb);
    ((ushort4*)g_ah)[t] = hs;
    ((ushort4*)g_al)[t] = ls;
}

// -------- pipelined fp16 GEMM: C[M,Nc] = Asplit[M,K] @ Bt[Nc,K]^T ------------
// NT=3: Ah*Bh + Al*Bh + Ah*Bl. NT=2: Ah*Bh + Al*Bh.
#define SSTRIDE 40                       // fp16 per SMEM row (80 B)
#define ABYTES  (128 * SSTRIDE * 2)      // 10240 B per array
#define BUFB    (4 * ABYTES)             // 40960 B per stage
template<int NT>
__global__ __launch_bounds__(256, 2) void k_mm_f16(const __half* __restrict__ AH,
                                                   const __half* __restrict__ AL,
                                                   const __half* __restrict__ BtH,
                                                   const __half* __restrict__ BtL,
                                                   float* __restrict__ C,
                                                   int M, int Nc, int K)
{
    extern __shared__ char smem[];
    const uint32_t sb = smem_u32(smem);

    const int tid  = threadIdx.x;
    const int wid  = tid >> 5, lane = tid & 31;
    const int wm   = wid & 1, wn = wid >> 1;
    const int row0 = blockIdx.y * 128, col0 = blockIdx.x * 128;

    uint32_t aoff[4];
    #pragma unroll
    for (int mi = 0; mi < 4; mi++) {
        int r = wm * 64 + mi * 16 + (lane & 7) + ((lane >> 3) & 1) * 8;
        aoff[mi] = (uint32_t)(r * (SSTRIDE * 2) + (lane >> 4) * 16);
    }
    uint32_t boff[2];
    #pragma unroll
    for (int jp = 0; jp < 2; jp++) {
        int n = wn * 32 + jp * 16 + (lane & 7) + ((lane >> 4) & 1) * 8;
        boff[jp] = (uint32_t)(n * (SSTRIDE * 2) + ((lane >> 3) & 1) * 16);
    }

    float acc[4][4][4];
    #pragma unroll
    for (int i = 0; i < 4; i++)
        #pragma unroll
        for (int j = 0; j < 4; j++)
            #pragma unroll
            for (int q = 0; q < 4; q++) acc[i][j][q] = 0.f;

    const int nit = K >> 5;
    auto issue = [&](int kt, int p) {
        #pragma unroll
        for (int c = 0; c < 2; c++) {
            int lin = tid + c * 256;
            int row = lin >> 2, q = lin & 3;
            uint32_t sd = sb + (uint32_t)(p * BUFB + row * (SSTRIDE * 2) + q * 16);
            int ar = row0 + row;
            uint32_t asz = (ar < M) ? 16u : 0u;
            if (ar >= M) ar = 0;
            size_t aoffg = (size_t)ar * K + kt * 32 + q * 8;
            size_t boffg = (size_t)(col0 + row) * K + kt * 32 + q * 8;
            cpa16(sd,              AH + aoffg, asz);
            cpa16(sd + ABYTES,     AL + aoffg, asz);
            cpa16(sd + 2 * ABYTES, BtH + boffg, 16u);
            if (NT == 3)
                cpa16(sd + 3 * ABYTES, BtL + boffg, 16u);
        }
        cpa_commit();
    };

    issue(0, 0);
    for (int kt = 0; kt < nit; kt++) {
        const int p = kt & 1;
        if (kt + 1 < nit) { issue(kt + 1, p ^ 1); cpa_wait<1>(); }
        else              { cpa_wait<0>(); }
        __syncthreads();

        const uint32_t uAh = sb + p * BUFB;
        const uint32_t uAl = uAh + ABYTES;
        const uint32_t uBh = uAh + 2 * ABYTES;
        const uint32_t uBl = uAh + 3 * ABYTES;

        #pragma unroll
        for (int ks = 0; ks < 2; ks++) {
            const uint32_t kb = (uint32_t)(ks * 32);
            uint32_t ah[4][4], al[4][4], bf[4][2];
            #pragma unroll
            for (int mi = 0; mi < 4; mi++) {
                ldsm4(ah[mi][0], ah[mi][1], ah[mi][2], ah[mi][3], uAh + aoff[mi] + kb);
                ldsm4(al[mi][0], al[mi][1], al[mi][2], al[mi][3], uAl + aoff[mi] + kb);
            }
            #pragma unroll
            for (int jp = 0; jp < 2; jp++)
                ldsm4(bf[jp * 2][0], bf[jp * 2][1], bf[jp * 2 + 1][0], bf[jp * 2 + 1][1],
                      uBh + boff[jp] + kb);
            #pragma unroll
            for (int mi = 0; mi < 4; mi++)
                #pragma unroll
                for (int nj = 0; nj < 4; nj++) {
                    mma16816(acc[mi][nj], ah[mi], bf[nj]);
                    mma16816(acc[mi][nj], al[mi], bf[nj]);
                }
            if (NT == 3) {
                #pragma unroll
                for (int jp = 0; jp < 2; jp++)
                    ldsm4(bf[jp * 2][0], bf[jp * 2][1], bf[jp * 2 + 1][0], bf[jp * 2 + 1][1],
                          uBl + boff[jp] + kb);
                #pragma unroll
                for (int mi = 0; mi < 4; mi++)
                    #pragma unroll
                    for (int nj = 0; nj < 4; nj++)
                        mma16816(acc[mi][nj], ah[mi], bf[nj]);
            }
        }
        __syncthreads();
    }

    #pragma unroll
    for (int mi = 0; mi < 4; mi++) {
        int r0g = row0 + wm * 64 + mi * 16 + (lane >> 2);
        int cg  = col0 + wn * 32 + (lane & 3) * 2;
        #pragma unroll
        for (int nj = 0; nj < 4; nj++) {
            int c = cg + nj * 8;
            if (r0g < M)
                *(float2*)(C + (size_t)r0g * Nc + c) = make_float2(acc[mi][nj][0], acc[mi][nj][1]);
            if (r0g + 8 < M)
                *(float2*)(C + (size_t)(r0g + 8) * Nc + c) = make_float2(acc[mi][nj][2], acc[mi][nj][3]);
        }
    }
}

// -------- fused GRU GEMM: 3 gate passes (r,z,n) + gate math in epilogue ------
// grid (2, MT): CTA owns 128 rows x 128 channels; B rows = gate*256+col0+n.
// 2-term fp16. Stashes sigmoid(r), sigmoid(z) in SMEM (thread-private mapping).
#define BUF2   (3 * ABYTES)              // 30720 B per stage (Ah, Al, Bh)
#define STSTR  129                       // stash stride (floats)
__global__ __launch_bounds__(256, 1) void k_mm_gru(const __half* __restrict__ AH,
                                                   const __half* __restrict__ AL,
                                                   const __half* __restrict__ BtH,
                                                   const float* __restrict__ b_ih,
                                                   const float* __restrict__ b_hh,
                                                   float* __restrict__ OUT,
                                                   int M)
{
    extern __shared__ char smem[];
    const uint32_t sb = smem_u32(smem);
    float* stash_r = (float*)(smem + 2 * BUF2);
    float* stash_z = stash_r + 128 * STSTR;

    const int tid  = threadIdx.x;
    const int wid  = tid >> 5, lane = tid & 31;
    const int wm   = wid & 1, wn = wid >> 1;
    const int row0 = blockIdx.y * 128, col0 = blockIdx.x * 128;
    const int K = Hd;                       // 256
    const int nit = K >> 5;                 // 8

    uint32_t aoff[4];
    #pragma unroll
    for (int mi = 0; mi < 4; mi++) {
        int r = wm * 64 + mi * 16 + (lane & 7) + ((lane >> 3) & 1) * 8;
        aoff[mi] = (uint32_t)(r * (SSTRIDE * 2) + (lane >> 4) * 16);
    }
    uint32_t boff[2];
    #pragma unroll
    for (int jp = 0; jp < 2; jp++) {
        int n = wn * 32 + jp * 16 + (lane & 7) + ((lane >> 4) & 1) * 8;
        boff[jp] = (uint32_t)(n * (SSTRIDE * 2) + ((lane >> 3) & 1) * 16);
    }

    for (int gate = 0; gate < 3; gate++) {
        float acc[4][4][4];
        #pragma unroll
        for (int i = 0; i < 4; i++)
            #pragma unroll
            for (int j = 0; j < 4; j++)
                #pragma unroll
                for (int q = 0; q < 4; q++) acc[i][j][q] = 0.f;

        const int brow0 = gate * 256 + col0;
        auto issue = [&](int kt, int p) {
            #pragma unroll
            for (int c = 0; c < 2; c++) {
                int lin = tid + c * 256;
                int row = lin >> 2, q = lin & 3;
                uint32_t sd = sb + (uint32_t)(p * BUF2 + row * (SSTRIDE * 2) + q * 16);
                int ar = row0 + row;
                uint32_t asz = (ar < M) ? 16u : 0u;
                if (ar >= M) ar = 0;
                size_t aoffg = (size_t)ar * K + kt * 32 + q * 8;
                size_t boffg = (size_t)(brow0 + row) * K + kt * 32 + q * 8;
                cpa16(sd,              AH + aoffg, asz);
                cpa16(sd + ABYTES,     AL + aoffg, asz);
                cpa16(sd + 2 * ABYTES, BtH + boffg, 16u);
            }
            cpa_commit();
        };

        issue(0, 0);
        for (int kt = 0; kt < nit; kt++) {
            const int p = kt & 1;
            if (kt + 1 < nit) { issue(kt + 1, p ^ 1); cpa_wait<1>(); }
            else              { cpa_wait<0>(); }
            __syncthreads();

            const uint32_t uAh = sb + p * BUF2;
            const uint32_t uAl = uAh + ABYTES;
            const uint32_t uBh = uAh + 2 * ABYTES;

            #pragma unroll
            for (int ks = 0; ks < 2; ks++) {
                const uint32_t kb = (uint32_t)(ks * 32);
                uint32_t ah[4][4], al[4][4], bf[4][2];
                #pragma unroll
                for (int mi = 0; mi < 4; mi++) {
                    ldsm4(ah[mi][0], ah[mi][1], ah[mi][2], ah[mi][3], uAh + aoff[mi] + kb);
                    ldsm4(al[mi][0], al[mi][1], al[mi][2], al[mi][3], uAl + aoff[mi] + kb);
                }
                #pragma unroll
                for (int jp = 0; jp < 2; jp++)
                    ldsm4(bf[jp * 2][0], bf[jp * 2][1], bf[jp * 2 + 1][0], bf[jp * 2 + 1][1],
                          uBh + boff[jp] + kb);
                #pragma unroll
                for (int mi = 0; mi < 4; mi++)
                    #pragma unroll
                    for (int nj = 0; nj < 4; nj++) {
                        mma16816(acc[mi][nj], ah[mi], bf[nj]);
                        mma16816(acc[mi][nj], al[mi], bf[nj]);
                    }
            }
            __syncthreads();
        }

        // ---- gate epilogue (thread-private stash: same mapping every pass) ----
        if (gate < 2) {
            float* st = (gate == 0) ? stash_r : stash_z;
            const int go = gate * 256 + col0;
            #pragma unroll
            for (int mi = 0; mi < 4; mi++) {
                int rl = wm * 64 + mi * 16 + (lane >> 2);
                #pragma unroll
                for (int nj = 0; nj < 4; nj++) {
                    int cl = wn * 32 + (lane & 3) * 2 + nj * 8;
                    float bs0 = b_ih[go + cl]     + b_hh[go + cl];
                    float bs1 = b_ih[go + cl + 1] + b_hh[go + cl + 1];
                    st[rl * STSTR + cl]           = 1.f / (1.f + expf(-(acc[mi][nj][0] + bs0)));
                    st[rl * STSTR + cl + 1]       = 1.f / (1.f + expf(-(acc[mi][nj][1] + bs1)));
                    st[(rl + 8) * STSTR + cl]     = 1.f / (1.f + expf(-(acc[mi][nj][2] + bs0)));
                    st[(rl + 8) * STSTR + cl + 1] = 1.f / (1.f + expf(-(acc[mi][nj][3] + bs1)));
                }
            }
        } else {
            const int go = 512 + col0;
            #pragma unroll
            for (int mi = 0; mi < 4; mi++) {
                int rl = wm * 64 + mi * 16 + (lane >> 2);
                int gr0 = row0 + rl, gr1 = gr0 + 8;
                #pragma unroll
                for (int nj = 0; nj < 4; nj++) {
                    int cl = wn * 32 + (lane & 3) * 2 + nj * 8;
                    float bi0 = b_ih[go + cl],     bh0 = b_hh[go + cl];
                    float bi1 = b_ih[go + cl + 1], bh1 = b_hh[go + cl + 1];
                    {
                        float r0 = stash_r[rl * STSTR + cl],     z0 = stash_z[rl * STSTR + cl];
                        float r1 = stash_r[rl * STSTR + cl + 1], z1 = stash_z[rl * STSTR + cl + 1];
                        float h0 = (1.f - z0) * tanhf(acc[mi][nj][0] + bi0 + r0 * bh0);
                        float h1 = (1.f - z1) * tanhf(acc[mi][nj][1] + bi1 + r1 * bh1);
                        if (gr0 < M)
                            *(float2*)(OUT + (size_t)gr0 * Hd + col0 + cl) = make_float2(h0, h1);
                    }
                    {
                        float r0 = stash_r[(rl + 8) * STSTR + cl],     z0 = stash_z[(rl + 8) * STSTR + cl];
                        float r1 = stash_r[(rl + 8) * STSTR + cl + 1], z1 = stash_z[(rl + 8) * STSTR + cl + 1];
                        float h0 = (1.f - z0) * tanhf(acc[mi][nj][2] + bi0 + r0 * bh0);
                        float h1 = (1.f - z1) * tanhf(acc[mi][nj][3] + bi1 + r1 * bh1);
                        if (gr1 < M)
                            *(float2*)(OUT + (size_t)gr1 * Hd + col0 + cl) = make_float2(h0, h1);
                    }
                }
            }
        }
    }
}

// ------------------------------ CSR build -----------------------------------
__global__ __launch_bounds__(1024) void k_scan(void)
{
    __shared__ int ssum[1024];
    const int CH = (Nn + 1023) / 1024;
    int tid = threadIdx.x;
    int base = tid * CH;
    int s = 0;
    for (int j = 0; j < CH; j++) {
        int idx = base + j;
        if (idx < Nn) s += g_cnt[idx];
    }
    ssum[tid] = s;
    __syncthreads();
    for (int off = 1; off < 1024; off <<= 1) {
        int v = (tid >= off) ? ssum[tid - off] : 0;
        __syncthreads();
        ssum[tid] += v;
        __syncthreads();
    }
    int run = (tid > 0) ? ssum[tid - 1] : 0;
    for (int j = 0; j < CH; j++) {
        int idx = base + j;
        if (idx < Nn) { g_offs[idx] = run; run += g_cnt[idx]; }
    }
    if (tid == 1023) g_offs[Nn] = ssum[1023];
}
__global__ void k_fill(void)
{
    int e = blockIdx.x * blockDim.x + threadIdx.x;
    if (e >= Ee) return;
    int d = g_dst[e];
    int pos = atomicAdd(&g_cur[d], 1);
    g_adj[g_offs[d] + pos] = g_src[e];
}

// -------- graph boundaries (batch is sorted): gstart[g] = lower_bound(g) ----
__global__ void k_gstart(void)
{
    int g = threadIdx.x;
    if (g > Gg) return;
    if (g == Gg) { g_gstart[g] = Nn; return; }
    int lo = 0, hi = Nn;
    while (lo < hi) {
        int mid = (lo + hi) >> 1;
        if (g_batch[mid] < g) lo = mid + 1; else hi = mid;
    }
    g_gstart[g] = lo;
}

// ------------- per-node prep: s_src/s_dst attention dots ---------------------
__global__ __launch_bounds__(256) void k_node_prep(const float* __restrict__ xp,
                                                   const float* __restrict__ avs,
                                                   const float* __restrict__ avd)
{
    int w = (blockIdx.x * blockDim.x + threadIdx.x) >> 5;
    int lane = threadIdx.x & 31;
    if (w >= Nn) return;
    const float4* row = (const float4*)(xp + (size_t)w * Hd);
    float ss = 0.f, sd = 0.f;
    #pragma unroll
    for (int it = 0; it < 2; it++) {
        int i4 = lane + it * 32;
        float4 v  = row[i4];
        float4 as = ((const float4*)avs)[i4];
        float4 ad = ((const float4*)avd)[i4];
        ss += v.x * as.x + v.y * as.y + v.z * as.z + v.w * as.w;
        sd += v.x * ad.x + v.y * ad.y + v.z * ad.z + v.w * ad.w;
    }
    #pragma unroll
    for (int o = 16; o > 0; o >>= 1) {
        ss += __shfl_down_sync(0xffffffffu, ss, o);
        sd += __shfl_down_sync(0xffffffffu, sd, o);
    }
    if (lane == 0) { g_ssrc[w] = ss; g_sdst[w] = sd; }
}

// ---- GAT aggregation gather: one warp per dst; emits relu + fp16 hi/lo split
__global__ __launch_bounds__(256) void k_gather(const float* __restrict__ xp,
                                                const float* __restrict__ bias,
                                                __half* __restrict__ oh,
                                                __half* __restrict__ ol)
{
    int w = (blockIdx.x * blockDim.x + threadIdx.x) >> 5;
    int lane = threadIdx.x & 31;
    if (w >= Nn) return;
    int beg = g_offs[w], end = g_offs[w + 1];
    float sd = g_sdst[w];

    float part = 0.f;
    for (int i = beg + lane; i < end; i += 32) {
        float v = g_ssrc[g_adj[i]] + sd;
        v = v > 0.f ? v : NEG * v;
        part += expf(v);
    }
    #pragma unroll
    for (int o = 16; o > 0; o >>= 1) part += __shfl_xor_sync(0xffffffffu, part, o);
    float vs = g_ssrc[w] + sd;
    vs = vs > 0.f ? vs : NEG * vs;
    float ps = expf(vs);
    float invden = 1.f / (part + ps);

    float c0 = ps * invden;
    const float4* srow = (const float4*)(xp + (size_t)w * Hd);
    float4 b0 = ((const float4*)bias)[lane];
    float4 b1 = ((const float4*)bias)[lane + 32];
    float4 x0 = srow[lane], x1 = srow[lane + 32];
    float4 acc0, acc1;
    acc0.x = fmaf(c0, x0.x, b0.x); acc0.y = fmaf(c0, x0.y, b0.y);
    acc0.z = fmaf(c0, x0.z, b0.z); acc0.w = fmaf(c0, x0.w, b0.w);
    acc1.x = fmaf(c0, x1.x, b1.x); acc1.y = fmaf(c0, x1.y, b1.y);
    acc1.z = fmaf(c0, x1.z, b1.z); acc1.w = fmaf(c0, x1.w, b1.w);

    for (int i = beg; i < end; i++) {
        int s = g_adj[i];
        float v = g_ssrc[s] + sd;
        v = v > 0.f ? v : NEG * v;
        float coef = expf(v) * invden;
        const float4* r = (const float4*)(xp + (size_t)s * Hd);
        float4 r0 = r[lane], r1 = r[lane + 32];
        acc0.x = fmaf(coef, r0.x, acc0.x); acc0.y = fmaf(coef, r0.y, acc0.y);
        acc0.z = fmaf(coef, r0.z, acc0.z); acc0.w = fmaf(coef, r0.w, acc0.w);
        acc1.x = fmaf(coef, r1.x, acc1.x); acc1.y = fmaf(coef, r1.y, acc1.y);
        acc1.z = fmaf(coef, r1.z, acc1.z); acc1.w = fmaf(coef, r1.w, acc1.w);
    }
    uint2 hs, ls;
    relu_split4(acc0, hs, ls);
    *(uint2*)(oh + (size_t)w * Hd + 4 * lane) = hs;
    *(uint2*)(ol + (size_t)w * Hd + 4 * lane) = ls;
    relu_split4(acc1, hs, ls);
    *(uint2*)(oh + (size_t)w * Hd + 128 + 4 * lane) = hs;
    *(uint2*)(ol + (size_t)w * Hd + 128 + 4 * lane) = ls;
}

// --------------- pooling: contiguous per-graph sum (batch sorted) -----------
__global__ __launch_bounds__(128) void k_pool_g(const float* __restrict__ hg,
                                                float* __restrict__ out)
{
    int g = blockIdx.x;
    int c = blockIdx.y * 128 + threadIdx.x;
    int beg = g_gstart[g], end = g_gstart[g + 1];
    float s = 0.f;
    for (int n = beg; n < end; n++) s += hg[(size_t)n * Hd + c];
    out[(size_t)g * (2 * Hd) + c] = s;
}

__global__ __launch_bounds__(256) void k_super(const float* __restrict__ Wf,
                                               const float* __restrict__ bf,
                                               float* __restrict__ out)
{
    __shared__ float s[Hd];
    int j = threadIdx.x;
    float sum = 0.f;
    for (int g = 0; g < Gg; g++) sum += out[(size_t)g * (2 * Hd) + j];
    s[j] = sum / (float)Gg;
    __syncthreads();
    float v = bf[j];
    #pragma unroll 8
    for (int c = 0; c < Hd; c++) v = fmaf(s[c], Wf[(size_t)j * Hd + c], v);
    v = fmaxf(v, 0.f);
    for (int g = 0; g < Gg; g++) out[(size_t)g * (2 * Hd) + Hd + j] = v;
}

// ------------------------------ launch --------------------------------------
extern "C" void kernel_launch(void* const* d_in, const int* in_sizes, int n_in,
                              void* d_out, int out_size)
{
    const float* x      = (const float*)d_in[0];
    const int*   ei32   = (const int*)d_in[1];
    const int*   b32    = (const int*)d_in[2];
    const float* W0     = (const float*)d_in[3];
    const float* a_src0 = (const float*)d_in[4];
    const float* a_dst0 = (const float*)d_in[5];
    const float* b0     = (const float*)d_in[6];
    const float* W1     = (const float*)d_in[7];
    const float* a_src1 = (const float*)d_in[8];
    const float* a_dst1 = (const float*)d_in[9];
    const float* b1     = (const float*)d_in[10];
    const float* W_ih   = (const float*)d_in[11];
    /* d_in[12] = W_hh: unused (h0 = 0) */
    const float* b_ih   = (const float*)d_in[13];
    const float* b_hh   = (const float*)d_in[14];
    const float* Wf     = (const float*)d_in[15];
    const float* bf     = (const float*)d_in[16];
    float*       out    = (float*)d_out;

    float *xp;
    __half *ah, *al, *bt0h, *bt0l, *bt1h, *bihh;
    cudaGetSymbolAddress((void**)&xp, g_xp);
    cudaGetSymbolAddress((void**)&ah, g_ah);
    cudaGetSymbolAddress((void**)&al, g_al);
    cudaGetSymbolAddress((void**)&bt0h, g_bt0h);
    cudaGetSymbolAddress((void**)&bt0l, g_bt0l);
    cudaGetSymbolAddress((void**)&bt1h, g_bt1h);
    cudaGetSymbolAddress((void**)&bihh, g_bihh);

    const int SMEM  = 2 * BUFB;                          // 81920
    const int SMEMG = 2 * BUF2 + 2 * 128 * STSTR * 4;    // 61440 + 132096 = 193536
    cudaFuncSetAttribute(k_mm_f16<3>, cudaFuncAttributeMaxDynamicSharedMemorySize, SMEM);
    cudaFuncSetAttribute(k_mm_f16<2>, cudaFuncAttributeMaxDynamicSharedMemorySize, SMEM);
    cudaFuncSetAttribute(k_mm_gru, cudaFuncAttributeMaxDynamicSharedMemorySize, SMEMG);

    const int MT = (Nn + 127) / 128;   // 391
    dim3 blk(256);

    k_detect<<<1, 1>>>(ei32);                                     // 1
    k_decode_batch<<<(Nn + 255) / 256, blk>>>(b32);               // 2
    k_decode_count<<<(Ee + 255) / 256, blk>>>(ei32);              // 3
    k_prep_w<<<(768 * 256 + 255) / 256, blk>>>(W0, W1, W_ih);     // 4
    k_split_x<<<(Nn * INC / 4 + 255) / 256, blk>>>(x, Nn * INC / 4); // 5

    // ---- GAT layer 0 GEMM (3-term) ----  (profile slot 6)
    k_mm_f16<3><<<dim3(2, MT), blk, SMEM>>>(ah, al, bt0h, bt0l, xp, Nn, Hd, INC);

    // ---- CSR + graph boundaries ----
    k_scan<<<1, 1024>>>();
    k_fill<<<(Ee + 255) / 256, blk>>>();
    k_gstart<<<1, Gg + 1>>>();

    // ---- GAT layer 0 attention + aggregate ----
    k_node_prep<<<(Nn * 32 + 255) / 256, blk>>>(xp, a_src0, a_dst0);
    k_gather<<<(Nn * 32 + 255) / 256, blk>>>(xp, b0, ah, al);

    // ---- GAT layer 1 (2-term) ----
    k_mm_f16<2><<<dim3(2, MT), blk, SMEM>>>(ah, al, bt1h, (const __half*)bt1h, xp, Nn, Hd, Hd);
    k_node_prep<<<(Nn * 32 + 255) / 256, blk>>>(xp, a_src1, a_dst1);
    k_gather<<<(Nn * 32 + 255) / 256, blk>>>(xp, b1, ah, al);

    // ---- fused GRU GEMM + gates -> h (xp) ----
    k_mm_gru<<<dim3(2, MT), blk, SMEMG>>>(ah, al, bihh, b_ih, b_hh, xp, Nn);

    // ---- pooling + super node ----
    k_pool_g<<<dim3(Gg, 2), 128>>>(xp, out);
    k_super<<<1, Hd>>>(Wf, bf, out);
}

// round 10
// speedup vs baseline: 1.8317x; 1.0492x over previous
#include <cuda_runtime.h>
#include <cuda_fp16.h>
#include <math.h>
#include <stdint.h>

#define Nn   50000
#define Ee   800000
#define INC  128
#define Hd   256
#define Gg   128
#define NEG  0.2f

// ---------------- scratch (device globals; no allocations allowed) ----------
__device__ float  g_xp[(size_t)Nn * Hd];          // GRU output (fp32, for pool)
__device__ __half g_xp16[(size_t)Nn * Hd];        // GAT projected features (fp16)
__device__ float g_ssrc[Nn];
__device__ float g_sdst[Nn];
__device__ int   g_src[Ee];
__device__ int   g_dst[Ee];
__device__ int   g_batch[Nn];
__device__ int   g_cnt[Nn];
__device__ int   g_cur[Nn];
__device__ int   g_offs[Nn + 1];
__device__ int   g_adj[Ee];
__device__ int   g_gstart[Gg + 1];
__device__ int   g_is64;
// fp16-split A (reused across the three GEMMs)
__device__ __half g_ah[(size_t)Nn * Hd], g_al[(size_t)Nn * Hd];
// fp16-split weights, stored [N][K] (B^T layout, K contiguous -> mma row.col)
__device__ __half g_bt0h[256 * 128], g_bt0l[256 * 128];
__device__ __half g_bt1h[256 * 256];
__device__ __half g_bihh[768 * 256];

// ---------------------------- PTX helpers -----------------------------------
__device__ __forceinline__ uint32_t smem_u32(const void* p) {
    uint32_t a;
    asm("{ .reg .u64 t; cvta.to.shared.u64 t, %1; cvt.u32.u64 %0, t; }" : "=r"(a) : "l"(p));
    return a;
}
__device__ __forceinline__ void ldsm4(uint32_t& r0, uint32_t& r1, uint32_t& r2, uint32_t& r3,
                                      uint32_t addr) {
    asm volatile("ldmatrix.sync.aligned.m8n8.x4.shared.b16 {%0,%1,%2,%3}, [%4];"
                 : "=r"(r0), "=r"(r1), "=r"(r2), "=r"(r3) : "r"(addr));
}
__device__ __forceinline__ void mma16816(float* d, const uint32_t* a, const uint32_t* b) {
    asm volatile("mma.sync.aligned.m16n8k16.row.col.f32.f16.f16.f32 "
                 "{%0,%1,%2,%3}, {%4,%5,%6,%7}, {%8,%9}, {%0,%1,%2,%3};"
                 : "+f"(d[0]), "+f"(d[1]), "+f"(d[2]), "+f"(d[3])
                 : "r"(a[0]), "r"(a[1]), "r"(a[2]), "r"(a[3]), "r"(b[0]), "r"(b[1]));
}
__device__ __forceinline__ void cpa16(uint32_t dst, const void* src, uint32_t sz) {
    asm volatile("cp.async.cg.shared.global [%0], [%1], 16, %2;"
                 :: "r"(dst), "l"(src), "r"(sz) : "memory");
}
__device__ __forceinline__ void cpa_commit() {
    asm volatile("cp.async.commit_group;" ::: "memory");
}
template<int N> __device__ __forceinline__ void cpa_wait() {
    asm volatile("cp.async.wait_group %0;" :: "n"(N) : "memory");
}

// ---------------- fp16 hi/lo split helpers -----------------------------------
__device__ __forceinline__ void f16split(float w, __half& h, __half& l) {
    h = __float2half_rn(w);
    l = __float2half_rn(w - __half2float(h));
}

// ---------------- index dtype detection + decode ----------------------------
__global__ void k_detect(const int* __restrict__ ei32)
{
    int is64 = 1;
    for (int i = 0; i < 64; i++)
        if (ei32[2 * i + 1] != 0) { is64 = 0; break; }
    g_is64 = is64;
}
__global__ void k_decode_batch(const int* __restrict__ b32)
{
    int n = blockIdx.x * blockDim.x + threadIdx.x;
    if (n >= Nn) return;
    g_batch[n] = g_is64 ? b32[2 * n] : b32[n];
    g_cnt[n] = 0;
    g_cur[n] = 0;
}
__global__ void k_decode_count(const int* __restrict__ ei32)
{
    int e = blockIdx.x * blockDim.x + threadIdx.x;
    if (e >= Ee) return;
    int s, d;
    if (g_is64) { s = ei32[2 * e]; d = ei32[2 * (Ee + e)]; }
    else        { s = ei32[e];     d = ei32[Ee + e]; }
    g_src[e] = s;
    g_dst[e] = d;
    atomicAdd(&g_cnt[d], 1);
}

// ---------------- weight prep: transpose + fp16 hi/lo split -----------------
__global__ void k_prep_w(const float* __restrict__ W0, const float* __restrict__ W1,
                         const float* __restrict__ Wih)
{
    int t = blockIdx.x * blockDim.x + threadIdx.x;
    if (t < 256 * 128) {                       // Bt0[n][k] = W0[k][n]
        int n = t >> 7, k = t & 127;
        f16split(W0[k * 256 + n], g_bt0h[t], g_bt0l[t]);
    }
    if (t < 256 * 256) {                       // Bt1[n][k] = W1[k][n]  (hi only)
        int n = t >> 8, k = t & 255;
        g_bt1h[t] = __float2half_rn(W1[k * 256 + n]);
    }
    if (t < 768 * 256) {                       // Bih[n][k] = W_ih[n][k] (hi only)
        g_bihh[t] = __float2half_rn(Wih[t]);
    }
}

// ---------------- A split for x: fp32 -> fp16 hi/lo --------------------------
__global__ __launch_bounds__(256) void k_split_x(const float* __restrict__ src, int n4)
{
    int t = blockIdx.x * blockDim.x + threadIdx.x;
    if (t >= n4) return;
    float4 v = ((const float4*)src)[t];
    float f[4] = {v.x, v.y, v.z, v.w};
    ushort4 hs, ls;
    __half hb, lb;
    f16split(f[0], hb, lb); hs.x = __half_as_ushort(hb); ls.x = __half_as_ushort(lb);
    f16split(f[1], hb, lb); hs.y = __half_as_ushort(hb); ls.y = __half_as_ushort(lb);
    f16split(f[2], hb, lb); hs.z = __half_as_ushort(hb); ls.z = __half_as_ushort(lb);
    f16split(f[3], hb, lb); hs.w = __half_as_ushort(hb); ls.w = __half_as_ushort(lb);
    ((ushort4*)g_ah)[t] = hs;
    ((ushort4*)g_al)[t] = ls;
}

// -------- pipelined fp16 GEMM: C16[M,Nc] = Asplit[M,K] @ Bt[Nc,K]^T ----------
// NT=3: Ah*Bh + Al*Bh + Ah*Bl. NT=2: Ah*Bh + Al*Bh. Output packed fp16.
#define SSTRIDE 40                       // fp16 per SMEM row (80 B)
#define ABYTES  (128 * SSTRIDE * 2)      // 10240 B per array
#define BUFB    (4 * ABYTES)             // 40960 B per stage
template<int NT>
__global__ __launch_bounds__(256, 2) void k_mm_f16(const __half* __restrict__ AH,
                                                   const __half* __restrict__ AL,
                                                   const __half* __restrict__ BtH,
                                                   const __half* __restrict__ BtL,
                                                   __half* __restrict__ C16,
                                                   int M, int Nc, int K)
{
    extern __shared__ char smem[];
    const uint32_t sb = smem_u32(smem);

    const int tid  = threadIdx.x;
    const int wid  = tid >> 5, lane = tid & 31;
    const int wm   = wid & 1, wn = wid >> 1;
    const int row0 = blockIdx.y * 128, col0 = blockIdx.x * 128;

    uint32_t aoff[4];
    #pragma unroll
    for (int mi = 0; mi < 4; mi++) {
        int r = wm * 64 + mi * 16 + (lane & 7) + ((lane >> 3) & 1) * 8;
        aoff[mi] = (uint32_t)(r * (SSTRIDE * 2) + (lane >> 4) * 16);
    }
    uint32_t boff[2];
    #pragma unroll
    for (int jp = 0; jp < 2; jp++) {
        int n = wn * 32 + jp * 16 + (lane & 7) + ((lane >> 4) & 1) * 8;
        boff[jp] = (uint32_t)(n * (SSTRIDE * 2) + ((lane >> 3) & 1) * 16);
    }

    float acc[4][4][4];
    #pragma unroll
    for (int i = 0; i < 4; i++)
        #pragma unroll
        for (int j = 0; j < 4; j++)
            #pragma unroll
            for (int q = 0; q < 4; q++) acc[i][j][q] = 0.f;

    const int nit = K >> 5;
    auto issue = [&](int kt, int p) {
        #pragma unroll
        for (int c = 0; c < 2; c++) {
            int lin = tid + c * 256;
            int row = lin >> 2, q = lin & 3;
            uint32_t sd = sb + (uint32_t)(p * BUFB + row * (SSTRIDE * 2) + q * 16);
            int ar = row0 + row;
            uint32_t asz = (ar < M) ? 16u : 0u;
            if (ar >= M) ar = 0;
            size_t aoffg = (size_t)ar * K + kt * 32 + q * 8;
            size_t boffg = (size_t)(col0 + row) * K + kt * 32 + q * 8;
            cpa16(sd,              AH + aoffg, asz);
            cpa16(sd + ABYTES,     AL + aoffg, asz);
            cpa16(sd + 2 * ABYTES, BtH + boffg, 16u);
            if (NT == 3)
                cpa16(sd + 3 * ABYTES, BtL + boffg, 16u);
        }
        cpa_commit();
    };

    issue(0, 0);
    for (int kt = 0; kt < nit; kt++) {
        const int p = kt & 1;
        if (kt + 1 < nit) { issue(kt + 1, p ^ 1); cpa_wait<1>(); }
        else              { cpa_wait<0>(); }
        __syncthreads();

        const uint32_t uAh = sb + p * BUFB;
        const uint32_t uAl = uAh + ABYTES;
        const uint32_t uBh = uAh + 2 * ABYTES;
        const uint32_t uBl = uAh + 3 * ABYTES;

        #pragma unroll
        for (int ks = 0; ks < 2; ks++) {
            const uint32_t kb = (uint32_t)(ks * 32);
            uint32_t ah[4][4], al[4][4], bf[4][2];
            #pragma unroll
            for (int mi = 0; mi < 4; mi++) {
                ldsm4(ah[mi][0], ah[mi][1], ah[mi][2], ah[mi][3], uAh + aoff[mi] + kb);
                ldsm4(al[mi][0], al[mi][1], al[mi][2], al[mi][3], uAl + aoff[mi] + kb);
            }
            #pragma unroll
            for (int jp = 0; jp < 2; jp++)
                ldsm4(bf[jp * 2][0], bf[jp * 2][1], bf[jp * 2 + 1][0], bf[jp * 2 + 1][1],
                      uBh + boff[jp] + kb);
            #pragma unroll
            for (int mi = 0; mi < 4; mi++)
                #pragma unroll
                for (int nj = 0; nj < 4; nj++) {
                    mma16816(acc[mi][nj], ah[mi], bf[nj]);
                    mma16816(acc[mi][nj], al[mi], bf[nj]);
                }
            if (NT == 3) {
                #pragma unroll
                for (int jp = 0; jp < 2; jp++)
                    ldsm4(bf[jp * 2][0], bf[jp * 2][1], bf[jp * 2 + 1][0], bf[jp * 2 + 1][1],
                          uBl + boff[jp] + kb);
                #pragma unroll
                for (int mi = 0; mi < 4; mi++)
                    #pragma unroll
                    for (int nj = 0; nj < 4; nj++)
                        mma16816(acc[mi][nj], ah[mi], bf[nj]);
            }
        }
        __syncthreads();
    }

    // ---- epilogue: packed fp16 stores ----
    #pragma unroll
    for (int mi = 0; mi < 4; mi++) {
        int r0g = row0 + wm * 64 + mi * 16 + (lane >> 2);
        int cg  = col0 + wn * 32 + (lane & 3) * 2;
        #pragma unroll
        for (int nj = 0; nj < 4; nj++) {
            int c = cg + nj * 8;
            if (r0g < M)
                *(__half2*)(C16 + (size_t)r0g * Nc + c) =
                    __floats2half2_rn(acc[mi][nj][0], acc[mi][nj][1]);
            if (r0g + 8 < M)
                *(__half2*)(C16 + (size_t)(r0g + 8) * Nc + c) =
                    __floats2half2_rn(acc[mi][nj][2], acc[mi][nj][3]);
        }
    }
}

// -------- fused GRU GEMM: 3 gate passes (r,z,n) + gate math in epilogue ------
#define BUF2   (3 * ABYTES)              // 30720 B per stage (Ah, Al, Bh)
#define STSTR  129                       // stash stride (floats)
__global__ __launch_bounds__(256, 1) void k_mm_gru(const __half* __restrict__ AH,
                                                   const __half* __restrict__ AL,
                                                   const __half* __restrict__ BtH,
                                                   const float* __restrict__ b_ih,
                                                   const float* __restrict__ b_hh,
                                                   float* __restrict__ OUT,
                                                   int M)
{
    extern __shared__ char smem[];
    const uint32_t sb = smem_u32(smem);
    float* stash_r = (float*)(smem + 2 * BUF2);
    float* stash_z = stash_r + 128 * STSTR;

    const int tid  = threadIdx.x;
    const int wid  = tid >> 5, lane = tid & 31;
    const int wm   = wid & 1, wn = wid >> 1;
    const int row0 = blockIdx.y * 128, col0 = blockIdx.x * 128;
    const int K = Hd;
    const int nit = K >> 5;

    uint32_t aoff[4];
    #pragma unroll
    for (int mi = 0; mi < 4; mi++) {
        int r = wm * 64 + mi * 16 + (lane & 7) + ((lane >> 3) & 1) * 8;
        aoff[mi] = (uint32_t)(r * (SSTRIDE * 2) + (lane >> 4) * 16);
    }
    uint32_t boff[2];
    #pragma unroll
    for (int jp = 0; jp < 2; jp++) {
        int n = wn * 32 + jp * 16 + (lane & 7) + ((lane >> 4) & 1) * 8;
        boff[jp] = (uint32_t)(n * (SSTRIDE * 2) + ((lane >> 3) & 1) * 16);
    }

    for (int gate = 0; gate < 3; gate++) {
        float acc[4][4][4];
        #pragma unroll
        for (int i = 0; i < 4; i++)
            #pragma unroll
            for (int j = 0; j < 4; j++)
                #pragma unroll
                for (int q = 0; q < 4; q++) acc[i][j][q] = 0.f;

        const int brow0 = gate * 256 + col0;
        auto issue = [&](int kt, int p) {
            #pragma unroll
            for (int c = 0; c < 2; c++) {
                int lin = tid + c * 256;
                int row = lin >> 2, q = lin & 3;
                uint32_t sd = sb + (uint32_t)(p * BUF2 + row * (SSTRIDE * 2) + q * 16);
                int ar = row0 + row;
                uint32_t asz = (ar < M) ? 16u : 0u;
                if (ar >= M) ar = 0;
                size_t aoffg = (size_t)ar * K + kt * 32 + q * 8;
                size_t boffg = (size_t)(brow0 + row) * K + kt * 32 + q * 8;
                cpa16(sd,              AH + aoffg, asz);
                cpa16(sd + ABYTES,     AL + aoffg, asz);
                cpa16(sd + 2 * ABYTES, BtH + boffg, 16u);
            }
            cpa_commit();
        };

        issue(0, 0);
        for (int kt = 0; kt < nit; kt++) {
            const int p = kt & 1;
            if (kt + 1 < nit) { issue(kt + 1, p ^ 1); cpa_wait<1>(); }
            else              { cpa_wait<0>(); }
            __syncthreads();

            const uint32_t uAh = sb + p * BUF2;
            const uint32_t uAl = uAh + ABYTES;
            const uint32_t uBh = uAh + 2 * ABYTES;

            #pragma unroll
            for (int ks = 0; ks < 2; ks++) {
                const uint32_t kb = (uint32_t)(ks * 32);
                uint32_t ah[4][4], al[4][4], bf[4][2];
                #pragma unroll
                for (int mi = 0; mi < 4; mi++) {
                    ldsm4(ah[mi][0], ah[mi][1], ah[mi][2], ah[mi][3], uAh + aoff[mi] + kb);
                    ldsm4(al[mi][0], al[mi][1], al[mi][2], al[mi][3], uAl + aoff[mi] + kb);
                }
                #pragma unroll
                for (int jp = 0; jp < 2; jp++)
                    ldsm4(bf[jp * 2][0], bf[jp * 2][1], bf[jp * 2 + 1][0], bf[jp * 2 + 1][1],
                          uBh + boff[jp] + kb);
                #pragma unroll
                for (int mi = 0; mi < 4; mi++)
                    #pragma unroll
                    for (int nj = 0; nj < 4; nj++) {
                        mma16816(acc[mi][nj], ah[mi], bf[nj]);
                        mma16816(acc[mi][nj], al[mi], bf[nj]);
                    }
            }
            __syncthreads();
        }

        if (gate < 2) {
            float* st = (gate == 0) ? stash_r : stash_z;
            const int go = gate * 256 + col0;
            #pragma unroll
            for (int mi = 0; mi < 4; mi++) {
                int rl = wm * 64 + mi * 16 + (lane >> 2);
                #pragma unroll
                for (int nj = 0; nj < 4; nj++) {
                    int cl = wn * 32 + (lane & 3) * 2 + nj * 8;
                    float bs0 = b_ih[go + cl]     + b_hh[go + cl];
                    float bs1 = b_ih[go + cl + 1] + b_hh[go + cl + 1];
                    st[rl * STSTR + cl]           = 1.f / (1.f + expf(-(acc[mi][nj][0] + bs0)));
                    st[rl * STSTR + cl + 1]       = 1.f / (1.f + expf(-(acc[mi][nj][1] + bs1)));
                    st[(rl + 8) * STSTR + cl]     = 1.f / (1.f + expf(-(acc[mi][nj][2] + bs0)));
                    st[(rl + 8) * STSTR + cl + 1] = 1.f / (1.f + expf(-(acc[mi][nj][3] + bs1)));
                }
            }
        } else {
            const int go = 512 + col0;
            #pragma unroll
            for (int mi = 0; mi < 4; mi++) {
                int rl = wm * 64 + mi * 16 + (lane >> 2);
                int gr0 = row0 + rl, gr1 = gr0 + 8;
                #pragma unroll
                for (int nj = 0; nj < 4; nj++) {
                    int cl = wn * 32 + (lane & 3) * 2 + nj * 8;
                    float bi0 = b_ih[go + cl],     bh0 = b_hh[go + cl];
                    float bi1 = b_ih[go + cl + 1], bh1 = b_hh[go + cl + 1];
                    {
                        float r0 = stash_r[rl * STSTR + cl],     z0 = stash_z[rl * STSTR + cl];
                        float r1 = stash_r[rl * STSTR + cl + 1], z1 = stash_z[rl * STSTR + cl + 1];
                        float h0 = (1.f - z0) * tanhf(acc[mi][nj][0] + bi0 + r0 * bh0);
                        float h1 = (1.f - z1) * tanhf(acc[mi][nj][1] + bi1 + r1 * bh1);
                        if (gr0 < M)
                            *(float2*)(OUT + (size_t)gr0 * Hd + col0 + cl) = make_float2(h0, h1);
                    }
                    {
                        float r0 = stash_r[(rl + 8) * STSTR + cl],     z0 = stash_z[(rl + 8) * STSTR + cl];
                        float r1 = stash_r[(rl + 8) * STSTR + cl + 1], z1 = stash_z[(rl + 8) * STSTR + cl + 1];
                        float h0 = (1.f - z0) * tanhf(acc[mi][nj][2] + bi0 + r0 * bh0);
                        float h1 = (1.f - z1) * tanhf(acc[mi][nj][3] + bi1 + r1 * bh1);
                        if (gr1 < M)
                            *(float2*)(OUT + (size_t)gr1 * Hd + col0 + cl) = make_float2(h0, h1);
                    }
                }
            }
        }
    }
}

// ------------------------------ CSR build -----------------------------------
__global__ __launch_bounds__(1024) void k_scan(void)
{
    __shared__ int ssum[1024];
    const int CH = (Nn + 1023) / 1024;
    int tid = threadIdx.x;
    int base = tid * CH;
    int s = 0;
    for (int j = 0; j < CH; j++) {
        int idx = base + j;
        if (idx < Nn) s += g_cnt[idx];
    }
    ssum[tid] = s;
    __syncthreads();
    for (int off = 1; off < 1024; off <<= 1) {
        int v = (tid >= off) ? ssum[tid - off] : 0;
        __syncthreads();
        ssum[tid] += v;
        __syncthreads();
    }
    int run = (tid > 0) ? ssum[tid - 1] : 0;
    for (int j = 0; j < CH; j++) {
        int idx = base + j;
        if (idx < Nn) { g_offs[idx] = run; run += g_cnt[idx]; }
    }
    if (tid == 1023) g_offs[Nn] = ssum[1023];
}
__global__ void k_fill(void)
{
    int e = blockIdx.x * blockDim.x + threadIdx.x;
    if (e >= Ee) return;
    int d = g_dst[e];
    int pos = atomicAdd(&g_cur[d], 1);
    g_adj[g_offs[d] + pos] = g_src[e];
}

// -------- graph boundaries (batch is sorted): gstart[g] = lower_bound(g) ----
__global__ void k_gstart(void)
{
    int g = threadIdx.x;
    if (g > Gg) return;
    if (g == Gg) { g_gstart[g] = Nn; return; }
    int lo = 0, hi = Nn;
    while (lo < hi) {
        int mid = (lo + hi) >> 1;
        if (g_batch[mid] < g) lo = mid + 1; else hi = mid;
    }
    g_gstart[g] = lo;
}

// ------------- per-node prep: s_src/s_dst attention dots (fp16 xp) -----------
__global__ __launch_bounds__(256) void k_node_prep(const __half* __restrict__ xp16,
                                                   const float* __restrict__ avs,
                                                   const float* __restrict__ avd)
{
    int w = (blockIdx.x * blockDim.x + threadIdx.x) >> 5;
    int lane = threadIdx.x & 31;
    if (w >= Nn) return;
    uint4 rv = ((const uint4*)(xp16 + (size_t)w * Hd))[lane];   // 8 halves
    float2 f0 = __half22float2(*(__half2*)&rv.x);
    float2 f1 = __half22float2(*(__half2*)&rv.y);
    float2 f2 = __half22float2(*(__half2*)&rv.z);
    float2 f3 = __half22float2(*(__half2*)&rv.w);
    float4 a0 = ((const float4*)avs)[lane * 2];
    float4 a1 = ((const float4*)avs)[lane * 2 + 1];
    float4 d0 = ((const float4*)avd)[lane * 2];
    float4 d1 = ((const float4*)avd)[lane * 2 + 1];
    float ss = f0.x * a0.x + f0.y * a0.y + f1.x * a0.z + f1.y * a0.w
             + f2.x * a1.x + f2.y * a1.y + f3.x * a1.z + f3.y * a1.w;
    float sd = f0.x * d0.x + f0.y * d0.y + f1.x * d0.z + f1.y * d0.w
             + f2.x * d1.x + f2.y * d1.y + f3.x * d1.z + f3.y * d1.w;
    #pragma unroll
    for (int o = 16; o > 0; o >>= 1) {
        ss += __shfl_down_sync(0xffffffffu, ss, o);
        sd += __shfl_down_sync(0xffffffffu, sd, o);
    }
    if (lane == 0) { g_ssrc[w] = ss; g_sdst[w] = sd; }
}

// ---- GAT gather: one warp per dst, fp16 xp rows; emits relu + hi/lo split ---
__global__ __launch_bounds__(256) void k_gather(const __half* __restrict__ xp16,
                                                const float* __restrict__ bias,
                                                __half* __restrict__ oh,
                                                __half* __restrict__ ol)
{
    int w = (blockIdx.x * blockDim.x + threadIdx.x) >> 5;
    int lane = threadIdx.x & 31;
    if (w >= Nn) return;
    int beg = g_offs[w], end = g_offs[w + 1];
    float sd = g_sdst[w];

    float part = 0.f;
    for (int i = beg + lane; i < end; i += 32) {
        float v = g_ssrc[g_adj[i]] + sd;
        v = v > 0.f ? v : NEG * v;
        part += expf(v);
    }
    #pragma unroll
    for (int o = 16; o > 0; o >>= 1) part += __shfl_xor_sync(0xffffffffu, part, o);
    float vs = g_ssrc[w] + sd;
    vs = vs > 0.f ? vs : NEG * vs;
    float ps = expf(vs);
    float invden = 1.f / (part + ps);

    // accumulators: 8 channels per lane (c = lane*8 .. lane*8+7)
    float acc[8];
    {
        float c0 = ps * invden;
        uint4 rv = ((const uint4*)(xp16 + (size_t)w * Hd))[lane];
        float2 f0 = __half22float2(*(__half2*)&rv.x);
        float2 f1 = __half22float2(*(__half2*)&rv.y);
        float2 f2 = __half22float2(*(__half2*)&rv.z);
        float2 f3 = __half22float2(*(__half2*)&rv.w);
        float4 b0 = ((const float4*)bias)[lane * 2];
        float4 b1 = ((const float4*)bias)[lane * 2 + 1];
        acc[0] = fmaf(c0, f0.x, b0.x); acc[1] = fmaf(c0, f0.y, b0.y);
        acc[2] = fmaf(c0, f1.x, b0.z); acc[3] = fmaf(c0, f1.y, b0.w);
        acc[4] = fmaf(c0, f2.x, b1.x); acc[5] = fmaf(c0, f2.y, b1.y);
        acc[6] = fmaf(c0, f3.x, b1.z); acc[7] = fmaf(c0, f3.y, b1.w);
    }

    for (int i = beg; i < end; i++) {
        int s = g_adj[i];
        float v = g_ssrc[s] + sd;
        v = v > 0.f ? v : NEG * v;
        float coef = expf(v) * invden;
        uint4 rv = ((const uint4*)(xp16 + (size_t)s * Hd))[lane];
        float2 f0 = __half22float2(*(__half2*)&rv.x);
        float2 f1 = __half22float2(*(__half2*)&rv.y);
        float2 f2 = __half22float2(*(__half2*)&rv.z);
        float2 f3 = __half22float2(*(__half2*)&rv.w);
        acc[0] = fmaf(coef, f0.x, acc[0]); acc[1] = fmaf(coef, f0.y, acc[1]);
        acc[2] = fmaf(coef, f1.x, acc[2]); acc[3] = fmaf(coef, f1.y, acc[3]);
        acc[4] = fmaf(coef, f2.x, acc[4]); acc[5] = fmaf(coef, f2.y, acc[5]);
        acc[6] = fmaf(coef, f3.x, acc[6]); acc[7] = fmaf(coef, f3.y, acc[7]);
    }

    // relu + fp16 hi/lo split, packed 16-B stores
    uint4 hs, ls;
    uint32_t* hw = (uint32_t*)&hs;
    uint32_t* lw = (uint32_t*)&ls;
    #pragma unroll
    for (int q = 0; q < 4; q++) {
        float v0 = fmaxf(acc[q * 2], 0.f), v1 = fmaxf(acc[q * 2 + 1], 0.f);
        __half h0, l0, h1, l1;
        f16split(v0, h0, l0);
        f16split(v1, h1, l1);
        hw[q] = (uint32_t)__half_as_ushort(h0) | ((uint32_t)__half_as_ushort(h1) << 16);
        lw[q] = (uint32_t)__half_as_ushort(l0) | ((uint32_t)__half_as_ushort(l1) << 16);
    }
    *(uint4*)(oh + (size_t)w * Hd + 8 * lane) = hs;
    *(uint4*)(ol + (size_t)w * Hd + 8 * lane) = ls;
}

// --------------- pooling: contiguous per-graph sum (batch sorted) -----------
__global__ __launch_bounds__(128) void k_pool_g(const float* __restrict__ hg,
                                                float* __restrict__ out)
{
    int g = blockIdx.x;
    int c = blockIdx.y * 128 + threadIdx.x;
    int beg = g_gstart[g], end = g_gstart[g + 1];
    float s = 0.f;
    for (int n = beg; n < end; n++) s += hg[(size_t)n * Hd + c];
    out[(size_t)g * (2 * Hd) + c] = s;
}

__global__ __launch_bounds__(256) void k_super(const float* __restrict__ Wf,
                                               const float* __restrict__ bf,
                                               float* __restrict__ out)
{
    __shared__ float s[Hd];
    int j = threadIdx.x;
    float sum = 0.f;
    for (int g = 0; g < Gg; g++) sum += out[(size_t)g * (2 * Hd) + j];
    s[j] = sum / (float)Gg;
    __syncthreads();
    float v = bf[j];
    #pragma unroll 8
    for (int c = 0; c < Hd; c++) v = fmaf(s[c], Wf[(size_t)j * Hd + c], v);
    v = fmaxf(v, 0.f);
    for (int g = 0; g < Gg; g++) out[(size_t)g * (2 * Hd) + Hd + j] = v;
}

// ------------------------------ launch --------------------------------------
extern "C" void kernel_launch(void* const* d_in, const int* in_sizes, int n_in,
                              void* d_out, int out_size)
{
    const float* x      = (const float*)d_in[0];
    const int*   ei32   = (const int*)d_in[1];
    const int*   b32    = (const int*)d_in[2];
    const float* W0     = (const float*)d_in[3];
    const float* a_src0 = (const float*)d_in[4];
    const float* a_dst0 = (const float*)d_in[5];
    const float* b0     = (const float*)d_in[6];
    const float* W1     = (const float*)d_in[7];
    const float* a_src1 = (const float*)d_in[8];
    const float* a_dst1 = (const float*)d_in[9];
    const float* b1     = (const float*)d_in[10];
    const float* W_ih   = (const float*)d_in[11];
    /* d_in[12] = W_hh: unused (h0 = 0) */
    const float* b_ih   = (const float*)d_in[13];
    const float* b_hh   = (const float*)d_in[14];
    const float* Wf     = (const float*)d_in[15];
    const float* bf     = (const float*)d_in[16];
    float*       out    = (float*)d_out;

    float *xp;
    __half *xp16, *ah, *al, *bt0h, *bt0l, *bt1h, *bihh;
    cudaGetSymbolAddress((void**)&xp,   g_xp);
    cudaGetSymbolAddress((void**)&xp16, g_xp16);
    cudaGetSymbolAddress((void**)&ah,   g_ah);
    cudaGetSymbolAddress((void**)&al,   g_al);
    cudaGetSymbolAddress((void**)&bt0h, g_bt0h);
    cudaGetSymbolAddress((void**)&bt0l, g_bt0l);
    cudaGetSymbolAddress((void**)&bt1h, g_bt1h);
    cudaGetSymbolAddress((void**)&bihh, g_bihh);

    const int SMEM  = 2 * BUFB;                          // 81920
    const int SMEMG = 2 * BUF2 + 2 * 128 * STSTR * 4;    // 193536
    cudaFuncSetAttribute(k_mm_f16<3>, cudaFuncAttributeMaxDynamicSharedMemorySize, SMEM);
    cudaFuncSetAttribute(k_mm_f16<2>, cudaFuncAttributeMaxDynamicSharedMemorySize, SMEM);
    cudaFuncSetAttribute(k_mm_gru, cudaFuncAttributeMaxDynamicSharedMemorySize, SMEMG);

    const int MT = (Nn + 127) / 128;   // 391
    dim3 blk(256);

    k_detect<<<1, 1>>>(ei32);
    k_decode_batch<<<(Nn + 255) / 256, blk>>>(b32);
    k_decode_count<<<(Ee + 255) / 256, blk>>>(ei32);
    k_prep_w<<<(768 * 256 + 255) / 256, blk>>>(W0, W1, W_ih);
    k_split_x<<<(Nn * INC / 4 + 255) / 256, blk>>>(x, Nn * INC / 4);

    // ---- GAT layer 0 GEMM (3-term) ----  (profile slot 6)
    k_mm_f16<3><<<dim3(2, MT), blk, SMEM>>>(ah, al, bt0h, bt0l, xp16, Nn, Hd, INC);

    // ---- CSR + graph boundaries ----
    k_scan<<<1, 1024>>>();
    k_fill<<<(Ee + 255) / 256, blk>>>();
    k_gstart<<<1, Gg + 1>>>();

    // ---- GAT layer 0 attention + aggregate ----
    k_node_prep<<<(Nn * 32 + 255) / 256, blk>>>(xp16, a_src0, a_dst0);
    k_gather<<<(Nn * 32 + 255) / 256, blk>>>(xp16, b0, ah, al);

    // ---- GAT layer 1 (2-term) ----
    k_mm_f16<2><<<dim3(2, MT), blk, SMEM>>>(ah, al, bt1h, (const __half*)bt1h, xp16, Nn, Hd, Hd);
    k_node_prep<<<(Nn * 32 + 255) / 256, blk>>>(xp16, a_src1, a_dst1);
    k_gather<<<(Nn * 32 + 255) / 256, blk>>>(xp16, b1, ah, al);

    // ---- fused GRU GEMM + gates -> h (xp fp32) ----
    k_mm_gru<<<dim3(2, MT), blk, SMEMG>>>(ah, al, bihh, b_ih, b_hh, xp, Nn);

    // ---- pooling + super node ----
    k_pool_g<<<dim3(Gg, 2), 128>>>(xp, out);
    k_super<<<1, Hd>>>(Wf, bf, out);
}

// round 11
// speedup vs baseline: 1.8951x; 1.0346x over previous
#include <cuda_runtime.h>
#include <cuda_fp16.h>
#include <math.h>
#include <stdint.h>

#define Nn   50000
#define Ee   800000
#define INC  128
#define Hd   256
#define Gg   128
#define NEG  0.2f

// ---------------- scratch (device globals; no allocations allowed) ----------
__device__ float  g_xp[(size_t)Nn * Hd];          // GRU output (fp32, for pool)
__device__ __half g_xp16[(size_t)Nn * Hd];        // GAT projected features (fp16)
__device__ float g_ssrc0[Nn], g_sdst0[Nn], g_den0[Nn];
__device__ float g_ssrc1[Nn], g_sdst1[Nn], g_den1[Nn];
__device__ float g_p[Ee];                          // edge exp-weights (CSR order)
__device__ int   g_src[Ee];
__device__ int   g_dst[Ee];
__device__ int   g_batch[Nn];
__device__ int   g_cnt[Nn];
__device__ int   g_cur[Nn];
__device__ int   g_offs[Nn + 1];
__device__ int   g_adj[Ee];                        // CSR: src ids grouped by dst
__device__ int   g_adjd[Ee];                       // CSR: dst id per slot
__device__ int   g_gstart[Gg + 1];
__device__ int   g_is64;
// fp16-split A (reused across the three GEMMs)
__device__ __half g_ah[(size_t)Nn * Hd], g_al[(size_t)Nn * Hd];
// fp16-split weights, stored [N][K] (B^T layout, K contiguous -> mma row.col)
__device__ __half g_bt0h[256 * 128], g_bt0l[256 * 128];
__device__ __half g_bt1h[256 * 256];
__device__ __half g_bihh[768 * 256];

// ---------------------------- PTX helpers -----------------------------------
__device__ __forceinline__ uint32_t smem_u32(const void* p) {
    uint32_t a;
    asm("{ .reg .u64 t; cvta.to.shared.u64 t, %1; cvt.u32.u64 %0, t; }" : "=r"(a) : "l"(p));
    return a;
}
__device__ __forceinline__ void ldsm4(uint32_t& r0, uint32_t& r1, uint32_t& r2, uint32_t& r3,
                                      uint32_t addr) {
    asm volatile("ldmatrix.sync.aligned.m8n8.x4.shared.b16 {%0,%1,%2,%3}, [%4];"
                 : "=r"(r0), "=r"(r1), "=r"(r2), "=r"(r3) : "r"(addr));
}
__device__ __forceinline__ void mma16816(float* d, const uint32_t* a, const uint32_t* b) {
    asm volatile("mma.sync.aligned.m16n8k16.row.col.f32.f16.f16.f32 "
                 "{%0,%1,%2,%3}, {%4,%5,%6,%7}, {%8,%9}, {%0,%1,%2,%3};"
                 : "+f"(d[0]), "+f"(d[1]), "+f"(d[2]), "+f"(d[3])
                 : "r"(a[0]), "r"(a[1]), "r"(a[2]), "r"(a[3]), "r"(b[0]), "r"(b[1]));
}
__device__ __forceinline__ void cpa16(uint32_t dst, const void* src, uint32_t sz) {
    asm volatile("cp.async.cg.shared.global [%0], [%1], 16, %2;"
                 :: "r"(dst), "l"(src), "r"(sz) : "memory");
}
__device__ __forceinline__ void cpa_commit() {
    asm volatile("cp.async.commit_group;" ::: "memory");
}
template<int N> __device__ __forceinline__ void cpa_wait() {
    asm volatile("cp.async.wait_group %0;" :: "n"(N) : "memory");
}

// ---------------- fp16 hi/lo split helpers -----------------------------------
__device__ __forceinline__ void f16split(float w, __half& h, __half& l) {
    h = __float2half_rn(w);
    l = __float2half_rn(w - __half2float(h));
}

// ---------------- index dtype detection + decode ----------------------------
__global__ void k_detect(const int* __restrict__ ei32)
{
    int is64 = 1;
    for (int i = 0; i < 64; i++)
        if (ei32[2 * i + 1] != 0) { is64 = 0; break; }
    g_is64 = is64;
}
__global__ void k_decode_batch(const int* __restrict__ b32)
{
    int n = blockIdx.x * blockDim.x + threadIdx.x;
    if (n >= Nn) return;
    g_batch[n] = g_is64 ? b32[2 * n] : b32[n];
    g_cnt[n] = 0;  g_cur[n] = 0;
    g_ssrc0[n] = 0.f; g_sdst0[n] = 0.f; g_den0[n] = 0.f;
    g_ssrc1[n] = 0.f; g_sdst1[n] = 0.f; g_den1[n] = 0.f;
}
__global__ void k_decode_count(const int* __restrict__ ei32)
{
    int e = blockIdx.x * blockDim.x + threadIdx.x;
    if (e >= Ee) return;
    int s, d;
    if (g_is64) { s = ei32[2 * e]; d = ei32[2 * (Ee + e)]; }
    else        { s = ei32[e];     d = ei32[Ee + e]; }
    g_src[e] = s;
    g_dst[e] = d;
    atomicAdd(&g_cnt[d], 1);
}

// ---------------- weight prep: transpose + fp16 hi/lo split -----------------
__global__ void k_prep_w(const float* __restrict__ W0, const float* __restrict__ W1,
                         const float* __restrict__ Wih)
{
    int t = blockIdx.x * blockDim.x + threadIdx.x;
    if (t < 256 * 128) {                       // Bt0[n][k] = W0[k][n]
        int n = t >> 7, k = t & 127;
        f16split(W0[k * 256 + n], g_bt0h[t], g_bt0l[t]);
    }
    if (t < 256 * 256) {                       // Bt1[n][k] = W1[k][n]  (hi only)
        int n = t >> 8, k = t & 255;
        g_bt1h[t] = __float2half_rn(W1[k * 256 + n]);
    }
    if (t < 768 * 256) {                       // Bih[n][k] = W_ih[n][k] (hi only)
        g_bihh[t] = __float2half_rn(Wih[t]);
    }
}

// ---------------- A split for x: fp32 -> fp16 hi/lo --------------------------
__global__ __launch_bounds__(256) void k_split_x(const float* __restrict__ src, int n4)
{
    int t = blockIdx.x * blockDim.x + threadIdx.x;
    if (t >= n4) return;
    float4 v = ((const float4*)src)[t];
    float f[4] = {v.x, v.y, v.z, v.w};
    ushort4 hs, ls;
    __half hb, lb;
    f16split(f[0], hb, lb); hs.x = __half_as_ushort(hb); ls.x = __half_as_ushort(lb);
    f16split(f[1], hb, lb); hs.y = __half_as_ushort(hb); ls.y = __half_as_ushort(lb);
    f16split(f[2], hb, lb); hs.z = __half_as_ushort(hb); ls.z = __half_as_ushort(lb);
    f16split(f[3], hb, lb); hs.w = __half_as_ushort(hb); ls.w = __half_as_ushort(lb);
    ((ushort4*)g_ah)[t] = hs;
    ((ushort4*)g_al)[t] = ls;
}

// -------- pipelined fp16 GEMM: C16 = Asplit @ Bt^T, + attention-dot epilogue -
// NT=3: Ah*Bh + Al*Bh + Ah*Bl. NT=2: Ah*Bh + Al*Bh. Output packed fp16.
// Epilogue also dots fragments with avs/avd and atomically accumulates
// per-row s_src / s_dst (partials over this CTA's 128 columns).
#define SSTRIDE 40                       // fp16 per SMEM row (80 B)
#define ABYTES  (128 * SSTRIDE * 2)      // 10240 B per array
#define BUFB    (4 * ABYTES)             // 40960 B per stage
template<int NT>
__global__ __launch_bounds__(256, 2) void k_mm_f16(const __half* __restrict__ AH,
                                                   const __half* __restrict__ AL,
                                                   const __half* __restrict__ BtH,
                                                   const __half* __restrict__ BtL,
                                                   __half* __restrict__ C16,
                                                   const float* __restrict__ avs,
                                                   const float* __restrict__ avd,
                                                   float* __restrict__ ssrc,
                                                   float* __restrict__ sdst,
                                                   int M, int Nc, int K)
{
    extern __shared__ char smem[];
    const uint32_t sb = smem_u32(smem);

    const int tid  = threadIdx.x;
    const int wid  = tid >> 5, lane = tid & 31;
    const int wm   = wid & 1, wn = wid >> 1;
    const int row0 = blockIdx.y * 128, col0 = blockIdx.x * 128;

    uint32_t aoff[4];
    #pragma unroll
    for (int mi = 0; mi < 4; mi++) {
        int r = wm * 64 + mi * 16 + (lane & 7) + ((lane >> 3) & 1) * 8;
        aoff[mi] = (uint32_t)(r * (SSTRIDE * 2) + (lane >> 4) * 16);
    }
    uint32_t boff[2];
    #pragma unroll
    for (int jp = 0; jp < 2; jp++) {
        int n = wn * 32 + jp * 16 + (lane & 7) + ((lane >> 4) & 1) * 8;
        boff[jp] = (uint32_t)(n * (SSTRIDE * 2) + ((lane >> 3) & 1) * 16);
    }

    float acc[4][4][4];
    #pragma unroll
    for (int i = 0; i < 4; i++)
        #pragma unroll
        for (int j = 0; j < 4; j++)
            #pragma unroll
            for (int q = 0; q < 4; q++) acc[i][j][q] = 0.f;

    const int nit = K >> 5;
    auto issue = [&](int kt, int p) {
        #pragma unroll
        for (int c = 0; c < 2; c++) {
            int lin = tid + c * 256;
            int row = lin >> 2, q = lin & 3;
            uint32_t sd = sb + (uint32_t)(p * BUFB + row * (SSTRIDE * 2) + q * 16);
            int ar = row0 + row;
            uint32_t asz = (ar < M) ? 16u : 0u;
            if (ar >= M) ar = 0;
            size_t aoffg = (size_t)ar * K + kt * 32 + q * 8;
            size_t boffg = (size_t)(col0 + row) * K + kt * 32 + q * 8;
            cpa16(sd,              AH + aoffg, asz);
            cpa16(sd + ABYTES,     AL + aoffg, asz);
            cpa16(sd + 2 * ABYTES, BtH + boffg, 16u);
            if (NT == 3)
                cpa16(sd + 3 * ABYTES, BtL + boffg, 16u);
        }
        cpa_commit();
    };

    issue(0, 0);
    for (int kt = 0; kt < nit; kt++) {
        const int p = kt & 1;
        if (kt + 1 < nit) { issue(kt + 1, p ^ 1); cpa_wait<1>(); }
        else              { cpa_wait<0>(); }
        __syncthreads();

        const uint32_t uAh = sb + p * BUFB;
        const uint32_t uAl = uAh + ABYTES;
        const uint32_t uBh = uAh + 2 * ABYTES;
        const uint32_t uBl = uAh + 3 * ABYTES;

        #pragma unroll
        for (int ks = 0; ks < 2; ks++) {
            const uint32_t kb = (uint32_t)(ks * 32);
            uint32_t ah[4][4], al[4][4], bf[4][2];
            #pragma unroll
            for (int mi = 0; mi < 4; mi++) {
                ldsm4(ah[mi][0], ah[mi][1], ah[mi][2], ah[mi][3], uAh + aoff[mi] + kb);
                ldsm4(al[mi][0], al[mi][1], al[mi][2], al[mi][3], uAl + aoff[mi] + kb);
            }
            #pragma unroll
            for (int jp = 0; jp < 2; jp++)
                ldsm4(bf[jp * 2][0], bf[jp * 2][1], bf[jp * 2 + 1][0], bf[jp * 2 + 1][1],
                      uBh + boff[jp] + kb);
            #pragma unroll
            for (int mi = 0; mi < 4; mi++)
                #pragma unroll
                for (int nj = 0; nj < 4; nj++) {
                    mma16816(acc[mi][nj], ah[mi], bf[nj]);
                    mma16816(acc[mi][nj], al[mi], bf[nj]);
                }
            if (NT == 3) {
                #pragma unroll
                for (int jp = 0; jp < 2; jp++)
                    ldsm4(bf[jp * 2][0], bf[jp * 2][1], bf[jp * 2 + 1][0], bf[jp * 2 + 1][1],
                          uBl + boff[jp] + kb);
                #pragma unroll
                for (int mi = 0; mi < 4; mi++)
                    #pragma unroll
                    for (int nj = 0; nj < 4; nj++)
                        mma16816(acc[mi][nj], ah[mi], bf[nj]);
            }
        }
        __syncthreads();
    }

    // ---- attention-dot vectors for this thread's columns ----
    float as0[4], as1[4], ad0[4], ad1[4];
    #pragma unroll
    for (int nj = 0; nj < 4; nj++) {
        int c = col0 + wn * 32 + (lane & 3) * 2 + nj * 8;
        as0[nj] = avs[c]; as1[nj] = avs[c + 1];
        ad0[nj] = avd[c]; ad1[nj] = avd[c + 1];
    }

    #pragma unroll
    for (int mi = 0; mi < 4; mi++) {
        int r0g = row0 + wm * 64 + mi * 16 + (lane >> 2);
        int cg  = col0 + wn * 32 + (lane & 3) * 2;
        float pss0 = 0.f, psd0 = 0.f, pss1 = 0.f, psd1 = 0.f;
        #pragma unroll
        for (int nj = 0; nj < 4; nj++) {
            int c = cg + nj * 8;
            if (r0g < M)
                *(__half2*)(C16 + (size_t)r0g * Nc + c) =
                    __floats2half2_rn(acc[mi][nj][0], acc[mi][nj][1]);
            if (r0g + 8 < M)
                *(__half2*)(C16 + (size_t)(r0g + 8) * Nc + c) =
                    __floats2half2_rn(acc[mi][nj][2], acc[mi][nj][3]);
            pss0 = fmaf(acc[mi][nj][0], as0[nj], fmaf(acc[mi][nj][1], as1[nj], pss0));
            psd0 = fmaf(acc[mi][nj][0], ad0[nj], fmaf(acc[mi][nj][1], ad1[nj], psd0));
            pss1 = fmaf(acc[mi][nj][2], as0[nj], fmaf(acc[mi][nj][3], as1[nj], pss1));
            psd1 = fmaf(acc[mi][nj][2], ad0[nj], fmaf(acc[mi][nj][3], ad1[nj], psd1));
        }
        // reduce across the 4 lanes of the quad (same row)
        pss0 += __shfl_xor_sync(0xffffffffu, pss0, 1);
        pss0 += __shfl_xor_sync(0xffffffffu, pss0, 2);
        psd0 += __shfl_xor_sync(0xffffffffu, psd0, 1);
        psd0 += __shfl_xor_sync(0xffffffffu, psd0, 2);
        pss1 += __shfl_xor_sync(0xffffffffu, pss1, 1);
        pss1 += __shfl_xor_sync(0xffffffffu, pss1, 2);
        psd1 += __shfl_xor_sync(0xffffffffu, psd1, 1);
        psd1 += __shfl_xor_sync(0xffffffffu, psd1, 2);
        if ((lane & 3) == 0) {
            if (r0g < M) {
                atomicAdd(&ssrc[r0g], pss0);
                atomicAdd(&sdst[r0g], psd0);
            }
            if (r0g + 8 < M) {
                atomicAdd(&ssrc[r0g + 8], pss1);
                atomicAdd(&sdst[r0g + 8], psd1);
            }
        }
    }
}

// -------- fused GRU GEMM: 3 gate passes (r,z,n) + gate math in epilogue ------
#define BUF2   (3 * ABYTES)              // 30720 B per stage (Ah, Al, Bh)
#define STSTR  129                       // stash stride (floats)
__global__ __launch_bounds__(256, 1) void k_mm_gru(const __half* __restrict__ AH,
                                                   const __half* __restrict__ AL,
                                                   const __half* __restrict__ BtH,
                                                   const float* __restrict__ b_ih,
                                                   const float* __restrict__ b_hh,
                                                   float* __restrict__ OUT,
                                                   int M)
{
    extern __shared__ char smem[];
    const uint32_t sb = smem_u32(smem);
    float* stash_r = (float*)(smem + 2 * BUF2);
    float* stash_z = stash_r + 128 * STSTR;

    const int tid  = threadIdx.x;
    const int wid  = tid >> 5, lane = tid & 31;
    const int wm   = wid & 1, wn = wid >> 1;
    const int row0 = blockIdx.y * 128, col0 = blockIdx.x * 128;
    const int K = Hd;
    const int nit = K >> 5;

    uint32_t aoff[4];
    #pragma unroll
    for (int mi = 0; mi < 4; mi++) {
        int r = wm * 64 + mi * 16 + (lane & 7) + ((lane >> 3) & 1) * 8;
        aoff[mi] = (uint32_t)(r * (SSTRIDE * 2) + (lane >> 4) * 16);
    }
    uint32_t boff[2];
    #pragma unroll
    for (int jp = 0; jp < 2; jp++) {
        int n = wn * 32 + jp * 16 + (lane & 7) + ((lane >> 4) & 1) * 8;
        boff[jp] = (uint32_t)(n * (SSTRIDE * 2) + ((lane >> 3) & 1) * 16);
    }

    for (int gate = 0; gate < 3; gate++) {
        float acc[4][4][4];
        #pragma unroll
        for (int i = 0; i < 4; i++)
            #pragma unroll
            for (int j = 0; j < 4; j++)
                #pragma unroll
                for (int q = 0; q < 4; q++) acc[i][j][q] = 0.f;

        const int brow0 = gate * 256 + col0;
        auto issue = [&](int kt, int p) {
            #pragma unroll
            for (int c = 0; c < 2; c++) {
                int lin = tid + c * 256;
                int row = lin >> 2, q = lin & 3;
                uint32_t sd = sb + (uint32_t)(p * BUF2 + row * (SSTRIDE * 2) + q * 16);
                int ar = row0 + row;
                uint32_t asz = (ar < M) ? 16u : 0u;
                if (ar >= M) ar = 0;
                size_t aoffg = (size_t)ar * K + kt * 32 + q * 8;
                size_t boffg = (size_t)(brow0 + row) * K + kt * 32 + q * 8;
                cpa16(sd,              AH + aoffg, asz);
                cpa16(sd + ABYTES,     AL + aoffg, asz);
                cpa16(sd + 2 * ABYTES, BtH + boffg, 16u);
            }
            cpa_commit();
        };

        issue(0, 0);
        for (int kt = 0; kt < nit; kt++) {
            const int p = kt & 1;
            if (kt + 1 < nit) { issue(kt + 1, p ^ 1); cpa_wait<1>(); }
            else              { cpa_wait<0>(); }
            __syncthreads();

            const uint32_t uAh = sb + p * BUF2;
            const uint32_t uAl = uAh + ABYTES;
            const uint32_t uBh = uAh + 2 * ABYTES;

            #pragma unroll
            for (int ks = 0; ks < 2; ks++) {
                const uint32_t kb = (uint32_t)(ks * 32);
                uint32_t ah[4][4], al[4][4], bf[4][2];
                #pragma unroll
                for (int mi = 0; mi < 4; mi++) {
                    ldsm4(ah[mi][0], ah[mi][1], ah[mi][2], ah[mi][3], uAh + aoff[mi] + kb);
                    ldsm4(al[mi][0], al[mi][1], al[mi][2], al[mi][3], uAl + aoff[mi] + kb);
                }
                #pragma unroll
                for (int jp = 0; jp < 2; jp++)
                    ldsm4(bf[jp * 2][0], bf[jp * 2][1], bf[jp * 2 + 1][0], bf[jp * 2 + 1][1],
                          uBh + boff[jp] + kb);
                #pragma unroll
                for (int mi = 0; mi < 4; mi++)
                    #pragma unroll
                    for (int nj = 0; nj < 4; nj++) {
                        mma16816(acc[mi][nj], ah[mi], bf[nj]);
                        mma16816(acc[mi][nj], al[mi], bf[nj]);
                    }
            }
            __syncthreads();
        }

        if (gate < 2) {
            float* st = (gate == 0) ? stash_r : stash_z;
            const int go = gate * 256 + col0;
            #pragma unroll
            for (int mi = 0; mi < 4; mi++) {
                int rl = wm * 64 + mi * 16 + (lane >> 2);
                #pragma unroll
                for (int nj = 0; nj < 4; nj++) {
                    int cl = wn * 32 + (lane & 3) * 2 + nj * 8;
                    float bs0 = b_ih[go + cl]     + b_hh[go + cl];
                    float bs1 = b_ih[go + cl + 1] + b_hh[go + cl + 1];
                    st[rl * STSTR + cl]           = 1.f / (1.f + expf(-(acc[mi][nj][0] + bs0)));
                    st[rl * STSTR + cl + 1]       = 1.f / (1.f + expf(-(acc[mi][nj][1] + bs1)));
                    st[(rl + 8) * STSTR + cl]     = 1.f / (1.f + expf(-(acc[mi][nj][2] + bs0)));
                    st[(rl + 8) * STSTR + cl + 1] = 1.f / (1.f + expf(-(acc[mi][nj][3] + bs1)));
                }
            }
        } else {
            const int go = 512 + col0;
            #pragma unroll
            for (int mi = 0; mi < 4; mi++) {
                int rl = wm * 64 + mi * 16 + (lane >> 2);
                int gr0 = row0 + rl, gr1 = gr0 + 8;
                #pragma unroll
                for (int nj = 0; nj < 4; nj++) {
                    int cl = wn * 32 + (lane & 3) * 2 + nj * 8;
                    float bi0 = b_ih[go + cl],     bh0 = b_hh[go + cl];
                    float bi1 = b_ih[go + cl + 1], bh1 = b_hh[go + cl + 1];
                    {
                        float r0 = stash_r[rl * STSTR + cl],     z0 = stash_z[rl * STSTR + cl];
                        float r1 = stash_r[rl * STSTR + cl + 1], z1 = stash_z[rl * STSTR + cl + 1];
                        float h0 = (1.f - z0) * tanhf(acc[mi][nj][0] + bi0 + r0 * bh0);
                        float h1 = (1.f - z1) * tanhf(acc[mi][nj][1] + bi1 + r1 * bh1);
                        if (gr0 < M)
                            *(float2*)(OUT + (size_t)gr0 * Hd + col0 + cl) = make_float2(h0, h1);
                    }
                    {
                        float r0 = stash_r[(rl + 8) * STSTR + cl],     z0 = stash_z[(rl + 8) * STSTR + cl];
                        float r1 = stash_r[(rl + 8) * STSTR + cl + 1], z1 = stash_z[(rl + 8) * STSTR + cl + 1];
                        float h0 = (1.f - z0) * tanhf(acc[mi][nj][2] + bi0 + r0 * bh0);
                        float h1 = (1.f - z1) * tanhf(acc[mi][nj][3] + bi1 + r1 * bh1);
                        if (gr1 < M)
                            *(float2*)(OUT + (size_t)gr1 * Hd + col0 + cl) = make_float2(h0, h1);
                    }
                }
            }
        }
    }
}

// ------------------------------ CSR build -----------------------------------
__global__ __launch_bounds__(1024) void k_scan(void)
{
    __shared__ int ssum[1024];
    const int CH = (Nn + 1023) / 1024;
    int tid = threadIdx.x;
    int base = tid * CH;
    int s = 0;
    for (int j = 0; j < CH; j++) {
        int idx = base + j;
        if (idx < Nn) s += g_cnt[idx];
    }
    ssum[tid] = s;
    __syncthreads();
    for (int off = 1; off < 1024; off <<= 1) {
        int v = (tid >= off) ? ssum[tid - off] : 0;
        __syncthreads();
        ssum[tid] += v;
        __syncthreads();
    }
    int run = (tid > 0) ? ssum[tid - 1] : 0;
    for (int j = 0; j < CH; j++) {
        int idx = base + j;
        if (idx < Nn) { g_offs[idx] = run; run += g_cnt[idx]; }
    }
    if (tid == 1023) g_offs[Nn] = ssum[1023];
}
__global__ void k_fill(void)
{
    int e = blockIdx.x * blockDim.x + threadIdx.x;
    if (e >= Ee) return;
    int d = g_dst[e];
    int pos = atomicAdd(&g_cur[d], 1);
    int slot = g_offs[d] + pos;
    g_adj[slot]  = g_src[e];
    g_adjd[slot] = d;
}

// ---- edge weights: p[i] = exp(lrelu(ssrc[src]+sdst[dst])); den[dst] += p ----
__global__ __launch_bounds__(256) void k_edgep(const float* __restrict__ ssrc,
                                               const float* __restrict__ sdst,
                                               float* __restrict__ den)
{
    int i = blockIdx.x * blockDim.x + threadIdx.x;
    if (i >= Ee) return;
    int s = g_adj[i], d = g_adjd[i];
    float v = ssrc[s] + sdst[d];
    v = v > 0.f ? v : NEG * v;
    float pp = expf(v);
    g_p[i] = pp;
    atomicAdd(&den[d], pp);
}

// -------- graph boundaries (batch is sorted): gstart[g] = lower_bound(g) ----
__global__ void k_gstart(void)
{
    int g = threadIdx.x;
    if (g > Gg) return;
    if (g == Gg) { g_gstart[g] = Nn; return; }
    int lo = 0, hi = Nn;
    while (lo < hi) {
        int mid = (lo + hi) >> 1;
        if (g_batch[mid] < g) lo = mid + 1; else hi = mid;
    }
    g_gstart[g] = lo;
}

// ---- GAT gather: one warp per dst; p precomputed; emits relu + hi/lo split --
__global__ __launch_bounds__(256) void k_gather(const __half* __restrict__ xp16,
                                                const float* __restrict__ bias,
                                                const float* __restrict__ ssrc,
                                                const float* __restrict__ sdst,
                                                const float* __restrict__ den,
                                                __half* __restrict__ oh,
                                                __half* __restrict__ ol)
{
    int w = (blockIdx.x * blockDim.x + threadIdx.x) >> 5;
    int lane = threadIdx.x & 31;
    if (w >= Nn) return;
    int beg = g_offs[w], end = g_offs[w + 1];

    // self-loop weight + total denominator
    float vs = ssrc[w] + sdst[w];
    vs = vs > 0.f ? vs : NEG * vs;
    float ps = expf(vs);
    float inv = 1.f / (den[w] + ps);

    // accumulators: 8 channels per lane; start with self term
    float acc[8];
    {
        uint4 rv = ((const uint4*)(xp16 + (size_t)w * Hd))[lane];
        float2 f0 = __half22float2(*(__half2*)&rv.x);
        float2 f1 = __half22float2(*(__half2*)&rv.y);
        float2 f2 = __half22float2(*(__half2*)&rv.z);
        float2 f3 = __half22float2(*(__half2*)&rv.w);
        acc[0] = ps * f0.x; acc[1] = ps * f0.y;
        acc[2] = ps * f1.x; acc[3] = ps * f1.y;
        acc[4] = ps * f2.x; acc[5] = ps * f2.y;
        acc[6] = ps * f3.x; acc[7] = ps * f3.y;
    }

    // main loop, 4-wide: independent row loads in flight
    int i = beg;
    for (; i + 4 <= end; i += 4) {
        int s0 = g_adj[i], s1 = g_adj[i + 1], s2 = g_adj[i + 2], s3 = g_adj[i + 3];
        float c0 = g_p[i], c1 = g_p[i + 1], c2 = g_p[i + 2], c3 = g_p[i + 3];
        uint4 r0 = ((const uint4*)(xp16 + (size_t)s0 * Hd))[lane];
        uint4 r1 = ((const uint4*)(xp16 + (size_t)s1 * Hd))[lane];
        uint4 r2 = ((const uint4*)(xp16 + (size_t)s2 * Hd))[lane];
        uint4 r3 = ((const uint4*)(xp16 + (size_t)s3 * Hd))[lane];
        #pragma unroll
        for (int q = 0; q < 4; q++) {
            uint32_t* rw;
            float cc;
            if (q == 0) { rw = (uint32_t*)&r0; cc = c0; }
            else if (q == 1) { rw = (uint32_t*)&r1; cc = c1; }
            else if (q == 2) { rw = (uint32_t*)&r2; cc = c2; }
            else { rw = (uint32_t*)&r3; cc = c3; }
            #pragma unroll
            for (int h = 0; h < 4; h++) {
                float2 f = __half22float2(*(__half2*)&rw[h]);
                acc[h * 2]     = fmaf(cc, f.x, acc[h * 2]);
                acc[h * 2 + 1] = fmaf(cc, f.y, acc[h * 2 + 1]);
            }
        }
    }
    for (; i < end; i++) {
        int s = g_adj[i];
        float cc = g_p[i];
        uint4 rv = ((const uint4*)(xp16 + (size_t)s * Hd))[lane];
        uint32_t* rw = (uint32_t*)&rv;
        #pragma unroll
        for (int h = 0; h < 4; h++) {
            float2 f = __half22float2(*(__half2*)&rw[h]);
            acc[h * 2]     = fmaf(cc, f.x, acc[h * 2]);
            acc[h * 2 + 1] = fmaf(cc, f.y, acc[h * 2 + 1]);
        }
    }

    // normalize + bias + relu + fp16 hi/lo split, packed 16-B stores
    float4 b0 = ((const float4*)bias)[lane * 2];
    float4 b1 = ((const float4*)bias)[lane * 2 + 1];
    float bb[8] = {b0.x, b0.y, b0.z, b0.w, b1.x, b1.y, b1.z, b1.w};
    uint4 hs, ls;
    uint32_t* hw = (uint32_t*)&hs;
    uint32_t* lw = (uint32_t*)&ls;
    #pragma unroll
    for (int q = 0; q < 4; q++) {
        float v0 = fmaxf(fmaf(acc[q * 2], inv, bb[q * 2]), 0.f);
        float v1 = fmaxf(fmaf(acc[q * 2 + 1], inv, bb[q * 2 + 1]), 0.f);
        __half h0, l0, h1, l1;
        f16split(v0, h0, l0);
        f16split(v1, h1, l1);
        hw[q] = (uint32_t)__half_as_ushort(h0) | ((uint32_t)__half_as_ushort(h1) << 16);
        lw[q] = (uint32_t)__half_as_ushort(l0) | ((uint32_t)__half_as_ushort(l1) << 16);
    }
    *(uint4*)(oh + (size_t)w * Hd + 8 * lane) = hs;
    *(uint4*)(ol + (size_t)w * Hd + 8 * lane) = ls;
}

// --------------- pooling: contiguous per-graph sum (batch sorted) -----------
__global__ __launch_bounds__(128) void k_pool_g(const float* __restrict__ hg,
                                                float* __restrict__ out)
{
    int g = blockIdx.x;
    int c = blockIdx.y * 128 + threadIdx.x;
    int beg = g_gstart[g], end = g_gstart[g + 1];
    float s = 0.f;
    for (int n = beg; n < end; n++) s += hg[(size_t)n * Hd + c];
    out[(size_t)g * (2 * Hd) + c] = s;
}

__global__ __launch_bounds__(256) void k_super(const float* __restrict__ Wf,
                                               const float* __restrict__ bf,
                                               float* __restrict__ out)
{
    __shared__ float s[Hd];
    int j = threadIdx.x;
    float sum = 0.f;
    for (int g = 0; g < Gg; g++) sum += out[(size_t)g * (2 * Hd) + j];
    s[j] = sum / (float)Gg;
    __syncthreads();
    float v = bf[j];
    #pragma unroll 8
    for (int c = 0; c < Hd; c++) v = fmaf(s[c], Wf[(size_t)j * Hd + c], v);
    v = fmaxf(v, 0.f);
    for (int g = 0; g < Gg; g++) out[(size_t)g * (2 * Hd) + Hd + j] = v;
}

// ------------------------------ launch --------------------------------------
extern "C" void kernel_launch(void* const* d_in, const int* in_sizes, int n_in,
                              void* d_out, int out_size)
{
    const float* x      = (const float*)d_in[0];
    const int*   ei32   = (const int*)d_in[1];
    const int*   b32    = (const int*)d_in[2];
    const float* W0     = (const float*)d_in[3];
    const float* a_src0 = (const float*)d_in[4];
    const float* a_dst0 = (const float*)d_in[5];
    const float* b0     = (const float*)d_in[6];
    const float* W1     = (const float*)d_in[7];
    const float* a_src1 = (const float*)d_in[8];
    const float* a_dst1 = (const float*)d_in[9];
    const float* b1     = (const float*)d_in[10];
    const float* W_ih   = (const float*)d_in[11];
    /* d_in[12] = W_hh: unused (h0 = 0) */
    const float* b_ih   = (const float*)d_in[13];
    const float* b_hh   = (const float*)d_in[14];
    const float* Wf     = (const float*)d_in[15];
    const float* bf     = (const float*)d_in[16];
    float*       out    = (float*)d_out;

    float *xp, *ssrc0, *sdst0, *den0, *ssrc1, *sdst1, *den1;
    __half *xp16, *ah, *al, *bt0h, *bt0l, *bt1h, *bihh;
    cudaGetSymbolAddress((void**)&xp,    g_xp);
    cudaGetSymbolAddress((void**)&xp16,  g_xp16);
    cudaGetSymbolAddress((void**)&ssrc0, g_ssrc0);
    cudaGetSymbolAddress((void**)&sdst0, g_sdst0);
    cudaGetSymbolAddress((void**)&den0,  g_den0);
    cudaGetSymbolAddress((void**)&ssrc1, g_ssrc1);
    cudaGetSymbolAddress((void**)&sdst1, g_sdst1);
    cudaGetSymbolAddress((void**)&den1,  g_den1);
    cudaGetSymbolAddress((void**)&ah,    g_ah);
    cudaGetSymbolAddress((void**)&al,    g_al);
    cudaGetSymbolAddress((void**)&bt0h,  g_bt0h);
    cudaGetSymbolAddress((void**)&bt0l,  g_bt0l);
    cudaGetSymbolAddress((void**)&bt1h,  g_bt1h);
    cudaGetSymbolAddress((void**)&bihh,  g_bihh);

    const int SMEM  = 2 * BUFB;                          // 81920
    const int SMEMG = 2 * BUF2 + 2 * 128 * STSTR * 4;    // 193536
    cudaFuncSetAttribute(k_mm_f16<3>, cudaFuncAttributeMaxDynamicSharedMemorySize, SMEM);
    cudaFuncSetAttribute(k_mm_f16<2>, cudaFuncAttributeMaxDynamicSharedMemorySize, SMEM);
    cudaFuncSetAttribute(k_mm_gru, cudaFuncAttributeMaxDynamicSharedMemorySize, SMEMG);

    const int MT = (Nn + 127) / 128;   // 391
    dim3 blk(256);

    k_detect<<<1, 1>>>(ei32);
    k_decode_batch<<<(Nn + 255) / 256, blk>>>(b32);
    k_decode_count<<<(Ee + 255) / 256, blk>>>(ei32);
    k_prep_w<<<(768 * 256 + 255) / 256, blk>>>(W0, W1, W_ih);
    k_split_x<<<(Nn * INC / 4 + 255) / 256, blk>>>(x, Nn * INC / 4);

    // ---- GAT layer 0 GEMM (3-term) + fused attention dots ----
    k_mm_f16<3><<<dim3(2, MT), blk, SMEM>>>(ah, al, bt0h, bt0l, xp16,
                                            a_src0, a_dst0, ssrc0, sdst0, Nn, Hd, INC);

    // ---- CSR + graph boundaries ----
    k_scan<<<1, 1024>>>();
    k_fill<<<(Ee + 255) / 256, blk>>>();
    k_gstart<<<1, Gg + 1>>>();

    // ---- GAT layer 0: edge weights + aggregate ----
    k_edgep<<<(Ee + 255) / 256, blk>>>(ssrc0, sdst0, den0);
    k_gather<<<(Nn * 32 + 255) / 256, blk>>>(xp16, b0, ssrc0, sdst0, den0, ah, al);

    // ---- GAT layer 1 (2-term) + fused attention dots ----
    k_mm_f16<2><<<dim3(2, MT), blk, SMEM>>>(ah, al, bt1h, (const __half*)bt1h, xp16,
                                            a_src1, a_dst1, ssrc1, sdst1, Nn, Hd, Hd);
    k_edgep<<<(Ee + 255) / 256, blk>>>(ssrc1, sdst1, den1);
    k_gather<<<(Nn * 32 + 255) / 256, blk>>>(xp16, b1, ssrc1, sdst1, den1, ah, al);

    // ---- fused GRU GEMM + gates -> h (xp fp32) ----
    k_mm_gru<<<dim3(2, MT), blk, SMEMG>>>(ah, al, bihh, b_ih, b_hh, xp, Nn);

    // ---- pooling + super node ----
    k_pool_g<<<dim3(Gg, 2), 128>>>(xp, out);
    k_super<<<1, Hd>>>(Wf, bf, out);
}

// round 12
// speedup vs baseline: 1.9052x; 1.0054x over previous
#include <cuda_runtime.h>
#include <cuda_fp16.h>
#include <math.h>
#include <stdint.h>

#define Nn   50000
#define Ee   800000
#define INC  128
#define Hd   256
#define Gg   128
#define NEG  0.2f

// ---------------- scratch (device globals; no allocations allowed) ----------
__device__ float  g_xp[(size_t)Nn * Hd];          // GRU output (fp32, for pool)
__device__ __half g_xp16[(size_t)Nn * Hd];        // GAT projected features (fp16)
__device__ float g_ssrc0[Nn], g_sdst0[Nn], g_den0[Nn];
__device__ float g_ssrc1[Nn], g_sdst1[Nn], g_den1[Nn];
__device__ float g_p[Ee];                          // edge exp-weights (CSR order)
__device__ int   g_src[Ee];
__device__ int   g_dst[Ee];
__device__ int   g_batch[Nn];
__device__ int   g_cnt[Nn];
__device__ int   g_cur[Nn];
__device__ int   g_offs[Nn + 1];
__device__ int   g_adj[Ee];                        // CSR: src ids grouped by dst
__device__ int   g_adjd[Ee];                       // CSR: dst id per slot
__device__ int   g_gstart[Gg + 1];
__device__ int   g_is64;
// fp16-split A (reused across the three GEMMs)
__device__ __half g_ah[(size_t)Nn * Hd], g_al[(size_t)Nn * Hd];
// fp16 weights, stored [N][K] (B^T layout, K contiguous -> mma row.col)
__device__ __half g_bt0h[256 * 128];
__device__ __half g_bt1h[256 * 256];
__device__ __half g_bihh[768 * 256];

// ---------------------------- PTX helpers -----------------------------------
__device__ __forceinline__ uint32_t smem_u32(const void* p) {
    uint32_t a;
    asm("{ .reg .u64 t; cvta.to.shared.u64 t, %1; cvt.u32.u64 %0, t; }" : "=r"(a) : "l"(p));
    return a;
}
__device__ __forceinline__ void ldsm4(uint32_t& r0, uint32_t& r1, uint32_t& r2, uint32_t& r3,
                                      uint32_t addr) {
    asm volatile("ldmatrix.sync.aligned.m8n8.x4.shared.b16 {%0,%1,%2,%3}, [%4];"
                 : "=r"(r0), "=r"(r1), "=r"(r2), "=r"(r3) : "r"(addr));
}
__device__ __forceinline__ void mma16816(float* d, const uint32_t* a, const uint32_t* b) {
    asm volatile("mma.sync.aligned.m16n8k16.row.col.f32.f16.f16.f32 "
                 "{%0,%1,%2,%3}, {%4,%5,%6,%7}, {%8,%9}, {%0,%1,%2,%3};"
                 : "+f"(d[0]), "+f"(d[1]), "+f"(d[2]), "+f"(d[3])
                 : "r"(a[0]), "r"(a[1]), "r"(a[2]), "r"(a[3]), "r"(b[0]), "r"(b[1]));
}
__device__ __forceinline__ void cpa16(uint32_t dst, const void* src, uint32_t sz) {
    asm volatile("cp.async.cg.shared.global [%0], [%1], 16, %2;"
                 :: "r"(dst), "l"(src), "r"(sz) : "memory");
}
__device__ __forceinline__ void cpa_commit() {
    asm volatile("cp.async.commit_group;" ::: "memory");
}
template<int N> __device__ __forceinline__ void cpa_wait() {
    asm volatile("cp.async.wait_group %0;" :: "n"(N) : "memory");
}

// ---------------- fp16 hi/lo split helpers -----------------------------------
__device__ __forceinline__ void f16split(float w, __half& h, __half& l) {
    h = __float2half_rn(w);
    l = __float2half_rn(w - __half2float(h));
}

// ---------------- index dtype detection + decode ----------------------------
__global__ void k_detect(const int* __restrict__ ei32)
{
    int is64 = 1;
    for (int i = 0; i < 64; i++)
        if (ei32[2 * i + 1] != 0) { is64 = 0; break; }
    g_is64 = is64;
}
__global__ void k_decode_batch(const int* __restrict__ b32)
{
    int n = blockIdx.x * blockDim.x + threadIdx.x;
    if (n >= Nn) return;
    g_batch[n] = g_is64 ? b32[2 * n] : b32[n];
    g_cnt[n] = 0;  g_cur[n] = 0;
    g_ssrc0[n] = 0.f; g_sdst0[n] = 0.f; g_den0[n] = 0.f;
    g_ssrc1[n] = 0.f; g_sdst1[n] = 0.f; g_den1[n] = 0.f;
}
__global__ void k_decode_count(const int* __restrict__ ei32)
{
    int e = blockIdx.x * blockDim.x + threadIdx.x;
    if (e >= Ee) return;
    int s, d;
    if (g_is64) { s = ei32[2 * e]; d = ei32[2 * (Ee + e)]; }
    else        { s = ei32[e];     d = ei32[Ee + e]; }
    g_src[e] = s;
    g_dst[e] = d;
    atomicAdd(&g_cnt[d], 1);
}

// ---------------- weight prep: transpose + fp16 (hi-only, 2-term) -----------
__global__ void k_prep_w(const float* __restrict__ W0, const float* __restrict__ W1,
                         const float* __restrict__ Wih)
{
    int t = blockIdx.x * blockDim.x + threadIdx.x;
    if (t < 256 * 128) {                       // Bt0[n][k] = W0[k][n]
        int n = t >> 7, k = t & 127;
        g_bt0h[t] = __float2half_rn(W0[k * 256 + n]);
    }
    if (t < 256 * 256) {                       // Bt1[n][k] = W1[k][n]
        int n = t >> 8, k = t & 255;
        g_bt1h[t] = __float2half_rn(W1[k * 256 + n]);
    }
    if (t < 768 * 256) {                       // Bih[n][k] = W_ih[n][k]
        g_bihh[t] = __float2half_rn(Wih[t]);
    }
}

// ---------------- A split for x: fp32 -> fp16 hi/lo --------------------------
__global__ __launch_bounds__(256) void k_split_x(const float* __restrict__ src, int n4)
{
    int t = blockIdx.x * blockDim.x + threadIdx.x;
    if (t >= n4) return;
    float4 v = ((const float4*)src)[t];
    float f[4] = {v.x, v.y, v.z, v.w};
    ushort4 hs, ls;
    __half hb, lb;
    f16split(f[0], hb, lb); hs.x = __half_as_ushort(hb); ls.x = __half_as_ushort(lb);
    f16split(f[1], hb, lb); hs.y = __half_as_ushort(hb); ls.y = __half_as_ushort(lb);
    f16split(f[2], hb, lb); hs.z = __half_as_ushort(hb); ls.z = __half_as_ushort(lb);
    f16split(f[3], hb, lb); hs.w = __half_as_ushort(hb); ls.w = __half_as_ushort(lb);
    ((ushort4*)g_ah)[t] = hs;
    ((ushort4*)g_al)[t] = ls;
}

// -------- pipelined 2-term fp16 GEMM + attention-dot epilogue ----------------
// C16 = (Ah+Al) @ Bt^T; epilogue dots fragments with avs/avd -> ssrc/sdst.
#define SSTRIDE 40                       // fp16 per SMEM row (80 B)
#define ABYTES  (128 * SSTRIDE * 2)      // 10240 B per array
#define BUF2    (3 * ABYTES)             // 30720 B per stage (Ah, Al, Bh)
__global__ __launch_bounds__(256, 2) void k_mm_f16(const __half* __restrict__ AH,
                                                   const __half* __restrict__ AL,
                                                   const __half* __restrict__ BtH,
                                                   __half* __restrict__ C16,
                                                   const float* __restrict__ avs,
                                                   const float* __restrict__ avd,
                                                   float* __restrict__ ssrc,
                                                   float* __restrict__ sdst,
                                                   int M, int Nc, int K)
{
    extern __shared__ char smem[];
    const uint32_t sb = smem_u32(smem);

    const int tid  = threadIdx.x;
    const int wid  = tid >> 5, lane = tid & 31;
    const int wm   = wid & 1, wn = wid >> 1;
    const int row0 = blockIdx.y * 128, col0 = blockIdx.x * 128;

    uint32_t aoff[4];
    #pragma unroll
    for (int mi = 0; mi < 4; mi++) {
        int r = wm * 64 + mi * 16 + (lane & 7) + ((lane >> 3) & 1) * 8;
        aoff[mi] = (uint32_t)(r * (SSTRIDE * 2) + (lane >> 4) * 16);
    }
    uint32_t boff[2];
    #pragma unroll
    for (int jp = 0; jp < 2; jp++) {
        int n = wn * 32 + jp * 16 + (lane & 7) + ((lane >> 4) & 1) * 8;
        boff[jp] = (uint32_t)(n * (SSTRIDE * 2) + ((lane >> 3) & 1) * 16);
    }

    float acc[4][4][4];
    #pragma unroll
    for (int i = 0; i < 4; i++)
        #pragma unroll
        for (int j = 0; j < 4; j++)
            #pragma unroll
            for (int q = 0; q < 4; q++) acc[i][j][q] = 0.f;

    const int nit = K >> 5;
    auto issue = [&](int kt, int p) {
        #pragma unroll
        for (int c = 0; c < 2; c++) {
            int lin = tid + c * 256;
            int row = lin >> 2, q = lin & 3;
            uint32_t sd = sb + (uint32_t)(p * BUF2 + row * (SSTRIDE * 2) + q * 16);
            int ar = row0 + row;
            uint32_t asz = (ar < M) ? 16u : 0u;
            if (ar >= M) ar = 0;
            size_t aoffg = (size_t)ar * K + kt * 32 + q * 8;
            size_t boffg = (size_t)(col0 + row) * K + kt * 32 + q * 8;
            cpa16(sd,              AH + aoffg, asz);
            cpa16(sd + ABYTES,     AL + aoffg, asz);
            cpa16(sd + 2 * ABYTES, BtH + boffg, 16u);
        }
        cpa_commit();
    };

    issue(0, 0);
    for (int kt = 0; kt < nit; kt++) {
        const int p = kt & 1;
        if (kt + 1 < nit) { issue(kt + 1, p ^ 1); cpa_wait<1>(); }
        else              { cpa_wait<0>(); }
        __syncthreads();

        const uint32_t uAh = sb + p * BUF2;
        const uint32_t uAl = uAh + ABYTES;
        const uint32_t uBh = uAh + 2 * ABYTES;

        #pragma unroll
        for (int ks = 0; ks < 2; ks++) {
            const uint32_t kb = (uint32_t)(ks * 32);
            uint32_t ah[4][4], al[4][4], bf[4][2];
            #pragma unroll
            for (int mi = 0; mi < 4; mi++) {
                ldsm4(ah[mi][0], ah[mi][1], ah[mi][2], ah[mi][3], uAh + aoff[mi] + kb);
                ldsm4(al[mi][0], al[mi][1], al[mi][2], al[mi][3], uAl + aoff[mi] + kb);
            }
            #pragma unroll
            for (int jp = 0; jp < 2; jp++)
                ldsm4(bf[jp * 2][0], bf[jp * 2][1], bf[jp * 2 + 1][0], bf[jp * 2 + 1][1],
                      uBh + boff[jp] + kb);
            #pragma unroll
            for (int mi = 0; mi < 4; mi++)
                #pragma unroll
                for (int nj = 0; nj < 4; nj++) {
                    mma16816(acc[mi][nj], ah[mi], bf[nj]);
                    mma16816(acc[mi][nj], al[mi], bf[nj]);
                }
        }
        __syncthreads();
    }

    // ---- attention-dot vectors for this thread's columns ----
    float as0[4], as1[4], ad0[4], ad1[4];
    #pragma unroll
    for (int nj = 0; nj < 4; nj++) {
        int c = col0 + wn * 32 + (lane & 3) * 2 + nj * 8;
        as0[nj] = avs[c]; as1[nj] = avs[c + 1];
        ad0[nj] = avd[c]; ad1[nj] = avd[c + 1];
    }

    #pragma unroll
    for (int mi = 0; mi < 4; mi++) {
        int r0g = row0 + wm * 64 + mi * 16 + (lane >> 2);
        int cg  = col0 + wn * 32 + (lane & 3) * 2;
        float pss0 = 0.f, psd0 = 0.f, pss1 = 0.f, psd1 = 0.f;
        #pragma unroll
        for (int nj = 0; nj < 4; nj++) {
            int c = cg + nj * 8;
            if (r0g < M)
                *(__half2*)(C16 + (size_t)r0g * Nc + c) =
                    __floats2half2_rn(acc[mi][nj][0], acc[mi][nj][1]);
            if (r0g + 8 < M)
                *(__half2*)(C16 + (size_t)(r0g + 8) * Nc + c) =
                    __floats2half2_rn(acc[mi][nj][2], acc[mi][nj][3]);
            pss0 = fmaf(acc[mi][nj][0], as0[nj], fmaf(acc[mi][nj][1], as1[nj], pss0));
            psd0 = fmaf(acc[mi][nj][0], ad0[nj], fmaf(acc[mi][nj][1], ad1[nj], psd0));
            pss1 = fmaf(acc[mi][nj][2], as0[nj], fmaf(acc[mi][nj][3], as1[nj], pss1));
            psd1 = fmaf(acc[mi][nj][2], ad0[nj], fmaf(acc[mi][nj][3], ad1[nj], psd1));
        }
        pss0 += __shfl_xor_sync(0xffffffffu, pss0, 1);
        pss0 += __shfl_xor_sync(0xffffffffu, pss0, 2);
        psd0 += __shfl_xor_sync(0xffffffffu, psd0, 1);
        psd0 += __shfl_xor_sync(0xffffffffu, psd0, 2);
        pss1 += __shfl_xor_sync(0xffffffffu, pss1, 1);
        pss1 += __shfl_xor_sync(0xffffffffu, pss1, 2);
        psd1 += __shfl_xor_sync(0xffffffffu, psd1, 1);
        psd1 += __shfl_xor_sync(0xffffffffu, psd1, 2);
        if ((lane & 3) == 0) {
            if (r0g < M) {
                atomicAdd(&ssrc[r0g], pss0);
                atomicAdd(&sdst[r0g], psd0);
            }
            if (r0g + 8 < M) {
                atomicAdd(&ssrc[r0g + 8], pss1);
                atomicAdd(&sdst[r0g + 8], psd1);
            }
        }
    }
}

// -------- fused GRU GEMM: flattened 24-chunk pipeline over 3 gates -----------
#define STSTR  129                       // stash stride (floats)
__global__ __launch_bounds__(256, 1) void k_mm_gru(const __half* __restrict__ AH,
                                                   const __half* __restrict__ AL,
                                                   const __half* __restrict__ BtH,
                                                   const float* __restrict__ b_ih,
                                                   const float* __restrict__ b_hh,
                                                   float* __restrict__ OUT,
                                                   int M)
{
    extern __shared__ char smem[];
    const uint32_t sb = smem_u32(smem);
    float* stash_r = (float*)(smem + 2 * BUF2);
    float* stash_z = stash_r + 128 * STSTR;

    const int tid  = threadIdx.x;
    const int wid  = tid >> 5, lane = tid & 31;
    const int wm   = wid & 1, wn = wid >> 1;
    const int row0 = blockIdx.y * 128, col0 = blockIdx.x * 128;
    const int K = Hd;
    const int NCH = 3 * (K >> 5);          // 24 chunks total

    uint32_t aoff[4];
    #pragma unroll
    for (int mi = 0; mi < 4; mi++) {
        int r = wm * 64 + mi * 16 + (lane & 7) + ((lane >> 3) & 1) * 8;
        aoff[mi] = (uint32_t)(r * (SSTRIDE * 2) + (lane >> 4) * 16);
    }
    uint32_t boff[2];
    #pragma unroll
    for (int jp = 0; jp < 2; jp++) {
        int n = wn * 32 + jp * 16 + (lane & 7) + ((lane >> 4) & 1) * 8;
        boff[jp] = (uint32_t)(n * (SSTRIDE * 2) + ((lane >> 3) & 1) * 16);
    }

    auto issue = [&](int tt, int p) {
        const int gate = tt >> 3, kt = tt & 7;
        const int brow0 = gate * 256 + col0;
        #pragma unroll
        for (int c = 0; c < 2; c++) {
            int lin = tid + c * 256;
            int row = lin >> 2, q = lin & 3;
            uint32_t sd = sb + (uint32_t)(p * BUF2 + row * (SSTRIDE * 2) + q * 16);
            int ar = row0 + row;
            uint32_t asz = (ar < M) ? 16u : 0u;
            if (ar >= M) ar = 0;
            size_t aoffg = (size_t)ar * K + kt * 32 + q * 8;
            size_t boffg = (size_t)(brow0 + row) * K + kt * 32 + q * 8;
            cpa16(sd,              AH + aoffg, asz);
            cpa16(sd + ABYTES,     AL + aoffg, asz);
            cpa16(sd + 2 * ABYTES, BtH + boffg, 16u);
        }
        cpa_commit();
    };

    float acc[4][4][4];
    #pragma unroll
    for (int i = 0; i < 4; i++)
        #pragma unroll
        for (int j = 0; j < 4; j++)
            #pragma unroll
            for (int q = 0; q < 4; q++) acc[i][j][q] = 0.f;

    issue(0, 0);
    for (int tt = 0; tt < NCH; tt++) {
        const int p = tt & 1;
        if (tt + 1 < NCH) { issue(tt + 1, p ^ 1); cpa_wait<1>(); }
        else              { cpa_wait<0>(); }
        __syncthreads();

        const uint32_t uAh = sb + p * BUF2;
        const uint32_t uAl = uAh + ABYTES;
        const uint32_t uBh = uAh + 2 * ABYTES;

        #pragma unroll
        for (int ks = 0; ks < 2; ks++) {
            const uint32_t kb = (uint32_t)(ks * 32);
            uint32_t ah[4][4], al[4][4], bf[4][2];
            #pragma unroll
            for (int mi = 0; mi < 4; mi++) {
                ldsm4(ah[mi][0], ah[mi][1], ah[mi][2], ah[mi][3], uAh + aoff[mi] + kb);
                ldsm4(al[mi][0], al[mi][1], al[mi][2], al[mi][3], uAl + aoff[mi] + kb);
            }
            #pragma unroll
            for (int jp = 0; jp < 2; jp++)
                ldsm4(bf[jp * 2][0], bf[jp * 2][1], bf[jp * 2 + 1][0], bf[jp * 2 + 1][1],
                      uBh + boff[jp] + kb);
            #pragma unroll
            for (int mi = 0; mi < 4; mi++)
                #pragma unroll
                for (int nj = 0; nj < 4; nj++) {
                    mma16816(acc[mi][nj], ah[mi], bf[nj]);
                    mma16816(acc[mi][nj], al[mi], bf[nj]);
                }
        }
        __syncthreads();

        if ((tt & 7) == 7) {
            const int gate = tt >> 3;
            if (gate < 2) {
                float* st = (gate == 0) ? stash_r : stash_z;
                const int go = gate * 256 + col0;
                #pragma unroll
                for (int mi = 0; mi < 4; mi++) {
                    int rl = wm * 64 + mi * 16 + (lane >> 2);
                    #pragma unroll
                    for (int nj = 0; nj < 4; nj++) {
                        int cl = wn * 32 + (lane & 3) * 2 + nj * 8;
                        float bs0 = b_ih[go + cl]     + b_hh[go + cl];
                        float bs1 = b_ih[go + cl + 1] + b_hh[go + cl + 1];
                        st[rl * STSTR + cl]           = 1.f / (1.f + expf(-(acc[mi][nj][0] + bs0)));
                        st[rl * STSTR + cl + 1]       = 1.f / (1.f + expf(-(acc[mi][nj][1] + bs1)));
                        st[(rl + 8) * STSTR + cl]     = 1.f / (1.f + expf(-(acc[mi][nj][2] + bs0)));
                        st[(rl + 8) * STSTR + cl + 1] = 1.f / (1.f + expf(-(acc[mi][nj][3] + bs1)));
                    }
                }
            } else {
                const int go = 512 + col0;
                #pragma unroll
                for (int mi = 0; mi < 4; mi++) {
                    int rl = wm * 64 + mi * 16 + (lane >> 2);
                    int gr0 = row0 + rl, gr1 = gr0 + 8;
                    #pragma unroll
                    for (int nj = 0; nj < 4; nj++) {
                        int cl = wn * 32 + (lane & 3) * 2 + nj * 8;
                        float bi0 = b_ih[go + cl],     bh0 = b_hh[go + cl];
                        float bi1 = b_ih[go + cl + 1], bh1 = b_hh[go + cl + 1];
                        {
                            float r0 = stash_r[rl * STSTR + cl],     z0 = stash_z[rl * STSTR + cl];
                            float r1 = stash_r[rl * STSTR + cl + 1], z1 = stash_z[rl * STSTR + cl + 1];
                            float h0 = (1.f - z0) * tanhf(acc[mi][nj][0] + bi0 + r0 * bh0);
                            float h1 = (1.f - z1) * tanhf(acc[mi][nj][1] + bi1 + r1 * bh1);
                            if (gr0 < M)
                                *(float2*)(OUT + (size_t)gr0 * Hd + col0 + cl) = make_float2(h0, h1);
                        }
                        {
                            float r0 = stash_r[(rl + 8) * STSTR + cl],     z0 = stash_z[(rl + 8) * STSTR + cl];
                            float r1 = stash_r[(rl + 8) * STSTR + cl + 1], z1 = stash_z[(rl + 8) * STSTR + cl + 1];
                            float h0 = (1.f - z0) * tanhf(acc[mi][nj][2] + bi0 + r0 * bh0);
                            float h1 = (1.f - z1) * tanhf(acc[mi][nj][3] + bi1 + r1 * bh1);
                            if (gr1 < M)
                                *(float2*)(OUT + (size_t)gr1 * Hd + col0 + cl) = make_float2(h0, h1);
                        }
                    }
                }
            }
            // reset accumulators for next gate
            #pragma unroll
            for (int i = 0; i < 4; i++)
                #pragma unroll
                for (int j = 0; j < 4; j++)
                    #pragma unroll
                    for (int q = 0; q < 4; q++) acc[i][j][q] = 0.f;
        }
    }
}

// ------------------------------ CSR build -----------------------------------
__global__ __launch_bounds__(1024) void k_scan(void)
{
    __shared__ int ssum[1024];
    const int CH = (Nn + 1023) / 1024;
    int tid = threadIdx.x;
    int base = tid * CH;
    int s = 0;
    for (int j = 0; j < CH; j++) {
        int idx = base + j;
        if (idx < Nn) s += g_cnt[idx];
    }
    ssum[tid] = s;
    __syncthreads();
    for (int off = 1; off < 1024; off <<= 1) {
        int v = (tid >= off) ? ssum[tid - off] : 0;
        __syncthreads();
        ssum[tid] += v;
        __syncthreads();
    }
    int run = (tid > 0) ? ssum[tid - 1] : 0;
    for (int j = 0; j < CH; j++) {
        int idx = base + j;
        if (idx < Nn) { g_offs[idx] = run; run += g_cnt[idx]; }
    }
    if (tid == 1023) g_offs[Nn] = ssum[1023];
}
__global__ void k_fill(void)
{
    int e = blockIdx.x * blockDim.x + threadIdx.x;
    if (e >= Ee) return;
    int d = g_dst[e];
    int pos = atomicAdd(&g_cur[d], 1);
    int slot = g_offs[d] + pos;
    g_adj[slot]  = g_src[e];
    g_adjd[slot] = d;
}

// ---- edge weights: p[i] = exp(lrelu(ssrc[src]+sdst[dst])); den[dst] += p ----
__global__ __launch_bounds__(256) void k_edgep(const float* __restrict__ ssrc,
                                               const float* __restrict__ sdst,
                                               float* __restrict__ den)
{
    int i = blockIdx.x * blockDim.x + threadIdx.x;
    if (i >= Ee) return;
    int s = g_adj[i], d = g_adjd[i];
    float v = ssrc[s] + sdst[d];
    v = v > 0.f ? v : NEG * v;
    float pp = expf(v);
    g_p[i] = pp;
    atomicAdd(&den[d], pp);
}

// -------- graph boundaries (batch is sorted): gstart[g] = lower_bound(g) ----
__global__ void k_gstart(void)
{
    int g = threadIdx.x;
    if (g > Gg) return;
    if (g == Gg) { g_gstart[g] = Nn; return; }
    int lo = 0, hi = Nn;
    while (lo < hi) {
        int mid = (lo + hi) >> 1;
        if (g_batch[mid] < g) lo = mid + 1; else hi = mid;
    }
    g_gstart[g] = lo;
}

// ---- GAT gather: one warp per dst; p precomputed; emits relu + hi/lo split --
__global__ __launch_bounds__(256) void k_gather(const __half* __restrict__ xp16,
                                                const float* __restrict__ bias,
                                                const float* __restrict__ ssrc,
                                                const float* __restrict__ sdst,
                                                const float* __restrict__ den,
                                                __half* __restrict__ oh,
                                                __half* __restrict__ ol)
{
    int w = (blockIdx.x * blockDim.x + threadIdx.x) >> 5;
    int lane = threadIdx.x & 31;
    if (w >= Nn) return;
    int beg = g_offs[w], end = g_offs[w + 1];

    float vs = ssrc[w] + sdst[w];
    vs = vs > 0.f ? vs : NEG * vs;
    float ps = expf(vs);
    float inv = 1.f / (den[w] + ps);

    float acc[8];
    {
        uint4 rv = ((const uint4*)(xp16 + (size_t)w * Hd))[lane];
        float2 f0 = __half22float2(*(__half2*)&rv.x);
        float2 f1 = __half22float2(*(__half2*)&rv.y);
        float2 f2 = __half22float2(*(__half2*)&rv.z);
        float2 f3 = __half22float2(*(__half2*)&rv.w);
        acc[0] = ps * f0.x; acc[1] = ps * f0.y;
        acc[2] = ps * f1.x; acc[3] = ps * f1.y;
        acc[4] = ps * f2.x; acc[5] = ps * f2.y;
        acc[6] = ps * f3.x; acc[7] = ps * f3.y;
    }

    int i = beg;
    for (; i + 4 <= end; i += 4) {
        int s0 = g_adj[i], s1 = g_adj[i + 1], s2 = g_adj[i + 2], s3 = g_adj[i + 3];
        float c0 = g_p[i], c1 = g_p[i + 1], c2 = g_p[i + 2], c3 = g_p[i + 3];
        uint4 r0 = ((const uint4*)(xp16 + (size_t)s0 * Hd))[lane];
        uint4 r1 = ((const uint4*)(xp16 + (size_t)s1 * Hd))[lane];
        uint4 r2 = ((const uint4*)(xp16 + (size_t)s2 * Hd))[lane];
        uint4 r3 = ((const uint4*)(xp16 + (size_t)s3 * Hd))[lane];
        #pragma unroll
        for (int q = 0; q < 4; q++) {
            uint32_t* rw;
            float cc;
            if (q == 0) { rw = (uint32_t*)&r0; cc = c0; }
            else if (q == 1) { rw = (uint32_t*)&r1; cc = c1; }
            else if (q == 2) { rw = (uint32_t*)&r2; cc = c2; }
            else { rw = (uint32_t*)&r3; cc = c3; }
            #pragma unroll
            for (int h = 0; h < 4; h++) {
                float2 f = __half22float2(*(__half2*)&rw[h]);
                acc[h * 2]     = fmaf(cc, f.x, acc[h * 2]);
                acc[h * 2 + 1] = fmaf(cc, f.y, acc[h * 2 + 1]);
            }
        }
    }
    for (; i < end; i++) {
        int s = g_adj[i];
        float cc = g_p[i];
        uint4 rv = ((const uint4*)(xp16 + (size_t)s * Hd))[lane];
        uint32_t* rw = (uint32_t*)&rv;
        #pragma unroll
        for (int h = 0; h < 4; h++) {
            float2 f = __half22float2(*(__half2*)&rw[h]);
            acc[h * 2]     = fmaf(cc, f.x, acc[h * 2]);
            acc[h * 2 + 1] = fmaf(cc, f.y, acc[h * 2 + 1]);
        }
    }

    float4 b0 = ((const float4*)bias)[lane * 2];
    float4 b1 = ((const float4*)bias)[lane * 2 + 1];
    float bb[8] = {b0.x, b0.y, b0.z, b0.w, b1.x, b1.y, b1.z, b1.w};
    uint4 hs, ls;
    uint32_t* hw = (uint32_t*)&hs;
    uint32_t* lw = (uint32_t*)&ls;
    #pragma unroll
    for (int q = 0; q < 4; q++) {
        float v0 = fmaxf(fmaf(acc[q * 2], inv, bb[q * 2]), 0.f);
        float v1 = fmaxf(fmaf(acc[q * 2 + 1], inv, bb[q * 2 + 1]), 0.f);
        __half h0, l0, h1, l1;
        f16split(v0, h0, l0);
        f16split(v1, h1, l1);
        hw[q] = (uint32_t)__half_as_ushort(h0) | ((uint32_t)__half_as_ushort(h1) << 16);
        lw[q] = (uint32_t)__half_as_ushort(l0) | ((uint32_t)__half_as_ushort(l1) << 16);
    }
    *(uint4*)(oh + (size_t)w * Hd + 8 * lane) = hs;
    *(uint4*)(ol + (size_t)w * Hd + 8 * lane) = ls;
}

// --------------- pooling: contiguous per-graph sum (batch sorted) -----------
__global__ __launch_bounds__(128) void k_pool_g(const float* __restrict__ hg,
                                                float* __restrict__ out)
{
    int g = blockIdx.x;
    int c = blockIdx.y * 128 + threadIdx.x;
    int beg = g_gstart[g], end = g_gstart[g + 1];
    float s = 0.f;
    for (int n = beg; n < end; n++) s += hg[(size_t)n * Hd + c];
    out[(size_t)g * (2 * Hd) + c] = s;
}

__global__ __launch_bounds__(256) void k_super(const float* __restrict__ Wf,
                                               const float* __restrict__ bf,
                                               float* __restrict__ out)
{
    __shared__ float s[Hd];
    int j = threadIdx.x;
    float sum = 0.f;
    for (int g = 0; g < Gg; g++) sum += out[(size_t)g * (2 * Hd) + j];
    s[j] = sum / (float)Gg;
    __syncthreads();
    float v = bf[j];
    #pragma unroll 8
    for (int c = 0; c < Hd; c++) v = fmaf(s[c], Wf[(size_t)j * Hd + c], v);
    v = fmaxf(v, 0.f);
    for (int g = 0; g < Gg; g++) out[(size_t)g * (2 * Hd) + Hd + j] = v;
}

// ------------------------------ launch --------------------------------------
extern "C" void kernel_launch(void* const* d_in, const int* in_sizes, int n_in,
                              void* d_out, int out_size)
{
    const float* x      = (const float*)d_in[0];
    const int*   ei32   = (const int*)d_in[1];
    const int*   b32    = (const int*)d_in[2];
    const float* W0     = (const float*)d_in[3];
    const float* a_src0 = (const float*)d_in[4];
    const float* a_dst0 = (const float*)d_in[5];
    const float* b0     = (const float*)d_in[6];
    const float* W1     = (const float*)d_in[7];
    const float* a_src1 = (const float*)d_in[8];
    const float* a_dst1 = (const float*)d_in[9];
    const float* b1     = (const float*)d_in[10];
    const float* W_ih   = (const float*)d_in[11];
    /* d_in[12] = W_hh: unused (h0 = 0) */
    const float* b_ih   = (const float*)d_in[13];
    const float* b_hh   = (const float*)d_in[14];
    const float* Wf     = (const float*)d_in[15];
    const float* bf     = (const float*)d_in[16];
    float*       out    = (float*)d_out;

    float *xp, *ssrc0, *sdst0, *den0, *ssrc1, *sdst1, *den1;
    __half *xp16, *ah, *al, *bt0h, *bt1h, *bihh;
    cudaGetSymbolAddress((void**)&xp,    g_xp);
    cudaGetSymbolAddress((void**)&xp16,  g_xp16);
    cudaGetSymbolAddress((void**)&ssrc0, g_ssrc0);
    cudaGetSymbolAddress((void**)&sdst0, g_sdst0);
    cudaGetSymbolAddress((void**)&den0,  g_den0);
    cudaGetSymbolAddress((void**)&ssrc1, g_ssrc1);
    cudaGetSymbolAddress((void**)&sdst1, g_sdst1);
    cudaGetSymbolAddress((void**)&den1,  g_den1);
    cudaGetSymbolAddress((void**)&ah,    g_ah);
    cudaGetSymbolAddress((void**)&al,    g_al);
    cudaGetSymbolAddress((void**)&bt0h,  g_bt0h);
    cudaGetSymbolAddress((void**)&bt1h,  g_bt1h);
    cudaGetSymbolAddress((void**)&bihh,  g_bihh);

    const int SMEM  = 2 * BUF2;                          // 61440
    const int SMEMG = 2 * BUF2 + 2 * 128 * STSTR * 4;    // 193536
    cudaFuncSetAttribute(k_mm_f16, cudaFuncAttributeMaxDynamicSharedMemorySize, SMEM);
    cudaFuncSetAttribute(k_mm_gru, cudaFuncAttributeMaxDynamicSharedMemorySize, SMEMG);

    const int MT = (Nn + 127) / 128;   // 391
    dim3 blk(256);

    k_detect<<<1, 1>>>(ei32);
    k_decode_batch<<<(Nn + 255) / 256, blk>>>(b32);
    k_decode_count<<<(Ee + 255) / 256, blk>>>(ei32);
    k_prep_w<<<(768 * 256 + 255) / 256, blk>>>(W0, W1, W_ih);
    k_split_x<<<(Nn * INC / 4 + 255) / 256, blk>>>(x, Nn * INC / 4);

    // ---- GAT layer 0 GEMM (2-term) + fused attention dots ----
    k_mm_f16<<<dim3(2, MT), blk, SMEM>>>(ah, al, bt0h, xp16,
                                         a_src0, a_dst0, ssrc0, sdst0, Nn, Hd, INC);

    // ---- CSR + graph boundaries ----
    k_scan<<<1, 1024>>>();
    k_fill<<<(Ee + 255) / 256, blk>>>();
    k_gstart<<<1, Gg + 1>>>();

    // ---- GAT layer 0: edge weights + aggregate ----
    k_edgep<<<(Ee + 255) / 256, blk>>>(ssrc0, sdst0, den0);
    k_gather<<<(Nn * 32 + 255) / 256, blk>>>(xp16, b0, ssrc0, sdst0, den0, ah, al);

    // ---- GAT layer 1 (2-term) + fused attention dots ----
    k_mm_f16<<<dim3(2, MT), blk, SMEM>>>(ah, al, bt1h, xp16,
                                         a_src1, a_dst1, ssrc1, sdst1, Nn, Hd, Hd);
    k_edgep<<<(Ee + 255) / 256, blk>>>(ssrc1, sdst1, den1);
    k_gather<<<(Nn * 32 + 255) / 256, blk>>>(xp16, b1, ssrc1, sdst1, den1, ah, al);

    // ---- fused GRU GEMM + gates -> h (xp fp32) ----
    k_mm_gru<<<dim3(2, MT), blk, SMEMG>>>(ah, al, bihh, b_ih, b_hh, xp, Nn);

    // ---- pooling + super node ----
    k_pool_g<<<dim3(Gg, 2), 128>>>(xp, out);
    k_super<<<1, Hd>>>(Wf, bf, out);
}

// round 13
// speedup vs baseline: 2.6428x; 1.3871x over previous
#include <cuda_runtime.h>
#include <cuda_fp16.h>
#include <math.h>
#include <stdint.h>

#define Nn   50000
#define Ee   800000
#define INC  128
#define Hd   256
#define Gg   128
#define NEG  0.2f

// ---------------- scratch (device globals; no allocations allowed) ----------
__device__ float  g_xp[(size_t)Nn * Hd];          // GRU output (fp32, for pool)
__device__ __half g_xp16[(size_t)Nn * Hd];        // GAT projected features (fp16)
__device__ float g_ssrc0[Nn], g_sdst0[Nn], g_den0[Nn];
__device__ float g_ssrc1[Nn], g_sdst1[Nn], g_den1[Nn];
__device__ float g_p[Ee];                          // edge exp-weights (CSR order)
__device__ int   g_src[Ee];
__device__ int   g_dst[Ee];
__device__ int   g_batch[Nn];
__device__ int   g_cnt[Nn];
__device__ int   g_cur[Nn];
__device__ int   g_offs[Nn + 1];
__device__ int   g_adj[Ee];                        // CSR: src ids grouped by dst
__device__ int   g_adjd[Ee];                       // CSR: dst id per slot
__device__ int   g_gstart[Gg + 1];
__device__ int   g_is64;
// fp16 A (reused across the three GEMMs)
__device__ __half g_ah[(size_t)Nn * Hd];
// fp16 weights, stored [N][K] (B^T layout, K contiguous -> mma row.col)
__device__ __half g_bt0h[256 * 128];
__device__ __half g_bt1h[256 * 256];
__device__ __half g_bihh[768 * 256];

// ---------------------------- PTX helpers -----------------------------------
__device__ __forceinline__ uint32_t smem_u32(const void* p) {
    uint32_t a;
    asm("{ .reg .u64 t; cvta.to.shared.u64 t, %1; cvt.u32.u64 %0, t; }" : "=r"(a) : "l"(p));
    return a;
}
__device__ __forceinline__ void ldsm4(uint32_t& r0, uint32_t& r1, uint32_t& r2, uint32_t& r3,
                                      uint32_t addr) {
    asm volatile("ldmatrix.sync.aligned.m8n8.x4.shared.b16 {%0,%1,%2,%3}, [%4];"
                 : "=r"(r0), "=r"(r1), "=r"(r2), "=r"(r3) : "r"(addr));
}
__device__ __forceinline__ void mma16816(float* d, const uint32_t* a, const uint32_t* b) {
    asm volatile("mma.sync.aligned.m16n8k16.row.col.f32.f16.f16.f32 "
                 "{%0,%1,%2,%3}, {%4,%5,%6,%7}, {%8,%9}, {%0,%1,%2,%3};"
                 : "+f"(d[0]), "+f"(d[1]), "+f"(d[2]), "+f"(d[3])
                 : "r"(a[0]), "r"(a[1]), "r"(a[2]), "r"(a[3]), "r"(b[0]), "r"(b[1]));
}
__device__ __forceinline__ void cpa16(uint32_t dst, const void* src, uint32_t sz) {
    asm volatile("cp.async.cg.shared.global [%0], [%1], 16, %2;"
                 :: "r"(dst), "l"(src), "r"(sz) : "memory");
}
__device__ __forceinline__ void cpa_commit() {
    asm volatile("cp.async.commit_group;" ::: "memory");
}
template<int N> __device__ __forceinline__ void cpa_wait() {
    asm volatile("cp.async.wait_group %0;" :: "n"(N) : "memory");
}

// ---------------- index dtype detection + decode ----------------------------
__global__ void k_detect(const int* __restrict__ ei32)
{
    int is64 = 1;
    for (int i = 0; i < 64; i++)
        if (ei32[2 * i + 1] != 0) { is64 = 0; break; }
    g_is64 = is64;
}
__global__ void k_decode_batch(const int* __restrict__ b32)
{
    int n = blockIdx.x * blockDim.x + threadIdx.x;
    if (n >= Nn) return;
    g_batch[n] = g_is64 ? b32[2 * n] : b32[n];
    g_cnt[n] = 0;  g_cur[n] = 0;
    g_ssrc0[n] = 0.f; g_sdst0[n] = 0.f; g_den0[n] = 0.f;
    g_ssrc1[n] = 0.f; g_sdst1[n] = 0.f; g_den1[n] = 0.f;
}
__global__ void k_decode_count(const int* __restrict__ ei32)
{
    int e = blockIdx.x * blockDim.x + threadIdx.x;
    if (e >= Ee) return;
    int s, d;
    if (g_is64) { s = ei32[2 * e]; d = ei32[2 * (Ee + e)]; }
    else        { s = ei32[e];     d = ei32[Ee + e]; }
    g_src[e] = s;
    g_dst[e] = d;
    atomicAdd(&g_cnt[d], 1);
}

// ---------------- weight prep: transpose + fp16 ------------------------------
__global__ void k_prep_w(const float* __restrict__ W0, const float* __restrict__ W1,
                         const float* __restrict__ Wih)
{
    int t = blockIdx.x * blockDim.x + threadIdx.x;
    if (t < 256 * 128) {                       // Bt0[n][k] = W0[k][n]
        int n = t >> 7, k = t & 127;
        g_bt0h[t] = __float2half_rn(W0[k * 256 + n]);
    }
    if (t < 256 * 256) {                       // Bt1[n][k] = W1[k][n]
        int n = t >> 8, k = t & 255;
        g_bt1h[t] = __float2half_rn(W1[k * 256 + n]);
    }
    if (t < 768 * 256) {                       // Bih[n][k] = W_ih[n][k]
        g_bihh[t] = __float2half_rn(Wih[t]);
    }
}

// ---------------- A convert for x: fp32 -> fp16 -------------------------------
__global__ __launch_bounds__(256) void k_split_x(const float* __restrict__ src, int n4)
{
    int t = blockIdx.x * blockDim.x + threadIdx.x;
    if (t >= n4) return;
    float4 v = ((const float4*)src)[t];
    ushort4 hs;
    hs.x = __half_as_ushort(__float2half_rn(v.x));
    hs.y = __half_as_ushort(__float2half_rn(v.y));
    hs.z = __half_as_ushort(__float2half_rn(v.z));
    hs.w = __half_as_ushort(__float2half_rn(v.w));
    ((ushort4*)g_ah)[t] = hs;
}

// -------- pipelined 1-term fp16 GEMM + attention-dot epilogue ----------------
// C16 = A @ Bt^T; epilogue dots fragments with avs/avd -> ssrc/sdst.
#define SSTRIDE 40                       // fp16 per SMEM row (80 B)
#define ABYTES  (128 * SSTRIDE * 2)      // 10240 B per array
#define BUF1    (2 * ABYTES)             // 20480 B per stage (A, Bh)
__global__ __launch_bounds__(256, 2) void k_mm_f16(const __half* __restrict__ AH,
                                                   const __half* __restrict__ BtH,
                                                   __half* __restrict__ C16,
                                                   const float* __restrict__ avs,
                                                   const float* __restrict__ avd,
                                                   float* __restrict__ ssrc,
                                                   float* __restrict__ sdst,
                                                   int M, int Nc, int K)
{
    extern __shared__ char smem[];
    const uint32_t sb = smem_u32(smem);

    const int tid  = threadIdx.x;
    const int wid  = tid >> 5, lane = tid & 31;
    const int wm   = wid & 1, wn = wid >> 1;
    const int row0 = blockIdx.y * 128, col0 = blockIdx.x * 128;

    uint32_t aoff[4];
    #pragma unroll
    for (int mi = 0; mi < 4; mi++) {
        int r = wm * 64 + mi * 16 + (lane & 7) + ((lane >> 3) & 1) * 8;
        aoff[mi] = (uint32_t)(r * (SSTRIDE * 2) + (lane >> 4) * 16);
    }
    uint32_t boff[2];
    #pragma unroll
    for (int jp = 0; jp < 2; jp++) {
        int n = wn * 32 + jp * 16 + (lane & 7) + ((lane >> 4) & 1) * 8;
        boff[jp] = (uint32_t)(n * (SSTRIDE * 2) + ((lane >> 3) & 1) * 16);
    }

    float acc[4][4][4];
    #pragma unroll
    for (int i = 0; i < 4; i++)
        #pragma unroll
        for (int j = 0; j < 4; j++)
            #pragma unroll
            for (int q = 0; q < 4; q++) acc[i][j][q] = 0.f;

    const int nit = K >> 5;
    auto issue = [&](int kt, int p) {
        #pragma unroll
        for (int c = 0; c < 2; c++) {
            int lin = tid + c * 256;
            int row = lin >> 2, q = lin & 3;
            uint32_t sd = sb + (uint32_t)(p * BUF1 + row * (SSTRIDE * 2) + q * 16);
            int ar = row0 + row;
            uint32_t asz = (ar < M) ? 16u : 0u;
            if (ar >= M) ar = 0;
            size_t aoffg = (size_t)ar * K + kt * 32 + q * 8;
            size_t boffg = (size_t)(col0 + row) * K + kt * 32 + q * 8;
            cpa16(sd,          AH + aoffg, asz);
            cpa16(sd + ABYTES, BtH + boffg, 16u);
        }
        cpa_commit();
    };

    issue(0, 0);
    for (int kt = 0; kt < nit; kt++) {
        const int p = kt & 1;
        if (kt + 1 < nit) { issue(kt + 1, p ^ 1); cpa_wait<1>(); }
        else              { cpa_wait<0>(); }
        __syncthreads();

        const uint32_t uAh = sb + p * BUF1;
        const uint32_t uBh = uAh + ABYTES;

        #pragma unroll
        for (int ks = 0; ks < 2; ks++) {
            const uint32_t kb = (uint32_t)(ks * 32);
            uint32_t ah[4][4], bf[4][2];
            #pragma unroll
            for (int mi = 0; mi < 4; mi++)
                ldsm4(ah[mi][0], ah[mi][1], ah[mi][2], ah[mi][3], uAh + aoff[mi] + kb);
            #pragma unroll
            for (int jp = 0; jp < 2; jp++)
                ldsm4(bf[jp * 2][0], bf[jp * 2][1], bf[jp * 2 + 1][0], bf[jp * 2 + 1][1],
                      uBh + boff[jp] + kb);
            #pragma unroll
            for (int mi = 0; mi < 4; mi++)
                #pragma unroll
                for (int nj = 0; nj < 4; nj++)
                    mma16816(acc[mi][nj], ah[mi], bf[nj]);
        }
        __syncthreads();
    }

    // ---- attention-dot vectors for this thread's columns ----
    float as0[4], as1[4], ad0[4], ad1[4];
    #pragma unroll
    for (int nj = 0; nj < 4; nj++) {
        int c = col0 + wn * 32 + (lane & 3) * 2 + nj * 8;
        as0[nj] = avs[c]; as1[nj] = avs[c + 1];
        ad0[nj] = avd[c]; ad1[nj] = avd[c + 1];
    }

    #pragma unroll
    for (int mi = 0; mi < 4; mi++) {
        int r0g = row0 + wm * 64 + mi * 16 + (lane >> 2);
        int cg  = col0 + wn * 32 + (lane & 3) * 2;
        float pss0 = 0.f, psd0 = 0.f, pss1 = 0.f, psd1 = 0.f;
        #pragma unroll
        for (int nj = 0; nj < 4; nj++) {
            int c = cg + nj * 8;
            if (r0g < M)
                *(__half2*)(C16 + (size_t)r0g * Nc + c) =
                    __floats2half2_rn(acc[mi][nj][0], acc[mi][nj][1]);
            if (r0g + 8 < M)
                *(__half2*)(C16 + (size_t)(r0g + 8) * Nc + c) =
                    __floats2half2_rn(acc[mi][nj][2], acc[mi][nj][3]);
            pss0 = fmaf(acc[mi][nj][0], as0[nj], fmaf(acc[mi][nj][1], as1[nj], pss0));
            psd0 = fmaf(acc[mi][nj][0], ad0[nj], fmaf(acc[mi][nj][1], ad1[nj], psd0));
            pss1 = fmaf(acc[mi][nj][2], as0[nj], fmaf(acc[mi][nj][3], as1[nj], pss1));
            psd1 = fmaf(acc[mi][nj][2], ad0[nj], fmaf(acc[mi][nj][3], ad1[nj], psd1));
        }
        pss0 += __shfl_xor_sync(0xffffffffu, pss0, 1);
        pss0 += __shfl_xor_sync(0xffffffffu, pss0, 2);
        psd0 += __shfl_xor_sync(0xffffffffu, psd0, 1);
        psd0 += __shfl_xor_sync(0xffffffffu, psd0, 2);
        pss1 += __shfl_xor_sync(0xffffffffu, pss1, 1);
        pss1 += __shfl_xor_sync(0xffffffffu, pss1, 2);
        psd1 += __shfl_xor_sync(0xffffffffu, psd1, 1);
        psd1 += __shfl_xor_sync(0xffffffffu, psd1, 2);
        if ((lane & 3) == 0) {
            if (r0g < M) {
                atomicAdd(&ssrc[r0g], pss0);
                atomicAdd(&sdst[r0g], psd0);
            }
            if (r0g + 8 < M) {
                atomicAdd(&ssrc[r0g + 8], pss1);
                atomicAdd(&sdst[r0g + 8], psd1);
            }
        }
    }
}

// -------- fused GRU GEMM: flattened 24-chunk pipeline, fp16 stash, 2 CTA/SM --
#define STSTR  130                       // stash stride (halves; 260 B rows)
__global__ __launch_bounds__(256, 2) void k_mm_gru(const __half* __restrict__ AH,
                                                   const __half* __restrict__ BtH,
                                                   const float* __restrict__ b_ih,
                                                   const float* __restrict__ b_hh,
                                                   float* __restrict__ OUT,
                                                   int M)
{
    extern __shared__ char smem[];
    const uint32_t sb = smem_u32(smem);
    __half* stash_r = (__half*)(smem + 2 * BUF1);
    __half* stash_z = stash_r + 128 * STSTR;

    const int tid  = threadIdx.x;
    const int wid  = tid >> 5, lane = tid & 31;
    const int wm   = wid & 1, wn = wid >> 1;
    const int row0 = blockIdx.y * 128, col0 = blockIdx.x * 128;
    const int K = Hd;
    const int NCH = 3 * (K >> 5);          // 24 chunks total

    uint32_t aoff[4];
    #pragma unroll
    for (int mi = 0; mi < 4; mi++) {
        int r = wm * 64 + mi * 16 + (lane & 7) + ((lane >> 3) & 1) * 8;
        aoff[mi] = (uint32_t)(r * (SSTRIDE * 2) + (lane >> 4) * 16);
    }
    uint32_t boff[2];
    #pragma unroll
    for (int jp = 0; jp < 2; jp++) {
        int n = wn * 32 + jp * 16 + (lane & 7) + ((lane >> 4) & 1) * 8;
        boff[jp] = (uint32_t)(n * (SSTRIDE * 2) + ((lane >> 3) & 1) * 16);
    }

    auto issue = [&](int tt, int p) {
        const int gate = tt >> 3, kt = tt & 7;
        const int brow0 = gate * 256 + col0;
        #pragma unroll
        for (int c = 0; c < 2; c++) {
            int lin = tid + c * 256;
            int row = lin >> 2, q = lin & 3;
            uint32_t sd = sb + (uint32_t)(p * BUF1 + row * (SSTRIDE * 2) + q * 16);
            int ar = row0 + row;
            uint32_t asz = (ar < M) ? 16u : 0u;
            if (ar >= M) ar = 0;
            size_t aoffg = (size_t)ar * K + kt * 32 + q * 8;
            size_t boffg = (size_t)(brow0 + row) * K + kt * 32 + q * 8;
            cpa16(sd,          AH + aoffg, asz);
            cpa16(sd + ABYTES, BtH + boffg, 16u);
        }
        cpa_commit();
    };

    float acc[4][4][4];
    #pragma unroll
    for (int i = 0; i < 4; i++)
        #pragma unroll
        for (int j = 0; j < 4; j++)
            #pragma unroll
            for (int q = 0; q < 4; q++) acc[i][j][q] = 0.f;

    issue(0, 0);
    for (int tt = 0; tt < NCH; tt++) {
        const int p = tt & 1;
        if (tt + 1 < NCH) { issue(tt + 1, p ^ 1); cpa_wait<1>(); }
        else              { cpa_wait<0>(); }
        __syncthreads();

        const uint32_t uAh = sb + p * BUF1;
        const uint32_t uBh = uAh + ABYTES;

        #pragma unroll
        for (int ks = 0; ks < 2; ks++) {
            const uint32_t kb = (uint32_t)(ks * 32);
            uint32_t ah[4][4], bf[4][2];
            #pragma unroll
            for (int mi = 0; mi < 4; mi++)
                ldsm4(ah[mi][0], ah[mi][1], ah[mi][2], ah[mi][3], uAh + aoff[mi] + kb);
            #pragma unroll
            for (int jp = 0; jp < 2; jp++)
                ldsm4(bf[jp * 2][0], bf[jp * 2][1], bf[jp * 2 + 1][0], bf[jp * 2 + 1][1],
                      uBh + boff[jp] + kb);
            #pragma unroll
            for (int mi = 0; mi < 4; mi++)
                #pragma unroll
                for (int nj = 0; nj < 4; nj++)
                    mma16816(acc[mi][nj], ah[mi], bf[nj]);
        }
        __syncthreads();

        if ((tt & 7) == 7) {
            const int gate = tt >> 3;
            if (gate < 2) {
                __half* st = (gate == 0) ? stash_r : stash_z;
                const int go = gate * 256 + col0;
                #pragma unroll
                for (int mi = 0; mi < 4; mi++) {
                    int rl = wm * 64 + mi * 16 + (lane >> 2);
                    #pragma unroll
                    for (int nj = 0; nj < 4; nj++) {
                        int cl = wn * 32 + (lane & 3) * 2 + nj * 8;
                        float bs0 = b_ih[go + cl]     + b_hh[go + cl];
                        float bs1 = b_ih[go + cl + 1] + b_hh[go + cl + 1];
                        float s00 = 1.f / (1.f + expf(-(acc[mi][nj][0] + bs0)));
                        float s01 = 1.f / (1.f + expf(-(acc[mi][nj][1] + bs1)));
                        float s10 = 1.f / (1.f + expf(-(acc[mi][nj][2] + bs0)));
                        float s11 = 1.f / (1.f + expf(-(acc[mi][nj][3] + bs1)));
                        *(__half2*)&st[rl * STSTR + cl]       = __floats2half2_rn(s00, s01);
                        *(__half2*)&st[(rl + 8) * STSTR + cl] = __floats2half2_rn(s10, s11);
                    }
                }
            } else {
                const int go = 512 + col0;
                #pragma unroll
                for (int mi = 0; mi < 4; mi++) {
                    int rl = wm * 64 + mi * 16 + (lane >> 2);
                    int gr0 = row0 + rl, gr1 = gr0 + 8;
                    #pragma unroll
                    for (int nj = 0; nj < 4; nj++) {
                        int cl = wn * 32 + (lane & 3) * 2 + nj * 8;
                        float bi0 = b_ih[go + cl],     bh0 = b_hh[go + cl];
                        float bi1 = b_ih[go + cl + 1], bh1 = b_hh[go + cl + 1];
                        {
                            float2 rr = __half22float2(*(__half2*)&stash_r[rl * STSTR + cl]);
                            float2 zz = __half22float2(*(__half2*)&stash_z[rl * STSTR + cl]);
                            float h0 = (1.f - zz.x) * tanhf(acc[mi][nj][0] + bi0 + rr.x * bh0);
                            float h1 = (1.f - zz.y) * tanhf(acc[mi][nj][1] + bi1 + rr.y * bh1);
                            if (gr0 < M)
                                *(float2*)(OUT + (size_t)gr0 * Hd + col0 + cl) = make_float2(h0, h1);
                        }
                        {
                            float2 rr = __half22float2(*(__half2*)&stash_r[(rl + 8) * STSTR + cl]);
                            float2 zz = __half22float2(*(__half2*)&stash_z[(rl + 8) * STSTR + cl]);
                            float h0 = (1.f - zz.x) * tanhf(acc[mi][nj][2] + bi0 + rr.x * bh0);
                            float h1 = (1.f - zz.y) * tanhf(acc[mi][nj][3] + bi1 + rr.y * bh1);
                            if (gr1 < M)
                                *(float2*)(OUT + (size_t)gr1 * Hd + col0 + cl) = make_float2(h0, h1);
                        }
                    }
                }
            }
            #pragma unroll
            for (int i = 0; i < 4; i++)
                #pragma unroll
                for (int j = 0; j < 4; j++)
                    #pragma unroll
                    for (int q = 0; q < 4; q++) acc[i][j][q] = 0.f;
        }
    }
}

// ------------------------------ CSR build -----------------------------------
__global__ __launch_bounds__(1024) void k_scan(void)
{
    __shared__ int ssum[1024];
    const int CH = (Nn + 1023) / 1024;
    int tid = threadIdx.x;
    int base = tid * CH;
    int s = 0;
    for (int j = 0; j < CH; j++) {
        int idx = base + j;
        if (idx < Nn) s += g_cnt[idx];
    }
    ssum[tid] = s;
    __syncthreads();
    for (int off = 1; off < 1024; off <<= 1) {
        int v = (tid >= off) ? ssum[tid - off] : 0;
        __syncthreads();
        ssum[tid] += v;
        __syncthreads();
    }
    int run = (tid > 0) ? ssum[tid - 1] : 0;
    for (int j = 0; j < CH; j++) {
        int idx = base + j;
        if (idx < Nn) { g_offs[idx] = run; run += g_cnt[idx]; }
    }
    if (tid == 1023) g_offs[Nn] = ssum[1023];
}
__global__ void k_fill(void)
{
    int e = blockIdx.x * blockDim.x + threadIdx.x;
    if (e >= Ee) return;
    int d = g_dst[e];
    int pos = atomicAdd(&g_cur[d], 1);
    int slot = g_offs[d] + pos;
    g_adj[slot]  = g_src[e];
    g_adjd[slot] = d;
}

// ---- edge weights: p[i] = exp(lrelu(ssrc[src]+sdst[dst])); den[dst] += p ----
__global__ __launch_bounds__(256) void k_edgep(const float* __restrict__ ssrc,
                                               const float* __restrict__ sdst,
                                               float* __restrict__ den)
{
    int i = blockIdx.x * blockDim.x + threadIdx.x;
    if (i >= Ee) return;
    int s = g_adj[i], d = g_adjd[i];
    float v = ssrc[s] + sdst[d];
    v = v > 0.f ? v : NEG * v;
    float pp = expf(v);
    g_p[i] = pp;
    atomicAdd(&den[d], pp);
}

// -------- graph boundaries (batch is sorted): gstart[g] = lower_bound(g) ----
__global__ void k_gstart(void)
{
    int g = threadIdx.x;
    if (g > Gg) return;
    if (g == Gg) { g_gstart[g] = Nn; return; }
    int lo = 0, hi = Nn;
    while (lo < hi) {
        int mid = (lo + hi) >> 1;
        if (g_batch[mid] < g) lo = mid + 1; else hi = mid;
    }
    g_gstart[g] = lo;
}

// ---- GAT gather: one warp per dst; p precomputed; emits relu'd fp16 ---------
__global__ __launch_bounds__(256) void k_gather(const __half* __restrict__ xp16,
                                                const float* __restrict__ bias,
                                                const float* __restrict__ ssrc,
                                                const float* __restrict__ sdst,
                                                const float* __restrict__ den,
                                                __half* __restrict__ oh)
{
    int w = (blockIdx.x * blockDim.x + threadIdx.x) >> 5;
    int lane = threadIdx.x & 31;
    if (w >= Nn) return;
    int beg = g_offs[w], end = g_offs[w + 1];

    float vs = ssrc[w] + sdst[w];
    vs = vs > 0.f ? vs : NEG * vs;
    float ps = expf(vs);
    float inv = 1.f / (den[w] + ps);

    float acc[8];
    {
        uint4 rv = ((const uint4*)(xp16 + (size_t)w * Hd))[lane];
        float2 f0 = __half22float2(*(__half2*)&rv.x);
        float2 f1 = __half22float2(*(__half2*)&rv.y);
        float2 f2 = __half22float2(*(__half2*)&rv.z);
        float2 f3 = __half22float2(*(__half2*)&rv.w);
        acc[0] = ps * f0.x; acc[1] = ps * f0.y;
        acc[2] = ps * f1.x; acc[3] = ps * f1.y;
        acc[4] = ps * f2.x; acc[5] = ps * f2.y;
        acc[6] = ps * f3.x; acc[7] = ps * f3.y;
    }

    int i = beg;
    for (; i + 4 <= end; i += 4) {
        int s0 = g_adj[i], s1 = g_adj[i + 1], s2 = g_adj[i + 2], s3 = g_adj[i + 3];
        float c0 = g_p[i], c1 = g_p[i + 1], c2 = g_p[i + 2], c3 = g_p[i + 3];
        uint4 r0 = ((const uint4*)(xp16 + (size_t)s0 * Hd))[lane];
        uint4 r1 = ((const uint4*)(xp16 + (size_t)s1 * Hd))[lane];
        uint4 r2 = ((const uint4*)(xp16 + (size_t)s2 * Hd))[lane];
        uint4 r3 = ((const uint4*)(xp16 + (size_t)s3 * Hd))[lane];
        #pragma unroll
        for (int q = 0; q < 4; q++) {
            uint32_t* rw;
            float cc;
            if (q == 0) { rw = (uint32_t*)&r0; cc = c0; }
            else if (q == 1) { rw = (uint32_t*)&r1; cc = c1; }
            else if (q == 2) { rw = (uint32_t*)&r2; cc = c2; }
            else { rw = (uint32_t*)&r3; cc = c3; }
            #pragma unroll
            for (int h = 0; h < 4; h++) {
                float2 f = __half22float2(*(__half2*)&rw[h]);
                acc[h * 2]     = fmaf(cc, f.x, acc[h * 2]);
                acc[h * 2 + 1] = fmaf(cc, f.y, acc[h * 2 + 1]);
            }
        }
    }
    for (; i < end; i++) {
        int s = g_adj[i];
        float cc = g_p[i];
        uint4 rv = ((const uint4*)(xp16 + (size_t)s * Hd))[lane];
        uint32_t* rw = (uint32_t*)&rv;
        #pragma unroll
        for (int h = 0; h < 4; h++) {
            float2 f = __half22float2(*(__half2*)&rw[h]);
            acc[h * 2]     = fmaf(cc, f.x, acc[h * 2]);
            acc[h * 2 + 1] = fmaf(cc, f.y, acc[h * 2 + 1]);
        }
    }

    float4 b0 = ((const float4*)bias)[lane * 2];
    float4 b1 = ((const float4*)bias)[lane * 2 + 1];
    float bb[8] = {b0.x, b0.y, b0.z, b0.w, b1.x, b1.y, b1.z, b1.w};
    uint4 hs;
    uint32_t* hw = (uint32_t*)&hs;
    #pragma unroll
    for (int q = 0; q < 4; q++) {
        float v0 = fmaxf(fmaf(acc[q * 2], inv, bb[q * 2]), 0.f);
        float v1 = fmaxf(fmaf(acc[q * 2 + 1], inv, bb[q * 2 + 1]), 0.f);
        __half2 hh = __floats2half2_rn(v0, v1);
        hw[q] = *(uint32_t*)&hh;
    }
    *(uint4*)(oh + (size_t)w * Hd + 8 * lane) = hs;
}

// --------------- pooling: contiguous per-graph sum (batch sorted) -----------
__global__ __launch_bounds__(128) void k_pool_g(const float* __restrict__ hg,
                                                float* __restrict__ out)
{
    int g = blockIdx.x;
    int c = blockIdx.y * 128 + threadIdx.x;
    int beg = g_gstart[g], end = g_gstart[g + 1];
    float s = 0.f;
    for (int n = beg; n < end; n++) s += hg[(size_t)n * Hd + c];
    out[(size_t)g * (2 * Hd) + c] = s;
}

__global__ __launch_bounds__(256) void k_super(const float* __restrict__ Wf,
                                               const float* __restrict__ bf,
                                               float* __restrict__ out)
{
    __shared__ float s[Hd];
    int j = threadIdx.x;
    float sum = 0.f;
    for (int g = 0; g < Gg; g++) sum += out[(size_t)g * (2 * Hd) + j];
    s[j] = sum / (float)Gg;
    __syncthreads();
    float v = bf[j];
    #pragma unroll 8
    for (int c = 0; c < Hd; c++) v = fmaf(s[c], Wf[(size_t)j * Hd + c], v);
    v = fmaxf(v, 0.f);
    for (int g = 0; g < Gg; g++) out[(size_t)g * (2 * Hd) + Hd + j] = v;
}

// ------------------------------ launch --------------------------------------
extern "C" void kernel_launch(void* const* d_in, const int* in_sizes, int n_in,
                              void* d_out, int out_size)
{
    const float* x      = (const float*)d_in[0];
    const int*   ei32   = (const int*)d_in[1];
    const int*   b32    = (const int*)d_in[2];
    const float* W0     = (const float*)d_in[3];
    const float* a_src0 = (const float*)d_in[4];
    const float* a_dst0 = (const float*)d_in[5];
    const float* b0     = (const float*)d_in[6];
    const float* W1     = (const float*)d_in[7];
    const float* a_src1 = (const float*)d_in[8];
    const float* a_dst1 = (const float*)d_in[9];
    const float* b1     = (const float*)d_in[10];
    const float* W_ih   = (const float*)d_in[11];
    /* d_in[12] = W_hh: unused (h0 = 0) */
    const float* b_ih   = (const float*)d_in[13];
    const float* b_hh   = (const float*)d_in[14];
    const float* Wf     = (const float*)d_in[15];
    const float* bf     = (const float*)d_in[16];
    float*       out    = (float*)d_out;

    float *xp, *ssrc0, *sdst0, *den0, *ssrc1, *sdst1, *den1;
    __half *xp16, *ah, *bt0h, *bt1h, *bihh;
    cudaGetSymbolAddress((void**)&xp,    g_xp);
    cudaGetSymbolAddress((void**)&xp16,  g_xp16);
    cudaGetSymbolAddress((void**)&ssrc0, g_ssrc0);
    cudaGetSymbolAddress((void**)&sdst0, g_sdst0);
    cudaGetSymbolAddress((void**)&den0,  g_den0);
    cudaGetSymbolAddress((void**)&ssrc1, g_ssrc1);
    cudaGetSymbolAddress((void**)&sdst1, g_sdst1);
    cudaGetSymbolAddress((void**)&den1,  g_den1);
    cudaGetSymbolAddress((void**)&ah,    g_ah);
    cudaGetSymbolAddress((void**)&bt0h,  g_bt0h);
    cudaGetSymbolAddress((void**)&bt1h,  g_bt1h);
    cudaGetSymbolAddress((void**)&bihh,  g_bihh);

    const int SMEM  = 2 * BUF1;                          // 40960
    const int SMEMG = 2 * BUF1 + 2 * 128 * STSTR * 2;    // 40960 + 66560 = 107520
    cudaFuncSetAttribute(k_mm_f16, cudaFuncAttributeMaxDynamicSharedMemorySize, SMEM);
    cudaFuncSetAttribute(k_mm_gru, cudaFuncAttributeMaxDynamicSharedMemorySize, SMEMG);

    const int MT = (Nn + 127) / 128;   // 391
    dim3 blk(256);

    k_detect<<<1, 1>>>(ei32);
    k_decode_batch<<<(Nn + 255) / 256, blk>>>(b32);
    k_decode_count<<<(Ee + 255) / 256, blk>>>(ei32);
    k_prep_w<<<(768 * 256 + 255) / 256, blk>>>(W0, W1, W_ih);
    k_split_x<<<(Nn * INC / 4 + 255) / 256, blk>>>(x, Nn * INC / 4);

    // ---- GAT layer 0 GEMM (fp16) + fused attention dots ----
    k_mm_f16<<<dim3(2, MT), blk, SMEM>>>(ah, bt0h, xp16,
                                         a_src0, a_dst0, ssrc0, sdst0, Nn, Hd, INC);

    // ---- CSR + graph boundaries ----
    k_scan<<<1, 1024>>>();
    k_fill<<<(Ee + 255) / 256, blk>>>();
    k_gstart<<<1, Gg + 1>>>();

    // ---- GAT layer 0: edge weights + aggregate ----
    k_edgep<<<(Ee + 255) / 256, blk>>>(ssrc0, sdst0, den0);
    k_gather<<<(Nn * 32 + 255) / 256, blk>>>(xp16, b0, ssrc0, sdst0, den0, ah);

    // ---- GAT layer 1 (fp16) + fused attention dots ----
    k_mm_f16<<<dim3(2, MT), blk, SMEM>>>(ah, bt1h, xp16,
                                         a_src1, a_dst1, ssrc1, sdst1, Nn, Hd, Hd);
    k_edgep<<<(Ee + 255) / 256, blk>>>(ssrc1, sdst1, den1);
    k_gather<<<(Nn * 32 + 255) / 256, blk>>>(xp16, b1, ssrc1, sdst1, den1, ah);

    // ---- fused GRU GEMM + gates -> h (xp fp32) ----
    k_mm_gru<<<dim3(2, MT), blk, SMEMG>>>(ah, bihh, b_ih, b_hh, xp, Nn);

    // ---- pooling + super node ----
    k_pool_g<<<dim3(Gg, 2), 128>>>(xp, out);
    k_super<<<1, Hd>>>(Wf, bf, out);
}

// round 14
// speedup vs baseline: 2.7917x; 1.0564x over previous
#include <cuda_runtime.h>
#include <cuda_fp16.h>
#include <math.h>
#include <stdint.h>

#define Nn   50000
#define Ee   800000
#define INC  128
#define Hd   256
#define Gg   128
#define NEG  0.2f

// ---------------- scratch (device globals; no allocations allowed) ----------
__device__ float  g_xp[(size_t)Nn * Hd];          // GRU output (fp32, for pool)
__device__ __half g_xp16[(size_t)Nn * Hd];        // GAT projected features (fp16)
__device__ float g_ssrc0[Nn], g_sdst0[Nn], g_den0[Nn];
__device__ float g_ssrc1[Nn], g_sdst1[Nn], g_den1[Nn];
__device__ float g_p[Ee];                          // edge exp-weights (CSR order)
__device__ int   g_src[Ee];
__device__ int   g_dst[Ee];
__device__ int   g_batch[Nn];
__device__ int   g_cnt[Nn];
__device__ int   g_cur[Nn];
__device__ int   g_offs[Nn + 1];
__device__ int   g_adj[Ee];                        // CSR: src ids grouped by dst
__device__ int   g_adjd[Ee];                       // CSR: dst id per slot
__device__ int   g_gstart[Gg + 1];
__device__ int   g_is64;
// fp16 A (reused across the three GEMMs)
__device__ __half g_ah[(size_t)Nn * Hd];
// fp16 weights, stored [N][K] (B^T layout, K contiguous -> mma row.col)
__device__ __half g_bt0h[256 * 128];
__device__ __half g_bt1h[256 * 256];
__device__ __half g_bihh[768 * 256];

// ---------------------------- PTX helpers -----------------------------------
__device__ __forceinline__ uint32_t smem_u32(const void* p) {
    uint32_t a;
    asm("{ .reg .u64 t; cvta.to.shared.u64 t, %1; cvt.u32.u64 %0, t; }" : "=r"(a) : "l"(p));
    return a;
}
__device__ __forceinline__ void ldsm4(uint32_t& r0, uint32_t& r1, uint32_t& r2, uint32_t& r3,
                                      uint32_t addr) {
    asm volatile("ldmatrix.sync.aligned.m8n8.x4.shared.b16 {%0,%1,%2,%3}, [%4];"
                 : "=r"(r0), "=r"(r1), "=r"(r2), "=r"(r3) : "r"(addr));
}
__device__ __forceinline__ void mma16816(float* d, const uint32_t* a, const uint32_t* b) {
    asm volatile("mma.sync.aligned.m16n8k16.row.col.f32.f16.f16.f32 "
                 "{%0,%1,%2,%3}, {%4,%5,%6,%7}, {%8,%9}, {%0,%1,%2,%3};"
                 : "+f"(d[0]), "+f"(d[1]), "+f"(d[2]), "+f"(d[3])
                 : "r"(a[0]), "r"(a[1]), "r"(a[2]), "r"(a[3]), "r"(b[0]), "r"(b[1]));
}
__device__ __forceinline__ void cpa16(uint32_t dst, const void* src, uint32_t sz) {
    asm volatile("cp.async.cg.shared.global [%0], [%1], 16, %2;"
                 :: "r"(dst), "l"(src), "r"(sz) : "memory");
}
__device__ __forceinline__ void cpa_commit() {
    asm volatile("cp.async.commit_group;" ::: "memory");
}
template<int N> __device__ __forceinline__ void cpa_wait() {
    asm volatile("cp.async.wait_group %0;" :: "n"(N) : "memory");
}

// ---------------- index dtype detection + decode ----------------------------
__global__ void k_detect(const int* __restrict__ ei32)
{
    int is64 = 1;
    for (int i = 0; i < 64; i++)
        if (ei32[2 * i + 1] != 0) { is64 = 0; break; }
    g_is64 = is64;
}
__global__ void k_decode_batch(const int* __restrict__ b32)
{
    int n = blockIdx.x * blockDim.x + threadIdx.x;
    if (n >= Nn) return;
    g_batch[n] = g_is64 ? b32[2 * n] : b32[n];
    g_cnt[n] = 0;  g_cur[n] = 0;
}
// zero attention scratch (main stream; must precede GEMM epilogue atomics)
__global__ void k_zero_s(void)
{
    int n = blockIdx.x * blockDim.x + threadIdx.x;
    if (n >= Nn) return;
    g_ssrc0[n] = 0.f; g_sdst0[n] = 0.f; g_den0[n] = 0.f;
    g_ssrc1[n] = 0.f; g_sdst1[n] = 0.f; g_den1[n] = 0.f;
}
__global__ void k_decode_count(const int* __restrict__ ei32)
{
    int e = blockIdx.x * blockDim.x + threadIdx.x;
    if (e >= Ee) return;
    int s, d;
    if (g_is64) { s = ei32[2 * e]; d = ei32[2 * (Ee + e)]; }
    else        { s = ei32[e];     d = ei32[Ee + e]; }
    g_src[e] = s;
    g_dst[e] = d;
    atomicAdd(&g_cnt[d], 1);
}

// ---------------- weight prep: transpose + fp16 ------------------------------
__global__ void k_prep_w(const float* __restrict__ W0, const float* __restrict__ W1,
                         const float* __restrict__ Wih)
{
    int t = blockIdx.x * blockDim.x + threadIdx.x;
    if (t < 256 * 128) {                       // Bt0[n][k] = W0[k][n]
        int n = t >> 7, k = t & 127;
        g_bt0h[t] = __float2half_rn(W0[k * 256 + n]);
    }
    if (t < 256 * 256) {                       // Bt1[n][k] = W1[k][n]
        int n = t >> 8, k = t & 255;
        g_bt1h[t] = __float2half_rn(W1[k * 256 + n]);
    }
    if (t < 768 * 256) {                       // Bih[n][k] = W_ih[n][k]
        g_bihh[t] = __float2half_rn(Wih[t]);
    }
}

// ---------------- A convert for x: fp32 -> fp16 -------------------------------
__global__ __launch_bounds__(256) void k_split_x(const float* __restrict__ src, int n4)
{
    int t = blockIdx.x * blockDim.x + threadIdx.x;
    if (t >= n4) return;
    float4 v = ((const float4*)src)[t];
    ushort4 hs;
    hs.x = __half_as_ushort(__float2half_rn(v.x));
    hs.y = __half_as_ushort(__float2half_rn(v.y));
    hs.z = __half_as_ushort(__float2half_rn(v.z));
    hs.w = __half_as_ushort(__float2half_rn(v.w));
    ((ushort4*)g_ah)[t] = hs;
}

// -------- pipelined 1-term fp16 GEMM + attention-dot epilogue ----------------
#define SSTRIDE 40                       // fp16 per SMEM row (80 B)
#define ABYTES  (128 * SSTRIDE * 2)      // 10240 B per array
#define BUF1    (2 * ABYTES)             // 20480 B per stage (A, Bh)
__global__ __launch_bounds__(256, 2) void k_mm_f16(const __half* __restrict__ AH,
                                                   const __half* __restrict__ BtH,
                                                   __half* __restrict__ C16,
                                                   const float* __restrict__ avs,
                                                   const float* __restrict__ avd,
                                                   float* __restrict__ ssrc,
                                                   float* __restrict__ sdst,
                                                   int M, int Nc, int K)
{
    extern __shared__ char smem[];
    const uint32_t sb = smem_u32(smem);

    const int tid  = threadIdx.x;
    const int wid  = tid >> 5, lane = tid & 31;
    const int wm   = wid & 1, wn = wid >> 1;
    const int row0 = blockIdx.y * 128, col0 = blockIdx.x * 128;

    uint32_t aoff[4];
    #pragma unroll
    for (int mi = 0; mi < 4; mi++) {
        int r = wm * 64 + mi * 16 + (lane & 7) + ((lane >> 3) & 1) * 8;
        aoff[mi] = (uint32_t)(r * (SSTRIDE * 2) + (lane >> 4) * 16);
    }
    uint32_t boff[2];
    #pragma unroll
    for (int jp = 0; jp < 2; jp++) {
        int n = wn * 32 + jp * 16 + (lane & 7) + ((lane >> 4) & 1) * 8;
        boff[jp] = (uint32_t)(n * (SSTRIDE * 2) + ((lane >> 3) & 1) * 16);
    }

    float acc[4][4][4];
    #pragma unroll
    for (int i = 0; i < 4; i++)
        #pragma unroll
        for (int j = 0; j < 4; j++)
            #pragma unroll
            for (int q = 0; q < 4; q++) acc[i][j][q] = 0.f;

    const int nit = K >> 5;
    auto issue = [&](int kt, int p) {
        #pragma unroll
        for (int c = 0; c < 2; c++) {
            int lin = tid + c * 256;
            int row = lin >> 2, q = lin & 3;
            uint32_t sd = sb + (uint32_t)(p * BUF1 + row * (SSTRIDE * 2) + q * 16);
            int ar = row0 + row;
            uint32_t asz = (ar < M) ? 16u : 0u;
            if (ar >= M) ar = 0;
            size_t aoffg = (size_t)ar * K + kt * 32 + q * 8;
            size_t boffg = (size_t)(col0 + row) * K + kt * 32 + q * 8;
            cpa16(sd,          AH + aoffg, asz);
            cpa16(sd + ABYTES, BtH + boffg, 16u);
        }
        cpa_commit();
    };

    issue(0, 0);
    for (int kt = 0; kt < nit; kt++) {
        const int p = kt & 1;
        if (kt + 1 < nit) { issue(kt + 1, p ^ 1); cpa_wait<1>(); }
        else              { cpa_wait<0>(); }
        __syncthreads();

        const uint32_t uAh = sb + p * BUF1;
        const uint32_t uBh = uAh + ABYTES;

        #pragma unroll
        for (int ks = 0; ks < 2; ks++) {
            const uint32_t kb = (uint32_t)(ks * 32);
            uint32_t ah[4][4], bf[4][2];
            #pragma unroll
            for (int mi = 0; mi < 4; mi++)
                ldsm4(ah[mi][0], ah[mi][1], ah[mi][2], ah[mi][3], uAh + aoff[mi] + kb);
            #pragma unroll
            for (int jp = 0; jp < 2; jp++)
                ldsm4(bf[jp * 2][0], bf[jp * 2][1], bf[jp * 2 + 1][0], bf[jp * 2 + 1][1],
                      uBh + boff[jp] + kb);
            #pragma unroll
            for (int mi = 0; mi < 4; mi++)
                #pragma unroll
                for (int nj = 0; nj < 4; nj++)
                    mma16816(acc[mi][nj], ah[mi], bf[nj]);
        }
        __syncthreads();
    }

    float as0[4], as1[4], ad0[4], ad1[4];
    #pragma unroll
    for (int nj = 0; nj < 4; nj++) {
        int c = col0 + wn * 32 + (lane & 3) * 2 + nj * 8;
        as0[nj] = avs[c]; as1[nj] = avs[c + 1];
        ad0[nj] = avd[c]; ad1[nj] = avd[c + 1];
    }

    #pragma unroll
    for (int mi = 0; mi < 4; mi++) {
        int r0g = row0 + wm * 64 + mi * 16 + (lane >> 2);
        int cg  = col0 + wn * 32 + (lane & 3) * 2;
        float pss0 = 0.f, psd0 = 0.f, pss1 = 0.f, psd1 = 0.f;
        #pragma unroll
        for (int nj = 0; nj < 4; nj++) {
            int c = cg + nj * 8;
            if (r0g < M)
                *(__half2*)(C16 + (size_t)r0g * Nc + c) =
                    __floats2half2_rn(acc[mi][nj][0], acc[mi][nj][1]);
            if (r0g + 8 < M)
                *(__half2*)(C16 + (size_t)(r0g + 8) * Nc + c) =
                    __floats2half2_rn(acc[mi][nj][2], acc[mi][nj][3]);
            pss0 = fmaf(acc[mi][nj][0], as0[nj], fmaf(acc[mi][nj][1], as1[nj], pss0));
            psd0 = fmaf(acc[mi][nj][0], ad0[nj], fmaf(acc[mi][nj][1], ad1[nj], psd0));
            pss1 = fmaf(acc[mi][nj][2], as0[nj], fmaf(acc[mi][nj][3], as1[nj], pss1));
            psd1 = fmaf(acc[mi][nj][2], ad0[nj], fmaf(acc[mi][nj][3], ad1[nj], psd1));
        }
        pss0 += __shfl_xor_sync(0xffffffffu, pss0, 1);
        pss0 += __shfl_xor_sync(0xffffffffu, pss0, 2);
        psd0 += __shfl_xor_sync(0xffffffffu, psd0, 1);
        psd0 += __shfl_xor_sync(0xffffffffu, psd0, 2);
        pss1 += __shfl_xor_sync(0xffffffffu, pss1, 1);
        pss1 += __shfl_xor_sync(0xffffffffu, pss1, 2);
        psd1 += __shfl_xor_sync(0xffffffffu, psd1, 1);
        psd1 += __shfl_xor_sync(0xffffffffu, psd1, 2);
        if ((lane & 3) == 0) {
            if (r0g < M) {
                atomicAdd(&ssrc[r0g], pss0);
                atomicAdd(&sdst[r0g], psd0);
            }
            if (r0g + 8 < M) {
                atomicAdd(&ssrc[r0g + 8], pss1);
                atomicAdd(&sdst[r0g + 8], psd1);
            }
        }
    }
}

// -------- fused GRU GEMM: flattened 24-chunk pipeline, fp16 stash, 2 CTA/SM --
#define STSTR  130                       // stash stride (halves; 260 B rows)
__global__ __launch_bounds__(256, 2) void k_mm_gru(const __half* __restrict__ AH,
                                                   const __half* __restrict__ BtH,
                                                   const float* __restrict__ b_ih,
                                                   const float* __restrict__ b_hh,
                                                   float* __restrict__ OUT,
                                                   int M)
{
    extern __shared__ char smem[];
    const uint32_t sb = smem_u32(smem);
    __half* stash_r = (__half*)(smem + 2 * BUF1);
    __half* stash_z = stash_r + 128 * STSTR;

    const int tid  = threadIdx.x;
    const int wid  = tid >> 5, lane = tid & 31;
    const int wm   = wid & 1, wn = wid >> 1;
    const int row0 = blockIdx.y * 128, col0 = blockIdx.x * 128;
    const int K = Hd;
    const int NCH = 3 * (K >> 5);          // 24 chunks total

    uint32_t aoff[4];
    #pragma unroll
    for (int mi = 0; mi < 4; mi++) {
        int r = wm * 64 + mi * 16 + (lane & 7) + ((lane >> 3) & 1) * 8;
        aoff[mi] = (uint32_t)(r * (SSTRIDE * 2) + (lane >> 4) * 16);
    }
    uint32_t boff[2];
    #pragma unroll
    for (int jp = 0; jp < 2; jp++) {
        int n = wn * 32 + jp * 16 + (lane & 7) + ((lane >> 4) & 1) * 8;
        boff[jp] = (uint32_t)(n * (SSTRIDE * 2) + ((lane >> 3) & 1) * 16);
    }

    auto issue = [&](int tt, int p) {
        const int gate = tt >> 3, kt = tt & 7;
        const int brow0 = gate * 256 + col0;
        #pragma unroll
        for (int c = 0; c < 2; c++) {
            int lin = tid + c * 256;
            int row = lin >> 2, q = lin & 3;
            uint32_t sd = sb + (uint32_t)(p * BUF1 + row * (SSTRIDE * 2) + q * 16);
            int ar = row0 + row;
            uint32_t asz = (ar < M) ? 16u : 0u;
            if (ar >= M) ar = 0;
            size_t aoffg = (size_t)ar * K + kt * 32 + q * 8;
            size_t boffg = (size_t)(brow0 + row) * K + kt * 32 + q * 8;
            cpa16(sd,          AH + aoffg, asz);
            cpa16(sd + ABYTES, BtH + boffg, 16u);
        }
        cpa_commit();
    };

    float acc[4][4][4];
    #pragma unroll
    for (int i = 0; i < 4; i++)
        #pragma unroll
        for (int j = 0; j < 4; j++)
            #pragma unroll
            for (int q = 0; q < 4; q++) acc[i][j][q] = 0.f;

    issue(0, 0);
    for (int tt = 0; tt < NCH; tt++) {
        const int p = tt & 1;
        if (tt + 1 < NCH) { issue(tt + 1, p ^ 1); cpa_wait<1>(); }
        else              { cpa_wait<0>(); }
        __syncthreads();

        const uint32_t uAh = sb + p * BUF1;
        const uint32_t uBh = uAh + ABYTES;

        #pragma unroll
        for (int ks = 0; ks < 2; ks++) {
            const uint32_t kb = (uint32_t)(ks * 32);
            uint32_t ah[4][4], bf[4][2];
            #pragma unroll
            for (int mi = 0; mi < 4; mi++)
                ldsm4(ah[mi][0], ah[mi][1], ah[mi][2], ah[mi][3], uAh + aoff[mi] + kb);
            #pragma unroll
            for (int jp = 0; jp < 2; jp++)
                ldsm4(bf[jp * 2][0], bf[jp * 2][1], bf[jp * 2 + 1][0], bf[jp * 2 + 1][1],
                      uBh + boff[jp] + kb);
            #pragma unroll
            for (int mi = 0; mi < 4; mi++)
                #pragma unroll
                for (int nj = 0; nj < 4; nj++)
                    mma16816(acc[mi][nj], ah[mi], bf[nj]);
        }
        __syncthreads();

        if ((tt & 7) == 7) {
            const int gate = tt >> 3;
            if (gate < 2) {
                __half* st = (gate == 0) ? stash_r : stash_z;
                const int go = gate * 256 + col0;
                #pragma unroll
                for (int mi = 0; mi < 4; mi++) {
                    int rl = wm * 64 + mi * 16 + (lane >> 2);
                    #pragma unroll
                    for (int nj = 0; nj < 4; nj++) {
                        int cl = wn * 32 + (lane & 3) * 2 + nj * 8;
                        float bs0 = b_ih[go + cl]     + b_hh[go + cl];
                        float bs1 = b_ih[go + cl + 1] + b_hh[go + cl + 1];
                        float s00 = 1.f / (1.f + expf(-(acc[mi][nj][0] + bs0)));
                        float s01 = 1.f / (1.f + expf(-(acc[mi][nj][1] + bs1)));
                        float s10 = 1.f / (1.f + expf(-(acc[mi][nj][2] + bs0)));
                        float s11 = 1.f / (1.f + expf(-(acc[mi][nj][3] + bs1)));
                        *(__half2*)&st[rl * STSTR + cl]       = __floats2half2_rn(s00, s01);
                        *(__half2*)&st[(rl + 8) * STSTR + cl] = __floats2half2_rn(s10, s11);
                    }
                }
            } else {
                const int go = 512 + col0;
                #pragma unroll
                for (int mi = 0; mi < 4; mi++) {
                    int rl = wm * 64 + mi * 16 + (lane >> 2);
                    int gr0 = row0 + rl, gr1 = gr0 + 8;
                    #pragma unroll
                    for (int nj = 0; nj < 4; nj++) {
                        int cl = wn * 32 + (lane & 3) * 2 + nj * 8;
                        float bi0 = b_ih[go + cl],     bh0 = b_hh[go + cl];
                        float bi1 = b_ih[go + cl + 1], bh1 = b_hh[go + cl + 1];
                        {
                            float2 rr = __half22float2(*(__half2*)&stash_r[rl * STSTR + cl]);
                            float2 zz = __half22float2(*(__half2*)&stash_z[rl * STSTR + cl]);
                            float h0 = (1.f - zz.x) * tanhf(acc[mi][nj][0] + bi0 + rr.x * bh0);
                            float h1 = (1.f - zz.y) * tanhf(acc[mi][nj][1] + bi1 + rr.y * bh1);
                            if (gr0 < M)
                                *(float2*)(OUT + (size_t)gr0 * Hd + col0 + cl) = make_float2(h0, h1);
                        }
                        {
                            float2 rr = __half22float2(*(__half2*)&stash_r[(rl + 8) * STSTR + cl]);
                            float2 zz = __half22float2(*(__half2*)&stash_z[(rl + 8) * STSTR + cl]);
                            float h0 = (1.f - zz.x) * tanhf(acc[mi][nj][2] + bi0 + rr.x * bh0);
                            float h1 = (1.f - zz.y) * tanhf(acc[mi][nj][3] + bi1 + rr.y * bh1);
                            if (gr1 < M)
                                *(float2*)(OUT + (size_t)gr1 * Hd + col0 + cl) = make_float2(h0, h1);
                        }
                    }
                }
            }
            #pragma unroll
            for (int i = 0; i < 4; i++)
                #pragma unroll
                for (int j = 0; j < 4; j++)
                    #pragma unroll
                    for (int q = 0; q < 4; q++) acc[i][j][q] = 0.f;
        }
    }
}

// ------------------------------ CSR build -----------------------------------
__global__ __launch_bounds__(1024) void k_scan(void)
{
    __shared__ int ssum[1024];
    const int CH = (Nn + 1023) / 1024;
    int tid = threadIdx.x;
    int base = tid * CH;
    int s = 0;
    for (int j = 0; j < CH; j++) {
        int idx = base + j;
        if (idx < Nn) s += g_cnt[idx];
    }
    ssum[tid] = s;
    __syncthreads();
    for (int off = 1; off < 1024; off <<= 1) {
        int v = (tid >= off) ? ssum[tid - off] : 0;
        __syncthreads();
        ssum[tid] += v;
        __syncthreads();
    }
    int run = (tid > 0) ? ssum[tid - 1] : 0;
    for (int j = 0; j < CH; j++) {
        int idx = base + j;
        if (idx < Nn) { g_offs[idx] = run; run += g_cnt[idx]; }
    }
    if (tid == 1023) g_offs[Nn] = ssum[1023];
}
__global__ void k_fill(void)
{
    int e = blockIdx.x * blockDim.x + threadIdx.x;
    if (e >= Ee) return;
    int d = g_dst[e];
    int pos = atomicAdd(&g_cur[d], 1);
    int slot = g_offs[d] + pos;
    g_adj[slot]  = g_src[e];
    g_adjd[slot] = d;
}

// ---- edge weights: p[i] = exp(lrelu(ssrc[src]+sdst[dst])); den[dst] += p ----
__global__ __launch_bounds__(256) void k_edgep(const float* __restrict__ ssrc,
                                               const float* __restrict__ sdst,
                                               float* __restrict__ den)
{
    int i = blockIdx.x * blockDim.x + threadIdx.x;
    if (i >= Ee) return;
    int s = g_adj[i], d = g_adjd[i];
    float v = ssrc[s] + sdst[d];
    v = v > 0.f ? v : NEG * v;
    float pp = expf(v);
    g_p[i] = pp;
    atomicAdd(&den[d], pp);
}

// -------- graph boundaries (batch is sorted): gstart[g] = lower_bound(g) ----
__global__ void k_gstart(void)
{
    int g = threadIdx.x;
    if (g > Gg) return;
    if (g == Gg) { g_gstart[g] = Nn; return; }
    int lo = 0, hi = Nn;
    while (lo < hi) {
        int mid = (lo + hi) >> 1;
        if (g_batch[mid] < g) lo = mid + 1; else hi = mid;
    }
    g_gstart[g] = lo;
}

// ---- GAT gather: one warp per dst; p precomputed; emits relu'd fp16 ---------
__global__ __launch_bounds__(256) void k_gather(const __half* __restrict__ xp16,
                                                const float* __restrict__ bias,
                                                const float* __restrict__ ssrc,
                                                const float* __restrict__ sdst,
                                                const float* __restrict__ den,
                                                __half* __restrict__ oh)
{
    int w = (blockIdx.x * blockDim.x + threadIdx.x) >> 5;
    int lane = threadIdx.x & 31;
    if (w >= Nn) return;
    int beg = g_offs[w], end = g_offs[w + 1];

    float vs = ssrc[w] + sdst[w];
    vs = vs > 0.f ? vs : NEG * vs;
    float ps = expf(vs);
    float inv = 1.f / (den[w] + ps);

    float acc[8];
    {
        uint4 rv = ((const uint4*)(xp16 + (size_t)w * Hd))[lane];
        float2 f0 = __half22float2(*(__half2*)&rv.x);
        float2 f1 = __half22float2(*(__half2*)&rv.y);
        float2 f2 = __half22float2(*(__half2*)&rv.z);
        float2 f3 = __half22float2(*(__half2*)&rv.w);
        acc[0] = ps * f0.x; acc[1] = ps * f0.y;
        acc[2] = ps * f1.x; acc[3] = ps * f1.y;
        acc[4] = ps * f2.x; acc[5] = ps * f2.y;
        acc[6] = ps * f3.x; acc[7] = ps * f3.y;
    }

    int i = beg;
    for (; i + 4 <= end; i += 4) {
        int s0 = g_adj[i], s1 = g_adj[i + 1], s2 = g_adj[i + 2], s3 = g_adj[i + 3];
        float c0 = g_p[i], c1 = g_p[i + 1], c2 = g_p[i + 2], c3 = g_p[i + 3];
        uint4 r0 = ((const uint4*)(xp16 + (size_t)s0 * Hd))[lane];
        uint4 r1 = ((const uint4*)(xp16 + (size_t)s1 * Hd))[lane];
        uint4 r2 = ((const uint4*)(xp16 + (size_t)s2 * Hd))[lane];
        uint4 r3 = ((const uint4*)(xp16 + (size_t)s3 * Hd))[lane];
        #pragma unroll
        for (int q = 0; q < 4; q++) {
            uint32_t* rw;
            float cc;
            if (q == 0) { rw = (uint32_t*)&r0; cc = c0; }
            else if (q == 1) { rw = (uint32_t*)&r1; cc = c1; }
            else if (q == 2) { rw = (uint32_t*)&r2; cc = c2; }
            else { rw = (uint32_t*)&r3; cc = c3; }
            #pragma unroll
            for (int h = 0; h < 4; h++) {
                float2 f = __half22float2(*(__half2*)&rw[h]);
                acc[h * 2]     = fmaf(cc, f.x, acc[h * 2]);
                acc[h * 2 + 1] = fmaf(cc, f.y, acc[h * 2 + 1]);
            }
        }
    }
    for (; i < end; i++) {
        int s = g_adj[i];
        float cc = g_p[i];
        uint4 rv = ((const uint4*)(xp16 + (size_t)s * Hd))[lane];
        uint32_t* rw = (uint32_t*)&rv;
        #pragma unroll
        for (int h = 0; h < 4; h++) {
            float2 f = __half22float2(*(__half2*)&rw[h]);
            acc[h * 2]     = fmaf(cc, f.x, acc[h * 2]);
            acc[h * 2 + 1] = fmaf(cc, f.y, acc[h * 2 + 1]);
        }
    }

    float4 b0 = ((const float4*)bias)[lane * 2];
    float4 b1 = ((const float4*)bias)[lane * 2 + 1];
    float bb[8] = {b0.x, b0.y, b0.z, b0.w, b1.x, b1.y, b1.z, b1.w};
    uint4 hs;
    uint32_t* hw = (uint32_t*)&hs;
    #pragma unroll
    for (int q = 0; q < 4; q++) {
        float v0 = fmaxf(fmaf(acc[q * 2], inv, bb[q * 2]), 0.f);
        float v1 = fmaxf(fmaf(acc[q * 2 + 1], inv, bb[q * 2 + 1]), 0.f);
        __half2 hh = __floats2half2_rn(v0, v1);
        hw[q] = *(uint32_t*)&hh;
    }
    *(uint4*)(oh + (size_t)w * Hd + 8 * lane) = hs;
}

// --------------- pooling: contiguous per-graph sum (batch sorted) -----------
__global__ __launch_bounds__(128) void k_pool_g(const float* __restrict__ hg,
                                                float* __restrict__ out)
{
    int g = blockIdx.x;
    int c = blockIdx.y * 128 + threadIdx.x;
    int beg = g_gstart[g], end = g_gstart[g + 1];
    float s = 0.f;
    for (int n = beg; n < end; n++) s += hg[(size_t)n * Hd + c];
    out[(size_t)g * (2 * Hd) + c] = s;
}

__global__ __launch_bounds__(256) void k_super(const float* __restrict__ Wf,
                                               const float* __restrict__ bf,
                                               float* __restrict__ out)
{
    __shared__ float s[Hd];
    int j = threadIdx.x;
    float sum = 0.f;
    for (int g = 0; g < Gg; g++) sum += out[(size_t)g * (2 * Hd) + j];
    s[j] = sum / (float)Gg;
    __syncthreads();
    float v = bf[j];
    #pragma unroll 8
    for (int c = 0; c < Hd; c++) v = fmaf(s[c], Wf[(size_t)j * Hd + c], v);
    v = fmaxf(v, 0.f);
    for (int g = 0; g < Gg; g++) out[(size_t)g * (2 * Hd) + Hd + j] = v;
}

// ------------------------------ launch --------------------------------------
extern "C" void kernel_launch(void* const* d_in, const int* in_sizes, int n_in,
                              void* d_out, int out_size)
{
    const float* x      = (const float*)d_in[0];
    const int*   ei32   = (const int*)d_in[1];
    const int*   b32    = (const int*)d_in[2];
    const float* W0     = (const float*)d_in[3];
    const float* a_src0 = (const float*)d_in[4];
    const float* a_dst0 = (const float*)d_in[5];
    const float* b0     = (const float*)d_in[6];
    const float* W1     = (const float*)d_in[7];
    const float* a_src1 = (const float*)d_in[8];
    const float* a_dst1 = (const float*)d_in[9];
    const float* b1     = (const float*)d_in[10];
    const float* W_ih   = (const float*)d_in[11];
    /* d_in[12] = W_hh: unused (h0 = 0) */
    const float* b_ih   = (const float*)d_in[13];
    const float* b_hh   = (const float*)d_in[14];
    const float* Wf     = (const float*)d_in[15];
    const float* bf     = (const float*)d_in[16];
    float*       out    = (float*)d_out;

    float *xp, *ssrc0, *sdst0, *den0, *ssrc1, *sdst1, *den1;
    __half *xp16, *ah, *bt0h, *bt1h, *bihh;
    cudaGetSymbolAddress((void**)&xp,    g_xp);
    cudaGetSymbolAddress((void**)&xp16,  g_xp16);
    cudaGetSymbolAddress((void**)&ssrc0, g_ssrc0);
    cudaGetSymbolAddress((void**)&sdst0, g_sdst0);
    cudaGetSymbolAddress((void**)&den0,  g_den0);
    cudaGetSymbolAddress((void**)&ssrc1, g_ssrc1);
    cudaGetSymbolAddress((void**)&sdst1, g_sdst1);
    cudaGetSymbolAddress((void**)&den1,  g_den1);
    cudaGetSymbolAddress((void**)&ah,    g_ah);
    cudaGetSymbolAddress((void**)&bt0h,  g_bt0h);
    cudaGetSymbolAddress((void**)&bt1h,  g_bt1h);
    cudaGetSymbolAddress((void**)&bihh,  g_bihh);

    const int SMEM  = 2 * BUF1;                          // 40960
    const int SMEMG = 2 * BUF1 + 2 * 128 * STSTR * 2;    // 107520
    cudaFuncSetAttribute(k_mm_f16, cudaFuncAttributeMaxDynamicSharedMemorySize, SMEM);
    cudaFuncSetAttribute(k_mm_gru, cudaFuncAttributeMaxDynamicSharedMemorySize, SMEMG);

    // one-time side stream + fork/join events (resource init only; per-call
    // work is identical and fully deterministic)
    static cudaStream_t s2 = nullptr;
    static cudaEvent_t evF = nullptr, evJ = nullptr;
    if (s2 == nullptr) {
        cudaStreamCreateWithFlags(&s2, cudaStreamNonBlocking);
        cudaEventCreateWithFlags(&evF, cudaEventDisableTiming);
        cudaEventCreateWithFlags(&evJ, cudaEventDisableTiming);
    }

    const int MT = (Nn + 127) / 128;   // 391
    dim3 blk(256);

    // ---- fork: CSR/decode branch on s2, weight/A-prep + L0 GEMM on main ----
    cudaEventRecord(evF, 0);
    cudaStreamWaitEvent(s2, evF, 0);

    // branch B (s2): index decode + CSR build + graph boundaries
    k_detect<<<1, 1, 0, s2>>>(ei32);
    k_decode_batch<<<(Nn + 255) / 256, blk, 0, s2>>>(b32);
    k_decode_count<<<(Ee + 255) / 256, blk, 0, s2>>>(ei32);
    k_scan<<<1, 1024, 0, s2>>>();
    k_fill<<<(Ee + 255) / 256, blk, 0, s2>>>();
    k_gstart<<<1, Gg + 1, 0, s2>>>();
    cudaEventRecord(evJ, s2);

    // branch A (main): zero attention scratch, prep weights, convert x, L0 GEMM
    k_zero_s<<<(Nn + 255) / 256, blk>>>();
    k_prep_w<<<(768 * 256 + 255) / 256, blk>>>(W0, W1, W_ih);
    k_split_x<<<(Nn * INC / 4 + 255) / 256, blk>>>(x, Nn * INC / 4);
    k_mm_f16<<<dim3(2, MT), blk, SMEM>>>(ah, bt0h, xp16,
                                         a_src0, a_dst0, ssrc0, sdst0, Nn, Hd, INC);

    // ---- join: everything below needs both branches ----
    cudaStreamWaitEvent(0, evJ, 0);

    // ---- GAT layer 0: edge weights + aggregate ----
    k_edgep<<<(Ee + 255) / 256, blk>>>(ssrc0, sdst0, den0);
    k_gather<<<(Nn * 32 + 255) / 256, blk>>>(xp16, b0, ssrc0, sdst0, den0, ah);

    // ---- GAT layer 1 (fp16) + fused attention dots ----
    k_mm_f16<<<dim3(2, MT), blk, SMEM>>>(ah, bt1h, xp16,
                                         a_src1, a_dst1, ssrc1, sdst1, Nn, Hd, Hd);
    k_edgep<<<(Ee + 255) / 256, blk>>>(ssrc1, sdst1, den1);
    k_gather<<<(Nn * 32 + 255) / 256, blk>>>(xp16, b1, ssrc1, sdst1, den1, ah);

    // ---- fused GRU GEMM + gates -> h (xp fp32) ----
    k_mm_gru<<<dim3(2, MT), blk, SMEMG>>>(ah, bihh, b_ih, b_hh, xp, Nn);

    // ---- pooling + super node ----
    k_pool_g<<<dim3(Gg, 2), 128>>>(xp, out);
    k_super<<<1, Hd>>>(Wf, bf, out);
}

// round 15
// speedup vs baseline: 3.0085x; 1.0777x over previous
#include <cuda_runtime.h>
#include <cuda_fp16.h>
#include <math.h>
#include <stdint.h>

#define Nn   50000
#define Ee   800000
#define INC  128
#define Hd   256
#define Gg   128
#define NEG  0.2f
#define SCB  512                          // scan elements per block
#define NSB  ((Nn + SCB - 1) / SCB)       // 98 scan blocks

// ---------------- scratch (device globals; no allocations allowed) ----------
__device__ float  g_xp[(size_t)Nn * Hd];          // GRU output (fp32, for pool)
__device__ __half g_xp16[(size_t)Nn * Hd];        // GAT projected features (fp16)
__device__ float g_ssrc0[Nn], g_sdst0[Nn], g_den0[Nn];
__device__ float g_ssrc1[Nn], g_sdst1[Nn], g_den1[Nn];
__device__ float g_p[Ee];                          // edge exp-weights (CSR order)
__device__ int   g_src[Ee];
__device__ int   g_dst[Ee];
__device__ int   g_batch[Nn];
__device__ int   g_cnt[Nn];
__device__ int   g_cur[Nn];
__device__ int   g_offs[Nn + 1];
__device__ int   g_bsum[NSB];
__device__ int   g_boff[NSB];
__device__ int   g_adj[Ee];                        // CSR: src ids grouped by dst
__device__ int   g_adjd[Ee];                       // CSR: dst id per slot
__device__ int   g_gstart[Gg + 1];
__device__ int   g_is64;
// fp16 A (reused across the three GEMMs)
__device__ __half g_ah[(size_t)Nn * Hd];
// fp16 weights, stored [N][K] (B^T layout, K contiguous -> mma row.col)
__device__ __half g_bt0h[256 * 128];
__device__ __half g_bt1h[256 * 256];
__device__ __half g_bihh[768 * 256];

// ---------------------------- PTX helpers -----------------------------------
__device__ __forceinline__ uint32_t smem_u32(const void* p) {
    uint32_t a;
    asm("{ .reg .u64 t; cvta.to.shared.u64 t, %1; cvt.u32.u64 %0, t; }" : "=r"(a) : "l"(p));
    return a;
}
__device__ __forceinline__ void ldsm4(uint32_t& r0, uint32_t& r1, uint32_t& r2, uint32_t& r3,
                                      uint32_t addr) {
    asm volatile("ldmatrix.sync.aligned.m8n8.x4.shared.b16 {%0,%1,%2,%3}, [%4];"
                 : "=r"(r0), "=r"(r1), "=r"(r2), "=r"(r3) : "r"(addr));
}
__device__ __forceinline__ void mma16816(float* d, const uint32_t* a, const uint32_t* b) {
    asm volatile("mma.sync.aligned.m16n8k16.row.col.f32.f16.f16.f32 "
                 "{%0,%1,%2,%3}, {%4,%5,%6,%7}, {%8,%9}, {%0,%1,%2,%3};"
                 : "+f"(d[0]), "+f"(d[1]), "+f"(d[2]), "+f"(d[3])
                 : "r"(a[0]), "r"(a[1]), "r"(a[2]), "r"(a[3]), "r"(b[0]), "r"(b[1]));
}
__device__ __forceinline__ void cpa16(uint32_t dst, const void* src, uint32_t sz) {
    asm volatile("cp.async.cg.shared.global [%0], [%1], 16, %2;"
                 :: "r"(dst), "l"(src), "r"(sz) : "memory");
}
__device__ __forceinline__ void cpa_commit() {
    asm volatile("cp.async.commit_group;" ::: "memory");
}
template<int N> __device__ __forceinline__ void cpa_wait() {
    asm volatile("cp.async.wait_group %0;" :: "n"(N) : "memory");
}

// ---------------- index dtype detection + decode ----------------------------
__global__ void k_detect(const int* __restrict__ ei32)
{
    // one warp: lanes check two high words each; int64 small values -> all zero
    int lane = threadIdx.x;
    int bad = (ei32[2 * lane + 1] != 0) | (ei32[2 * (lane + 32) + 1] != 0);
    unsigned m = __ballot_sync(0xffffffffu, bad);
    if (lane == 0) g_is64 = (m == 0u);
}
__global__ void k_decode_batch(const int* __restrict__ b32)
{
    int n = blockIdx.x * blockDim.x + threadIdx.x;
    if (n >= Nn) return;
    g_batch[n] = g_is64 ? b32[2 * n] : b32[n];
    g_cnt[n] = 0;  g_cur[n] = 0;
}
// zero attention scratch (main stream; must precede GEMM epilogue atomics)
__global__ void k_zero_s(void)
{
    int n = blockIdx.x * blockDim.x + threadIdx.x;
    if (n >= Nn) return;
    g_ssrc0[n] = 0.f; g_sdst0[n] = 0.f; g_den0[n] = 0.f;
    g_ssrc1[n] = 0.f; g_sdst1[n] = 0.f; g_den1[n] = 0.f;
}
__global__ void k_decode_count(const int* __restrict__ ei32)
{
    int e = blockIdx.x * blockDim.x + threadIdx.x;
    if (e >= Ee) return;
    int s, d;
    if (g_is64) { s = ei32[2 * e]; d = ei32[2 * (Ee + e)]; }
    else        { s = ei32[e];     d = ei32[Ee + e]; }
    g_src[e] = s;
    g_dst[e] = d;
    atomicAdd(&g_cnt[d], 1);
}

// ---------------- weight prep: transpose + fp16 ------------------------------
__global__ void k_prep_w(const float* __restrict__ W0, const float* __restrict__ W1,
                         const float* __restrict__ Wih)
{
    int t = blockIdx.x * blockDim.x + threadIdx.x;
    if (t < 256 * 128) {                       // Bt0[n][k] = W0[k][n]
        int n = t >> 7, k = t & 127;
        g_bt0h[t] = __float2half_rn(W0[k * 256 + n]);
    }
    if (t < 256 * 256) {                       // Bt1[n][k] = W1[k][n]
        int n = t >> 8, k = t & 255;
        g_bt1h[t] = __float2half_rn(W1[k * 256 + n]);
    }
    if (t < 768 * 256) {                       // Bih[n][k] = W_ih[n][k]
        g_bihh[t] = __float2half_rn(Wih[t]);
    }
}

// ---------------- A convert for x: fp32 -> fp16 -------------------------------
__global__ __launch_bounds__(256) void k_split_x(const float* __restrict__ src, int n4)
{
    int t = blockIdx.x * blockDim.x + threadIdx.x;
    if (t >= n4) return;
    float4 v = ((const float4*)src)[t];
    ushort4 hs;
    hs.x = __half_as_ushort(__float2half_rn(v.x));
    hs.y = __half_as_ushort(__float2half_rn(v.y));
    hs.z = __half_as_ushort(__float2half_rn(v.z));
    hs.w = __half_as_ushort(__float2half_rn(v.w));
    ((ushort4*)g_ah)[t] = hs;
}

// -------- pipelined 1-term fp16 GEMM + attention-dot epilogue ----------------
#define SSTRIDE 40                       // fp16 per SMEM row (80 B)
#define ABYTES  (128 * SSTRIDE * 2)      // 10240 B per array
#define BUF1    (2 * ABYTES)             // 20480 B per stage (A, Bh)
__global__ __launch_bounds__(256, 2) void k_mm_f16(const __half* __restrict__ AH,
                                                   const __half* __restrict__ BtH,
                                                   __half* __restrict__ C16,
                                                   const float* __restrict__ avs,
                                                   const float* __restrict__ avd,
                                                   float* __restrict__ ssrc,
                                                   float* __restrict__ sdst,
                                                   int M, int Nc, int K)
{
    extern __shared__ char smem[];
    const uint32_t sb = smem_u32(smem);

    const int tid  = threadIdx.x;
    const int wid  = tid >> 5, lane = tid & 31;
    const int wm   = wid & 1, wn = wid >> 1;
    const int row0 = blockIdx.y * 128, col0 = blockIdx.x * 128;

    uint32_t aoff[4];
    #pragma unroll
    for (int mi = 0; mi < 4; mi++) {
        int r = wm * 64 + mi * 16 + (lane & 7) + ((lane >> 3) & 1) * 8;
        aoff[mi] = (uint32_t)(r * (SSTRIDE * 2) + (lane >> 4) * 16);
    }
    uint32_t boff[2];
    #pragma unroll
    for (int jp = 0; jp < 2; jp++) {
        int n = wn * 32 + jp * 16 + (lane & 7) + ((lane >> 4) & 1) * 8;
        boff[jp] = (uint32_t)(n * (SSTRIDE * 2) + ((lane >> 3) & 1) * 16);
    }

    float acc[4][4][4];
    #pragma unroll
    for (int i = 0; i < 4; i++)
        #pragma unroll
        for (int j = 0; j < 4; j++)
            #pragma unroll
            for (int q = 0; q < 4; q++) acc[i][j][q] = 0.f;

    const int nit = K >> 5;
    auto issue = [&](int kt, int p) {
        #pragma unroll
        for (int c = 0; c < 2; c++) {
            int lin = tid + c * 256;
            int row = lin >> 2, q = lin & 3;
            uint32_t sd = sb + (uint32_t)(p * BUF1 + row * (SSTRIDE * 2) + q * 16);
            int ar = row0 + row;
            uint32_t asz = (ar < M) ? 16u : 0u;
            if (ar >= M) ar = 0;
            size_t aoffg = (size_t)ar * K + kt * 32 + q * 8;
            size_t boffg = (size_t)(col0 + row) * K + kt * 32 + q * 8;
            cpa16(sd,          AH + aoffg, asz);
            cpa16(sd + ABYTES, BtH + boffg, 16u);
        }
        cpa_commit();
    };

    issue(0, 0);
    for (int kt = 0; kt < nit; kt++) {
        const int p = kt & 1;
        if (kt + 1 < nit) { issue(kt + 1, p ^ 1); cpa_wait<1>(); }
        else              { cpa_wait<0>(); }
        __syncthreads();

        const uint32_t uAh = sb + p * BUF1;
        const uint32_t uBh = uAh + ABYTES;

        #pragma unroll
        for (int ks = 0; ks < 2; ks++) {
            const uint32_t kb = (uint32_t)(ks * 32);
            uint32_t ah[4][4], bf[4][2];
            #pragma unroll
            for (int mi = 0; mi < 4; mi++)
                ldsm4(ah[mi][0], ah[mi][1], ah[mi][2], ah[mi][3], uAh + aoff[mi] + kb);
            #pragma unroll
            for (int jp = 0; jp < 2; jp++)
                ldsm4(bf[jp * 2][0], bf[jp * 2][1], bf[jp * 2 + 1][0], bf[jp * 2 + 1][1],
                      uBh + boff[jp] + kb);
            #pragma unroll
            for (int mi = 0; mi < 4; mi++)
                #pragma unroll
                for (int nj = 0; nj < 4; nj++)
                    mma16816(acc[mi][nj], ah[mi], bf[nj]);
        }
        __syncthreads();
    }

    float as0[4], as1[4], ad0[4], ad1[4];
    #pragma unroll
    for (int nj = 0; nj < 4; nj++) {
        int c = col0 + wn * 32 + (lane & 3) * 2 + nj * 8;
        as0[nj] = avs[c]; as1[nj] = avs[c + 1];
        ad0[nj] = avd[c]; ad1[nj] = avd[c + 1];
    }

    #pragma unroll
    for (int mi = 0; mi < 4; mi++) {
        int r0g = row0 + wm * 64 + mi * 16 + (lane >> 2);
        int cg  = col0 + wn * 32 + (lane & 3) * 2;
        float pss0 = 0.f, psd0 = 0.f, pss1 = 0.f, psd1 = 0.f;
        #pragma unroll
        for (int nj = 0; nj < 4; nj++) {
            int c = cg + nj * 8;
            if (r0g < M)
                *(__half2*)(C16 + (size_t)r0g * Nc + c) =
                    __floats2half2_rn(acc[mi][nj][0], acc[mi][nj][1]);
            if (r0g + 8 < M)
                *(__half2*)(C16 + (size_t)(r0g + 8) * Nc + c) =
                    __floats2half2_rn(acc[mi][nj][2], acc[mi][nj][3]);
            pss0 = fmaf(acc[mi][nj][0], as0[nj], fmaf(acc[mi][nj][1], as1[nj], pss0));
            psd0 = fmaf(acc[mi][nj][0], ad0[nj], fmaf(acc[mi][nj][1], ad1[nj], psd0));
            pss1 = fmaf(acc[mi][nj][2], as0[nj], fmaf(acc[mi][nj][3], as1[nj], pss1));
            psd1 = fmaf(acc[mi][nj][2], ad0[nj], fmaf(acc[mi][nj][3], ad1[nj], psd1));
        }
        pss0 += __shfl_xor_sync(0xffffffffu, pss0, 1);
        pss0 += __shfl_xor_sync(0xffffffffu, pss0, 2);
        psd0 += __shfl_xor_sync(0xffffffffu, psd0, 1);
        psd0 += __shfl_xor_sync(0xffffffffu, psd0, 2);
        pss1 += __shfl_xor_sync(0xffffffffu, pss1, 1);
        pss1 += __shfl_xor_sync(0xffffffffu, pss1, 2);
        psd1 += __shfl_xor_sync(0xffffffffu, psd1, 1);
        psd1 += __shfl_xor_sync(0xffffffffu, psd1, 2);
        if ((lane & 3) == 0) {
            if (r0g < M) {
                atomicAdd(&ssrc[r0g], pss0);
                atomicAdd(&sdst[r0g], psd0);
            }
            if (r0g + 8 < M) {
                atomicAdd(&ssrc[r0g + 8], pss1);
                atomicAdd(&sdst[r0g + 8], psd1);
            }
        }
    }
}

// -------- fused GRU GEMM: flattened 24-chunk pipeline, fp16 stash, 2 CTA/SM --
#define STSTR  130                       // stash stride (halves; 260 B rows)
__global__ __launch_bounds__(256, 2) void k_mm_gru(const __half* __restrict__ AH,
                                                   const __half* __restrict__ BtH,
                                                   const float* __restrict__ b_ih,
                                                   const float* __restrict__ b_hh,
                                                   float* __restrict__ OUT,
                                                   int M)
{
    extern __shared__ char smem[];
    const uint32_t sb = smem_u32(smem);
    __half* stash_r = (__half*)(smem + 2 * BUF1);
    __half* stash_z = stash_r + 128 * STSTR;

    const int tid  = threadIdx.x;
    const int wid  = tid >> 5, lane = tid & 31;
    const int wm   = wid & 1, wn = wid >> 1;
    const int row0 = blockIdx.y * 128, col0 = blockIdx.x * 128;
    const int K = Hd;
    const int NCH = 3 * (K >> 5);          // 24 chunks total

    uint32_t aoff[4];
    #pragma unroll
    for (int mi = 0; mi < 4; mi++) {
        int r = wm * 64 + mi * 16 + (lane & 7) + ((lane >> 3) & 1) * 8;
        aoff[mi] = (uint32_t)(r * (SSTRIDE * 2) + (lane >> 4) * 16);
    }
    uint32_t boff[2];
    #pragma unroll
    for (int jp = 0; jp < 2; jp++) {
        int n = wn * 32 + jp * 16 + (lane & 7) + ((lane >> 4) & 1) * 8;
        boff[jp] = (uint32_t)(n * (SSTRIDE * 2) + ((lane >> 3) & 1) * 16);
    }

    auto issue = [&](int tt, int p) {
        const int gate = tt >> 3, kt = tt & 7;
        const int brow0 = gate * 256 + col0;
        #pragma unroll
        for (int c = 0; c < 2; c++) {
            int lin = tid + c * 256;
            int row = lin >> 2, q = lin & 3;
            uint32_t sd = sb + (uint32_t)(p * BUF1 + row * (SSTRIDE * 2) + q * 16);
            int ar = row0 + row;
            uint32_t asz = (ar < M) ? 16u : 0u;
            if (ar >= M) ar = 0;
            size_t aoffg = (size_t)ar * K + kt * 32 + q * 8;
            size_t boffg = (size_t)(brow0 + row) * K + kt * 32 + q * 8;
            cpa16(sd,          AH + aoffg, asz);
            cpa16(sd + ABYTES, BtH + boffg, 16u);
        }
        cpa_commit();
    };

    float acc[4][4][4];
    #pragma unroll
    for (int i = 0; i < 4; i++)
        #pragma unroll
        for (int j = 0; j < 4; j++)
            #pragma unroll
            for (int q = 0; q < 4; q++) acc[i][j][q] = 0.f;

    issue(0, 0);
    for (int tt = 0; tt < NCH; tt++) {
        const int p = tt & 1;
        if (tt + 1 < NCH) { issue(tt + 1, p ^ 1); cpa_wait<1>(); }
        else              { cpa_wait<0>(); }
        __syncthreads();

        const uint32_t uAh = sb + p * BUF1;
        const uint32_t uBh = uAh + ABYTES;

        #pragma unroll
        for (int ks = 0; ks < 2; ks++) {
            const uint32_t kb = (uint32_t)(ks * 32);
            uint32_t ah[4][4], bf[4][2];
            #pragma unroll
            for (int mi = 0; mi < 4; mi++)
                ldsm4(ah[mi][0], ah[mi][1], ah[mi][2], ah[mi][3], uAh + aoff[mi] + kb);
            #pragma unroll
            for (int jp = 0; jp < 2; jp++)
                ldsm4(bf[jp * 2][0], bf[jp * 2][1], bf[jp * 2 + 1][0], bf[jp * 2 + 1][1],
                      uBh + boff[jp] + kb);
            #pragma unroll
            for (int mi = 0; mi < 4; mi++)
                #pragma unroll
                for (int nj = 0; nj < 4; nj++)
                    mma16816(acc[mi][nj], ah[mi], bf[nj]);
        }
        __syncthreads();

        if ((tt & 7) == 7) {
            const int gate = tt >> 3;
            if (gate < 2) {
                __half* st = (gate == 0) ? stash_r : stash_z;
                const int go = gate * 256 + col0;
                #pragma unroll
                for (int mi = 0; mi < 4; mi++) {
                    int rl = wm * 64 + mi * 16 + (lane >> 2);
                    #pragma unroll
                    for (int nj = 0; nj < 4; nj++) {
                        int cl = wn * 32 + (lane & 3) * 2 + nj * 8;
                        float bs0 = b_ih[go + cl]     + b_hh[go + cl];
                        float bs1 = b_ih[go + cl + 1] + b_hh[go + cl + 1];
                        float s00 = 1.f / (1.f + expf(-(acc[mi][nj][0] + bs0)));
                        float s01 = 1.f / (1.f + expf(-(acc[mi][nj][1] + bs1)));
                        float s10 = 1.f / (1.f + expf(-(acc[mi][nj][2] + bs0)));
                        float s11 = 1.f / (1.f + expf(-(acc[mi][nj][3] + bs1)));
                        *(__half2*)&st[rl * STSTR + cl]       = __floats2half2_rn(s00, s01);
                        *(__half2*)&st[(rl + 8) * STSTR + cl] = __floats2half2_rn(s10, s11);
                    }
                }
            } else {
                const int go = 512 + col0;
                #pragma unroll
                for (int mi = 0; mi < 4; mi++) {
                    int rl = wm * 64 + mi * 16 + (lane >> 2);
                    int gr0 = row0 + rl, gr1 = gr0 + 8;
                    #pragma unroll
                    for (int nj = 0; nj < 4; nj++) {
                        int cl = wn * 32 + (lane & 3) * 2 + nj * 8;
                        float bi0 = b_ih[go + cl],     bh0 = b_hh[go + cl];
                        float bi1 = b_ih[go + cl + 1], bh1 = b_hh[go + cl + 1];
                        {
                            float2 rr = __half22float2(*(__half2*)&stash_r[rl * STSTR + cl]);
                            float2 zz = __half22float2(*(__half2*)&stash_z[rl * STSTR + cl]);
                            float h0 = (1.f - zz.x) * tanhf(acc[mi][nj][0] + bi0 + rr.x * bh0);
                            float h1 = (1.f - zz.y) * tanhf(acc[mi][nj][1] + bi1 + rr.y * bh1);
                            if (gr0 < M)
                                *(float2*)(OUT + (size_t)gr0 * Hd + col0 + cl) = make_float2(h0, h1);
                        }
                        {
                            float2 rr = __half22float2(*(__half2*)&stash_r[(rl + 8) * STSTR + cl]);
                            float2 zz = __half22float2(*(__half2*)&stash_z[(rl + 8) * STSTR + cl]);
                            float h0 = (1.f - zz.x) * tanhf(acc[mi][nj][2] + bi0 + rr.x * bh0);
                            float h1 = (1.f - zz.y) * tanhf(acc[mi][nj][3] + bi1 + rr.y * bh1);
                            if (gr1 < M)
                                *(float2*)(OUT + (size_t)gr1 * Hd + col0 + cl) = make_float2(h0, h1);
                        }
                    }
                }
            }
            #pragma unroll
            for (int i = 0; i < 4; i++)
                #pragma unroll
                for (int j = 0; j < 4; j++)
                    #pragma unroll
                    for (int q = 0; q < 4; q++) acc[i][j][q] = 0.f;
        }
    }
}

// ------------------------- device-wide 3-phase scan --------------------------
__global__ __launch_bounds__(SCB) void k_scan_a(void)
{
    __shared__ int ssum[SCB];
    int i = blockIdx.x * SCB + threadIdx.x;
    int v = (i < Nn) ? g_cnt[i] : 0;
    ssum[threadIdx.x] = v;
    __syncthreads();
    #pragma unroll
    for (int off = 1; off < SCB; off <<= 1) {
        int t = (threadIdx.x >= off) ? ssum[threadIdx.x - off] : 0;
        __syncthreads();
        ssum[threadIdx.x] += t;
        __syncthreads();
    }
    if (i < Nn) g_offs[i] = ssum[threadIdx.x] - v;     // local exclusive
    if (threadIdx.x == SCB - 1) g_bsum[blockIdx.x] = ssum[SCB - 1];
}
__global__ __launch_bounds__(128) void k_scan_b(void)
{
    __shared__ int ssum[128];
    int t = threadIdx.x;
    int v = (t < NSB) ? g_bsum[t] : 0;
    ssum[t] = v;
    __syncthreads();
    #pragma unroll
    for (int off = 1; off < 128; off <<= 1) {
        int u = (t >= off) ? ssum[t - off] : 0;
        __syncthreads();
        ssum[t] += u;
        __syncthreads();
    }
    if (t < NSB) g_boff[t] = ssum[t] - v;              // exclusive block offsets
}
__global__ __launch_bounds__(SCB) void k_scan_c(void)
{
    int i = blockIdx.x * SCB + threadIdx.x;
    if (i < Nn) g_offs[i] += g_boff[blockIdx.x];
    if (i == 0) g_offs[Nn] = Ee;                       // total edge count
}
__global__ void k_fill(void)
{
    int e = blockIdx.x * blockDim.x + threadIdx.x;
    if (e >= Ee) return;
    int d = g_dst[e];
    int pos = atomicAdd(&g_cur[d], 1);
    int slot = g_offs[d] + pos;
    g_adj[slot]  = g_src[e];
    g_adjd[slot] = d;
}

// ---- edge weights: p[i] = exp(lrelu(ssrc[src]+sdst[dst])); den[dst] += p ----
__global__ __launch_bounds__(256) void k_edgep(const float* __restrict__ ssrc,
                                               const float* __restrict__ sdst,
                                               float* __restrict__ den)
{
    int i = blockIdx.x * blockDim.x + threadIdx.x;
    if (i >= Ee) return;
    int s = g_adj[i], d = g_adjd[i];
    float v = ssrc[s] + sdst[d];
    v = v > 0.f ? v : NEG * v;
    float pp = expf(v);
    g_p[i] = pp;
    atomicAdd(&den[d], pp);
}

// -------- graph boundaries (batch is sorted): gstart[g] = lower_bound(g) ----
__global__ void k_gstart(void)
{
    int g = threadIdx.x;
    if (g > Gg) return;
    if (g == Gg) { g_gstart[g] = Nn; return; }
    int lo = 0, hi = Nn;
    while (lo < hi) {
        int mid = (lo + hi) >> 1;
        if (g_batch[mid] < g) lo = mid + 1; else hi = mid;
    }
    g_gstart[g] = lo;
}

// ---- GAT gather: one warp per dst; p precomputed; emits relu'd fp16 ---------
__global__ __launch_bounds__(256) void k_gather(const __half* __restrict__ xp16,
                                                const float* __restrict__ bias,
                                                const float* __restrict__ ssrc,
                                                const float* __restrict__ sdst,
                                                const float* __restrict__ den,
                                                __half* __restrict__ oh)
{
    int w = (blockIdx.x * blockDim.x + threadIdx.x) >> 5;
    int lane = threadIdx.x & 31;
    if (w >= Nn) return;
    int beg = g_offs[w], end = g_offs[w + 1];

    float vs = ssrc[w] + sdst[w];
    vs = vs > 0.f ? vs : NEG * vs;
    float ps = expf(vs);
    float inv = 1.f / (den[w] + ps);

    float acc[8];
    {
        uint4 rv = ((const uint4*)(xp16 + (size_t)w * Hd))[lane];
        float2 f0 = __half22float2(*(__half2*)&rv.x);
        float2 f1 = __half22float2(*(__half2*)&rv.y);
        float2 f2 = __half22float2(*(__half2*)&rv.z);
        float2 f3 = __half22float2(*(__half2*)&rv.w);
        acc[0] = ps * f0.x; acc[1] = ps * f0.y;
        acc[2] = ps * f1.x; acc[3] = ps * f1.y;
        acc[4] = ps * f2.x; acc[5] = ps * f2.y;
        acc[6] = ps * f3.x; acc[7] = ps * f3.y;
    }

    int i = beg;
    for (; i + 4 <= end; i += 4) {
        int s0 = g_adj[i], s1 = g_adj[i + 1], s2 = g_adj[i + 2], s3 = g_adj[i + 3];
        float c0 = g_p[i], c1 = g_p[i + 1], c2 = g_p[i + 2], c3 = g_p[i + 3];
        uint4 r0 = ((const uint4*)(xp16 + (size_t)s0 * Hd))[lane];
        uint4 r1 = ((const uint4*)(xp16 + (size_t)s1 * Hd))[lane];
        uint4 r2 = ((const uint4*)(xp16 + (size_t)s2 * Hd))[lane];
        uint4 r3 = ((const uint4*)(xp16 + (size_t)s3 * Hd))[lane];
        #pragma unroll
        for (int q = 0; q < 4; q++) {
            uint32_t* rw;
            float cc;
            if (q == 0) { rw = (uint32_t*)&r0; cc = c0; }
            else if (q == 1) { rw = (uint32_t*)&r1; cc = c1; }
            else if (q == 2) { rw = (uint32_t*)&r2; cc = c2; }
            else { rw = (uint32_t*)&r3; cc = c3; }
            #pragma unroll
            for (int h = 0; h < 4; h++) {
                float2 f = __half22float2(*(__half2*)&rw[h]);
                acc[h * 2]     = fmaf(cc, f.x, acc[h * 2]);
                acc[h * 2 + 1] = fmaf(cc, f.y, acc[h * 2 + 1]);
            }
        }
    }
    for (; i < end; i++) {
        int s = g_adj[i];
        float cc = g_p[i];
        uint4 rv = ((const uint4*)(xp16 + (size_t)s * Hd))[lane];
        uint32_t* rw = (uint32_t*)&rv;
        #pragma unroll
        for (int h = 0; h < 4; h++) {
            float2 f = __half22float2(*(__half2*)&rw[h]);
            acc[h * 2]     = fmaf(cc, f.x, acc[h * 2]);
            acc[h * 2 + 1] = fmaf(cc, f.y, acc[h * 2 + 1]);
        }
    }

    float4 b0 = ((const float4*)bias)[lane * 2];
    float4 b1 = ((const float4*)bias)[lane * 2 + 1];
    float bb[8] = {b0.x, b0.y, b0.z, b0.w, b1.x, b1.y, b1.z, b1.w};
    uint4 hs;
    uint32_t* hw = (uint32_t*)&hs;
    #pragma unroll
    for (int q = 0; q < 4; q++) {
        float v0 = fmaxf(fmaf(acc[q * 2], inv, bb[q * 2]), 0.f);
        float v1 = fmaxf(fmaf(acc[q * 2 + 1], inv, bb[q * 2 + 1]), 0.f);
        __half2 hh = __floats2half2_rn(v0, v1);
        hw[q] = *(uint32_t*)&hh;
    }
    *(uint4*)(oh + (size_t)w * Hd + 8 * lane) = hs;
}

// --------------- pooling: contiguous per-graph sum (batch sorted) -----------
__global__ __launch_bounds__(128) void k_pool_g(const float* __restrict__ hg,
                                                float* __restrict__ out)
{
    int g = blockIdx.x;
    int c = blockIdx.y * 128 + threadIdx.x;
    int beg = g_gstart[g], end = g_gstart[g + 1];
    float s = 0.f;
    for (int n = beg; n < end; n++) s += hg[(size_t)n * Hd + c];
    out[(size_t)g * (2 * Hd) + c] = s;
}

__global__ __launch_bounds__(256) void k_super(const float* __restrict__ Wf,
                                               const float* __restrict__ bf,
                                               float* __restrict__ out)
{
    __shared__ float s[Hd];
    int j = threadIdx.x;
    float sum = 0.f;
    for (int g = 0; g < Gg; g++) sum += out[(size_t)g * (2 * Hd) + j];
    s[j] = sum / (float)Gg;
    __syncthreads();
    float v = bf[j];
    #pragma unroll 8
    for (int c = 0; c < Hd; c++) v = fmaf(s[c], Wf[(size_t)j * Hd + c], v);
    v = fmaxf(v, 0.f);
    for (int g = 0; g < Gg; g++) out[(size_t)g * (2 * Hd) + Hd + j] = v;
}

// ------------------------------ launch --------------------------------------
extern "C" void kernel_launch(void* const* d_in, const int* in_sizes, int n_in,
                              void* d_out, int out_size)
{
    const float* x      = (const float*)d_in[0];
    const int*   ei32   = (const int*)d_in[1];
    const int*   b32    = (const int*)d_in[2];
    const float* W0     = (const float*)d_in[3];
    const float* a_src0 = (const float*)d_in[4];
    const float* a_dst0 = (const float*)d_in[5];
    const float* b0     = (const float*)d_in[6];
    const float* W1     = (const float*)d_in[7];
    const float* a_src1 = (const float*)d_in[8];
    const float* a_dst1 = (const float*)d_in[9];
    const float* b1     = (const float*)d_in[10];
    const float* W_ih   = (const float*)d_in[11];
    /* d_in[12] = W_hh: unused (h0 = 0) */
    const float* b_ih   = (const float*)d_in[13];
    const float* b_hh   = (const float*)d_in[14];
    const float* Wf     = (const float*)d_in[15];
    const float* bf     = (const float*)d_in[16];
    float*       out    = (float*)d_out;

    float *xp, *ssrc0, *sdst0, *den0, *ssrc1, *sdst1, *den1;
    __half *xp16, *ah, *bt0h, *bt1h, *bihh;
    cudaGetSymbolAddress((void**)&xp,    g_xp);
    cudaGetSymbolAddress((void**)&xp16,  g_xp16);
    cudaGetSymbolAddress((void**)&ssrc0, g_ssrc0);
    cudaGetSymbolAddress((void**)&sdst0, g_sdst0);
    cudaGetSymbolAddress((void**)&den0,  g_den0);
    cudaGetSymbolAddress((void**)&ssrc1, g_ssrc1);
    cudaGetSymbolAddress((void**)&sdst1, g_sdst1);
    cudaGetSymbolAddress((void**)&den1,  g_den1);
    cudaGetSymbolAddress((void**)&ah,    g_ah);
    cudaGetSymbolAddress((void**)&bt0h,  g_bt0h);
    cudaGetSymbolAddress((void**)&bt1h,  g_bt1h);
    cudaGetSymbolAddress((void**)&bihh,  g_bihh);

    const int SMEM  = 2 * BUF1;                          // 40960
    const int SMEMG = 2 * BUF1 + 2 * 128 * STSTR * 2;    // 107520
    cudaFuncSetAttribute(k_mm_f16, cudaFuncAttributeMaxDynamicSharedMemorySize, SMEM);
    cudaFuncSetAttribute(k_mm_gru, cudaFuncAttributeMaxDynamicSharedMemorySize, SMEMG);

    // one-time side stream + fork/join events (resource init only)
    static cudaStream_t s2 = nullptr;
    static cudaEvent_t evF = nullptr, evJ = nullptr;
    if (s2 == nullptr) {
        cudaStreamCreateWithFlags(&s2, cudaStreamNonBlocking);
        cudaEventCreateWithFlags(&evF, cudaEventDisableTiming);
        cudaEventCreateWithFlags(&evJ, cudaEventDisableTiming);
    }

    const int MT = (Nn + 127) / 128;   // 391
    dim3 blk(256);

    // ---- fork: CSR/decode branch on s2, weight/A-prep + L0 GEMM on main ----
    cudaEventRecord(evF, 0);
    cudaStreamWaitEvent(s2, evF, 0);

    // branch B (s2): index decode + CSR build + graph boundaries
    k_detect<<<1, 32, 0, s2>>>(ei32);
    k_decode_batch<<<(Nn + 255) / 256, blk, 0, s2>>>(b32);
    k_decode_count<<<(Ee + 255) / 256, blk, 0, s2>>>(ei32);
    k_scan_a<<<NSB, SCB, 0, s2>>>();
    k_scan_b<<<1, 128, 0, s2>>>();
    k_scan_c<<<NSB, SCB, 0, s2>>>();
    k_fill<<<(Ee + 255) / 256, blk, 0, s2>>>();
    k_gstart<<<1, Gg + 1, 0, s2>>>();
    cudaEventRecord(evJ, s2);

    // branch A (main): zero attention scratch, prep weights, convert x, L0 GEMM
    k_zero_s<<<(Nn + 255) / 256, blk>>>();
    k_prep_w<<<(768 * 256 + 255) / 256, blk>>>(W0, W1, W_ih);
    k_split_x<<<(Nn * INC / 4 + 255) / 256, blk>>>(x, Nn * INC / 4);
    k_mm_f16<<<dim3(2, MT), blk, SMEM>>>(ah, bt0h, xp16,
                                         a_src0, a_dst0, ssrc0, sdst0, Nn, Hd, INC);

    // ---- join: everything below needs both branches ----
    cudaStreamWaitEvent(0, evJ, 0);

    // ---- GAT layer 0: edge weights + aggregate ----
    k_edgep<<<(Ee + 255) / 256, blk>>>(ssrc0, sdst0, den0);
    k_gather<<<(Nn * 32 + 255) / 256, blk>>>(xp16, b0, ssrc0, sdst0, den0, ah);

    // ---- GAT layer 1 (fp16) + fused attention dots ----
    k_mm_f16<<<dim3(2, MT), blk, SMEM>>>(ah, bt1h, xp16,
                                         a_src1, a_dst1, ssrc1, sdst1, Nn, Hd, Hd);
    k_edgep<<<(Ee + 255) / 256, blk>>>(ssrc1, sdst1, den1);
    k_gather<<<(Nn * 32 + 255) / 256, blk>>>(xp16, b1, ssrc1, sdst1, den1, ah);

    // ---- fused GRU GEMM + gates -> h (xp fp32) ----
    k_mm_gru<<<dim3(2, MT), blk, SMEMG>>>(ah, bihh, b_ih, b_hh, xp, Nn);

    // ---- pooling + super node ----
    k_pool_g<<<dim3(Gg, 2), 128>>>(xp, out);
    k_super<<<1, Hd>>>(Wf, bf, out);
}

// round 16
// speedup vs baseline: 3.1122x; 1.0344x over previous
#include <cuda_runtime.h>
#include <cuda_fp16.h>
#include <math.h>
#include <stdint.h>

#define Nn   50000
#define Ee   800000
#define INC  128
#define Hd   256
#define Gg   128
#define NEG  0.2f
#define SCB  512                          // scan elements per block
#define NSB  ((Nn + SCB - 1) / SCB)       // 98 scan blocks

// ---------------- scratch (device globals; no allocations allowed) ----------
__device__ float  g_xp[(size_t)Nn * Hd];          // GRU output (fp32, for pool)
__device__ __half g_xp16[(size_t)Nn * Hd];        // GAT projected features (fp16)
__device__ float g_ssrc0[Nn], g_sdst0[Nn];
__device__ float g_ssrc1[Nn], g_sdst1[Nn];
__device__ float g_p[Ee];                          // edge exp-weights (CSR order)
__device__ int   g_src[Ee];
__device__ int   g_dst[Ee];
__device__ int   g_batch[Nn];
__device__ int   g_cnt[Nn];
__device__ int   g_cur[Nn];
__device__ int   g_offs[Nn + 1];
__device__ int   g_bsum[NSB];
__device__ int   g_boff[NSB];
__device__ int   g_adj[Ee];                        // CSR: src ids grouped by dst
__device__ int   g_adjd[Ee];                       // CSR: dst id per slot
__device__ int   g_gstart[Gg + 1];
__device__ int   g_is64;
// fp16 A (reused across the three GEMMs)
__device__ __half g_ah[(size_t)Nn * Hd];
// fp16 weights, stored [N][K] (B^T layout, K contiguous -> mma row.col)
__device__ __half g_bt0h[256 * 128];
__device__ __half g_bt1h[256 * 256];
__device__ __half g_bihh[768 * 256];

// ---------------------------- PTX helpers -----------------------------------
__device__ __forceinline__ uint32_t smem_u32(const void* p) {
    uint32_t a;
    asm("{ .reg .u64 t; cvta.to.shared.u64 t, %1; cvt.u32.u64 %0, t; }" : "=r"(a) : "l"(p));
    return a;
}
__device__ __forceinline__ void ldsm4(uint32_t& r0, uint32_t& r1, uint32_t& r2, uint32_t& r3,
                                      uint32_t addr) {
    asm volatile("ldmatrix.sync.aligned.m8n8.x4.shared.b16 {%0,%1,%2,%3}, [%4];"
                 : "=r"(r0), "=r"(r1), "=r"(r2), "=r"(r3) : "r"(addr));
}
__device__ __forceinline__ void mma16816(float* d, const uint32_t* a, const uint32_t* b) {
    asm volatile("mma.sync.aligned.m16n8k16.row.col.f32.f16.f16.f32 "
                 "{%0,%1,%2,%3}, {%4,%5,%6,%7}, {%8,%9}, {%0,%1,%2,%3};"
                 : "+f"(d[0]), "+f"(d[1]), "+f"(d[2]), "+f"(d[3])
                 : "r"(a[0]), "r"(a[1]), "r"(a[2]), "r"(a[3]), "r"(b[0]), "r"(b[1]));
}
__device__ __forceinline__ void cpa16(uint32_t dst, const void* src, uint32_t sz) {
    asm volatile("cp.async.cg.shared.global [%0], [%1], 16, %2;"
                 :: "r"(dst), "l"(src), "r"(sz) : "memory");
}
__device__ __forceinline__ void cpa_commit() {
    asm volatile("cp.async.commit_group;" ::: "memory");
}
template<int N> __device__ __forceinline__ void cpa_wait() {
    asm volatile("cp.async.wait_group %0;" :: "n"(N) : "memory");
}

// ---------------- index dtype detection + decode ----------------------------
__global__ void k_detect(const int* __restrict__ ei32)
{
    int lane = threadIdx.x;
    int bad = (ei32[2 * lane + 1] != 0) | (ei32[2 * (lane + 32) + 1] != 0);
    unsigned m = __ballot_sync(0xffffffffu, bad);
    if (lane == 0) g_is64 = (m == 0u);
}
__global__ void k_decode_batch(const int* __restrict__ b32)
{
    int n = blockIdx.x * blockDim.x + threadIdx.x;
    if (n >= Nn) return;
    g_batch[n] = g_is64 ? b32[2 * n] : b32[n];
    g_cnt[n] = 0;  g_cur[n] = 0;
}
__global__ void k_decode_count(const int* __restrict__ ei32)
{
    int e = blockIdx.x * blockDim.x + threadIdx.x;
    if (e >= Ee) return;
    int s, d;
    if (g_is64) { s = ei32[2 * e]; d = ei32[2 * (Ee + e)]; }
    else        { s = ei32[e];     d = ei32[Ee + e]; }
    g_src[e] = s;
    g_dst[e] = d;
    atomicAdd(&g_cnt[d], 1);
}

// ------- weight prep: transpose + fp16; also zeros attention scratch --------
__global__ void k_prep_w(const float* __restrict__ W0, const float* __restrict__ W1,
                         const float* __restrict__ Wih)
{
    int t = blockIdx.x * blockDim.x + threadIdx.x;
    if (t < Nn) {                              // zero attention scratch (main stream)
        g_ssrc0[t] = 0.f; g_sdst0[t] = 0.f;
        g_ssrc1[t] = 0.f; g_sdst1[t] = 0.f;
    }
    if (t < 256 * 128) {                       // Bt0[n][k] = W0[k][n]
        int n = t >> 7, k = t & 127;
        g_bt0h[t] = __float2half_rn(W0[k * 256 + n]);
    }
    if (t < 256 * 256) {                       // Bt1[n][k] = W1[k][n]
        int n = t >> 8, k = t & 255;
        g_bt1h[t] = __float2half_rn(W1[k * 256 + n]);
    }
    if (t < 768 * 256) {                       // Bih[n][k] = W_ih[n][k]
        g_bihh[t] = __float2half_rn(Wih[t]);
    }
}

// ---------------- A convert for x: fp32 -> fp16 -------------------------------
__global__ __launch_bounds__(256) void k_split_x(const float* __restrict__ src, int n4)
{
    int t = blockIdx.x * blockDim.x + threadIdx.x;
    if (t >= n4) return;
    float4 v = ((const float4*)src)[t];
    ushort4 hs;
    hs.x = __half_as_ushort(__float2half_rn(v.x));
    hs.y = __half_as_ushort(__float2half_rn(v.y));
    hs.z = __half_as_ushort(__float2half_rn(v.z));
    hs.w = __half_as_ushort(__float2half_rn(v.w));
    ((ushort4*)g_ah)[t] = hs;
}

// -------- pipelined 1-term fp16 GEMM + attention-dot epilogue ----------------
#define SSTRIDE 40                       // fp16 per SMEM row (80 B)
#define ABYTES  (128 * SSTRIDE * 2)      // 10240 B per array
#define BUF1    (2 * ABYTES)             // 20480 B per stage (A, Bh)
__global__ __launch_bounds__(256, 2) void k_mm_f16(const __half* __restrict__ AH,
                                                   const __half* __restrict__ BtH,
                                                   __half* __restrict__ C16,
                                                   const float* __restrict__ avs,
                                                   const float* __restrict__ avd,
                                                   float* __restrict__ ssrc,
                                                   float* __restrict__ sdst,
                                                   int M, int Nc, int K)
{
    extern __shared__ char smem[];
    const uint32_t sb = smem_u32(smem);

    const int tid  = threadIdx.x;
    const int wid  = tid >> 5, lane = tid & 31;
    const int wm   = wid & 1, wn = wid >> 1;
    const int row0 = blockIdx.y * 128, col0 = blockIdx.x * 128;

    uint32_t aoff[4];
    #pragma unroll
    for (int mi = 0; mi < 4; mi++) {
        int r = wm * 64 + mi * 16 + (lane & 7) + ((lane >> 3) & 1) * 8;
        aoff[mi] = (uint32_t)(r * (SSTRIDE * 2) + (lane >> 4) * 16);
    }
    uint32_t boff[2];
    #pragma unroll
    for (int jp = 0; jp < 2; jp++) {
        int n = wn * 32 + jp * 16 + (lane & 7) + ((lane >> 4) & 1) * 8;
        boff[jp] = (uint32_t)(n * (SSTRIDE * 2) + ((lane >> 3) & 1) * 16);
    }

    float acc[4][4][4];
    #pragma unroll
    for (int i = 0; i < 4; i++)
        #pragma unroll
        for (int j = 0; j < 4; j++)
            #pragma unroll
            for (int q = 0; q < 4; q++) acc[i][j][q] = 0.f;

    const int nit = K >> 5;
    auto issue = [&](int kt, int p) {
        #pragma unroll
        for (int c = 0; c < 2; c++) {
            int lin = tid + c * 256;
            int row = lin >> 2, q = lin & 3;
            uint32_t sd = sb + (uint32_t)(p * BUF1 + row * (SSTRIDE * 2) + q * 16);
            int ar = row0 + row;
            uint32_t asz = (ar < M) ? 16u : 0u;
            if (ar >= M) ar = 0;
            size_t aoffg = (size_t)ar * K + kt * 32 + q * 8;
            size_t boffg = (size_t)(col0 + row) * K + kt * 32 + q * 8;
            cpa16(sd,          AH + aoffg, asz);
            cpa16(sd + ABYTES, BtH + boffg, 16u);
        }
        cpa_commit();
    };

    issue(0, 0);
    for (int kt = 0; kt < nit; kt++) {
        const int p = kt & 1;
        if (kt + 1 < nit) { issue(kt + 1, p ^ 1); cpa_wait<1>(); }
        else              { cpa_wait<0>(); }
        __syncthreads();

        const uint32_t uAh = sb + p * BUF1;
        const uint32_t uBh = uAh + ABYTES;

        #pragma unroll
        for (int ks = 0; ks < 2; ks++) {
            const uint32_t kb = (uint32_t)(ks * 32);
            uint32_t ah[4][4], bf[4][2];
            #pragma unroll
            for (int mi = 0; mi < 4; mi++)
                ldsm4(ah[mi][0], ah[mi][1], ah[mi][2], ah[mi][3], uAh + aoff[mi] + kb);
            #pragma unroll
            for (int jp = 0; jp < 2; jp++)
                ldsm4(bf[jp * 2][0], bf[jp * 2][1], bf[jp * 2 + 1][0], bf[jp * 2 + 1][1],
                      uBh + boff[jp] + kb);
            #pragma unroll
            for (int mi = 0; mi < 4; mi++)
                #pragma unroll
                for (int nj = 0; nj < 4; nj++)
                    mma16816(acc[mi][nj], ah[mi], bf[nj]);
        }
        __syncthreads();
    }

    float as0[4], as1[4], ad0[4], ad1[4];
    #pragma unroll
    for (int nj = 0; nj < 4; nj++) {
        int c = col0 + wn * 32 + (lane & 3) * 2 + nj * 8;
        as0[nj] = avs[c]; as1[nj] = avs[c + 1];
        ad0[nj] = avd[c]; ad1[nj] = avd[c + 1];
    }

    #pragma unroll
    for (int mi = 0; mi < 4; mi++) {
        int r0g = row0 + wm * 64 + mi * 16 + (lane >> 2);
        int cg  = col0 + wn * 32 + (lane & 3) * 2;
        float pss0 = 0.f, psd0 = 0.f, pss1 = 0.f, psd1 = 0.f;
        #pragma unroll
        for (int nj = 0; nj < 4; nj++) {
            int c = cg + nj * 8;
            if (r0g < M)
                *(__half2*)(C16 + (size_t)r0g * Nc + c) =
                    __floats2half2_rn(acc[mi][nj][0], acc[mi][nj][1]);
            if (r0g + 8 < M)
                *(__half2*)(C16 + (size_t)(r0g + 8) * Nc + c) =
                    __floats2half2_rn(acc[mi][nj][2], acc[mi][nj][3]);
            pss0 = fmaf(acc[mi][nj][0], as0[nj], fmaf(acc[mi][nj][1], as1[nj], pss0));
            psd0 = fmaf(acc[mi][nj][0], ad0[nj], fmaf(acc[mi][nj][1], ad1[nj], psd0));
            pss1 = fmaf(acc[mi][nj][2], as0[nj], fmaf(acc[mi][nj][3], as1[nj], pss1));
            psd1 = fmaf(acc[mi][nj][2], ad0[nj], fmaf(acc[mi][nj][3], ad1[nj], psd1));
        }
        pss0 += __shfl_xor_sync(0xffffffffu, pss0, 1);
        pss0 += __shfl_xor_sync(0xffffffffu, pss0, 2);
        psd0 += __shfl_xor_sync(0xffffffffu, psd0, 1);
        psd0 += __shfl_xor_sync(0xffffffffu, psd0, 2);
        pss1 += __shfl_xor_sync(0xffffffffu, pss1, 1);
        pss1 += __shfl_xor_sync(0xffffffffu, pss1, 2);
        psd1 += __shfl_xor_sync(0xffffffffu, psd1, 1);
        psd1 += __shfl_xor_sync(0xffffffffu, psd1, 2);
        if ((lane & 3) == 0) {
            if (r0g < M) {
                atomicAdd(&ssrc[r0g], pss0);
                atomicAdd(&sdst[r0g], psd0);
            }
            if (r0g + 8 < M) {
                atomicAdd(&ssrc[r0g + 8], pss1);
                atomicAdd(&sdst[r0g + 8], psd1);
            }
        }
    }
}

// -------- fused GRU GEMM: flattened 24-chunk pipeline, fp16 stash, 2 CTA/SM --
#define STSTR  130                       // stash stride (halves; 260 B rows)
__global__ __launch_bounds__(256, 2) void k_mm_gru(const __half* __restrict__ AH,
                                                   const __half* __restrict__ BtH,
                                                   const float* __restrict__ b_ih,
                                                   const float* __restrict__ b_hh,
                                                   float* __restrict__ OUT,
                                                   int M)
{
    extern __shared__ char smem[];
    const uint32_t sb = smem_u32(smem);
    __half* stash_r = (__half*)(smem + 2 * BUF1);
    __half* stash_z = stash_r + 128 * STSTR;

    const int tid  = threadIdx.x;
    const int wid  = tid >> 5, lane = tid & 31;
    const int wm   = wid & 1, wn = wid >> 1;
    const int row0 = blockIdx.y * 128, col0 = blockIdx.x * 128;
    const int K = Hd;
    const int NCH = 3 * (K >> 5);          // 24 chunks total

    uint32_t aoff[4];
    #pragma unroll
    for (int mi = 0; mi < 4; mi++) {
        int r = wm * 64 + mi * 16 + (lane & 7) + ((lane >> 3) & 1) * 8;
        aoff[mi] = (uint32_t)(r * (SSTRIDE * 2) + (lane >> 4) * 16);
    }
    uint32_t boff[2];
    #pragma unroll
    for (int jp = 0; jp < 2; jp++) {
        int n = wn * 32 + jp * 16 + (lane & 7) + ((lane >> 4) & 1) * 8;
        boff[jp] = (uint32_t)(n * (SSTRIDE * 2) + ((lane >> 3) & 1) * 16);
    }

    auto issue = [&](int tt, int p) {
        const int gate = tt >> 3, kt = tt & 7;
        const int brow0 = gate * 256 + col0;
        #pragma unroll
        for (int c = 0; c < 2; c++) {
            int lin = tid + c * 256;
            int row = lin >> 2, q = lin & 3;
            uint32_t sd = sb + (uint32_t)(p * BUF1 + row * (SSTRIDE * 2) + q * 16);
            int ar = row0 + row;
            uint32_t asz = (ar < M) ? 16u : 0u;
            if (ar >= M) ar = 0;
            size_t aoffg = (size_t)ar * K + kt * 32 + q * 8;
            size_t boffg = (size_t)(brow0 + row) * K + kt * 32 + q * 8;
            cpa16(sd,          AH + aoffg, asz);
            cpa16(sd + ABYTES, BtH + boffg, 16u);
        }
        cpa_commit();
    };

    float acc[4][4][4];
    #pragma unroll
    for (int i = 0; i < 4; i++)
        #pragma unroll
        for (int j = 0; j < 4; j++)
            #pragma unroll
            for (int q = 0; q < 4; q++) acc[i][j][q] = 0.f;

    issue(0, 0);
    for (int tt = 0; tt < NCH; tt++) {
        const int p = tt & 1;
        if (tt + 1 < NCH) { issue(tt + 1, p ^ 1); cpa_wait<1>(); }
        else              { cpa_wait<0>(); }
        __syncthreads();

        const uint32_t uAh = sb + p * BUF1;
        const uint32_t uBh = uAh + ABYTES;

        #pragma unroll
        for (int ks = 0; ks < 2; ks++) {
            const uint32_t kb = (uint32_t)(ks * 32);
            uint32_t ah[4][4], bf[4][2];
            #pragma unroll
            for (int mi = 0; mi < 4; mi++)
                ldsm4(ah[mi][0], ah[mi][1], ah[mi][2], ah[mi][3], uAh + aoff[mi] + kb);
            #pragma unroll
            for (int jp = 0; jp < 2; jp++)
                ldsm4(bf[jp * 2][0], bf[jp * 2][1], bf[jp * 2 + 1][0], bf[jp * 2 + 1][1],
                      uBh + boff[jp] + kb);
            #pragma unroll
            for (int mi = 0; mi < 4; mi++)
                #pragma unroll
                for (int nj = 0; nj < 4; nj++)
                    mma16816(acc[mi][nj], ah[mi], bf[nj]);
        }
        __syncthreads();

        if ((tt & 7) == 7) {
            const int gate = tt >> 3;
            if (gate < 2) {
                __half* st = (gate == 0) ? stash_r : stash_z;
                const int go = gate * 256 + col0;
                #pragma unroll
                for (int mi = 0; mi < 4; mi++) {
                    int rl = wm * 64 + mi * 16 + (lane >> 2);
                    #pragma unroll
                    for (int nj = 0; nj < 4; nj++) {
                        int cl = wn * 32 + (lane & 3) * 2 + nj * 8;
                        float bs0 = b_ih[go + cl]     + b_hh[go + cl];
                        float bs1 = b_ih[go + cl + 1] + b_hh[go + cl + 1];
                        float s00 = 1.f / (1.f + expf(-(acc[mi][nj][0] + bs0)));
                        float s01 = 1.f / (1.f + expf(-(acc[mi][nj][1] + bs1)));
                        float s10 = 1.f / (1.f + expf(-(acc[mi][nj][2] + bs0)));
                        float s11 = 1.f / (1.f + expf(-(acc[mi][nj][3] + bs1)));
                        *(__half2*)&st[rl * STSTR + cl]       = __floats2half2_rn(s00, s01);
                        *(__half2*)&st[(rl + 8) * STSTR + cl] = __floats2half2_rn(s10, s11);
                    }
                }
            } else {
                const int go = 512 + col0;
                #pragma unroll
                for (int mi = 0; mi < 4; mi++) {
                    int rl = wm * 64 + mi * 16 + (lane >> 2);
                    int gr0 = row0 + rl, gr1 = gr0 + 8;
                    #pragma unroll
                    for (int nj = 0; nj < 4; nj++) {
                        int cl = wn * 32 + (lane & 3) * 2 + nj * 8;
                        float bi0 = b_ih[go + cl],     bh0 = b_hh[go + cl];
                        float bi1 = b_ih[go + cl + 1], bh1 = b_hh[go + cl + 1];
                        {
                            float2 rr = __half22float2(*(__half2*)&stash_r[rl * STSTR + cl]);
                            float2 zz = __half22float2(*(__half2*)&stash_z[rl * STSTR + cl]);
                            float h0 = (1.f - zz.x) * tanhf(acc[mi][nj][0] + bi0 + rr.x * bh0);
                            float h1 = (1.f - zz.y) * tanhf(acc[mi][nj][1] + bi1 + rr.y * bh1);
                            if (gr0 < M)
                                *(float2*)(OUT + (size_t)gr0 * Hd + col0 + cl) = make_float2(h0, h1);
                        }
                        {
                            float2 rr = __half22float2(*(__half2*)&stash_r[(rl + 8) * STSTR + cl]);
                            float2 zz = __half22float2(*(__half2*)&stash_z[(rl + 8) * STSTR + cl]);
                            float h0 = (1.f - zz.x) * tanhf(acc[mi][nj][2] + bi0 + rr.x * bh0);
                            float h1 = (1.f - zz.y) * tanhf(acc[mi][nj][3] + bi1 + rr.y * bh1);
                            if (gr1 < M)
                                *(float2*)(OUT + (size_t)gr1 * Hd + col0 + cl) = make_float2(h0, h1);
                        }
                    }
                }
            }
            #pragma unroll
            for (int i = 0; i < 4; i++)
                #pragma unroll
                for (int j = 0; j < 4; j++)
                    #pragma unroll
                    for (int q = 0; q < 4; q++) acc[i][j][q] = 0.f;
        }
    }
}

// ------------------------- device-wide 3-phase scan --------------------------
__global__ __launch_bounds__(SCB) void k_scan_a(void)
{
    __shared__ int ssum[SCB];
    int i = blockIdx.x * SCB + threadIdx.x;
    int v = (i < Nn) ? g_cnt[i] : 0;
    ssum[threadIdx.x] = v;
    __syncthreads();
    #pragma unroll
    for (int off = 1; off < SCB; off <<= 1) {
        int t = (threadIdx.x >= off) ? ssum[threadIdx.x - off] : 0;
        __syncthreads();
        ssum[threadIdx.x] += t;
        __syncthreads();
    }
    if (i < Nn) g_offs[i] = ssum[threadIdx.x] - v;     // local exclusive
    if (threadIdx.x == SCB - 1) g_bsum[blockIdx.x] = ssum[SCB - 1];
}
__global__ __launch_bounds__(128) void k_scan_b(void)
{
    __shared__ int ssum[128];
    int t = threadIdx.x;
    int v = (t < NSB) ? g_bsum[t] : 0;
    ssum[t] = v;
    __syncthreads();
    #pragma unroll
    for (int off = 1; off < 128; off <<= 1) {
        int u = (t >= off) ? ssum[t - off] : 0;
        __syncthreads();
        ssum[t] += u;
        __syncthreads();
    }
    if (t < NSB) g_boff[t] = ssum[t] - v;              // exclusive block offsets
}
__global__ __launch_bounds__(SCB) void k_scan_c(void)
{
    int i = blockIdx.x * SCB + threadIdx.x;
    if (i < Nn) g_offs[i] += g_boff[blockIdx.x];
    if (i == 0) g_offs[Nn] = Ee;
}
__global__ void k_fill(void)
{
    int e = blockIdx.x * blockDim.x + threadIdx.x;
    if (e >= Ee) return;
    int d = g_dst[e];
    int pos = atomicAdd(&g_cur[d], 1);
    int slot = g_offs[d] + pos;
    g_adj[slot]  = g_src[e];
    g_adjd[slot] = d;
}

// ---- edge weights: p[i] = exp(lrelu(ssrc[src]+sdst[dst])) (pure map) --------
__global__ __launch_bounds__(256) void k_edgep(const float* __restrict__ ssrc,
                                               const float* __restrict__ sdst)
{
    int i = blockIdx.x * blockDim.x + threadIdx.x;
    if (i >= Ee) return;
    float v = ssrc[g_adj[i]] + sdst[g_adjd[i]];
    v = v > 0.f ? v : NEG * v;
    g_p[i] = expf(v);
}

// -------- graph boundaries (batch is sorted): gstart[g] = lower_bound(g) ----
__global__ void k_gstart(void)
{
    int g = threadIdx.x;
    if (g > Gg) return;
    if (g == Gg) { g_gstart[g] = Nn; return; }
    int lo = 0, hi = Nn;
    while (lo < hi) {
        int mid = (lo + hi) >> 1;
        if (g_batch[mid] < g) lo = mid + 1; else hi = mid;
    }
    g_gstart[g] = lo;
}

// ---- GAT gather: one warp per dst; p precomputed; den summed inline ---------
__global__ __launch_bounds__(256) void k_gather(const __half* __restrict__ xp16,
                                                const float* __restrict__ bias,
                                                const float* __restrict__ ssrc,
                                                const float* __restrict__ sdst,
                                                __half* __restrict__ oh)
{
    int w = (blockIdx.x * blockDim.x + threadIdx.x) >> 5;
    int lane = threadIdx.x & 31;
    if (w >= Nn) return;
    int beg = g_offs[w], end = g_offs[w + 1];

    float vs = ssrc[w] + sdst[w];
    vs = vs > 0.f ? vs : NEG * vs;
    float ps = expf(vs);
    float den = ps;                       // accumulate denominator inline

    float acc[8];
    {
        uint4 rv = ((const uint4*)(xp16 + (size_t)w * Hd))[lane];
        float2 f0 = __half22float2(*(__half2*)&rv.x);
        float2 f1 = __half22float2(*(__half2*)&rv.y);
        float2 f2 = __half22float2(*(__half2*)&rv.z);
        float2 f3 = __half22float2(*(__half2*)&rv.w);
        acc[0] = ps * f0.x; acc[1] = ps * f0.y;
        acc[2] = ps * f1.x; acc[3] = ps * f1.y;
        acc[4] = ps * f2.x; acc[5] = ps * f2.y;
        acc[6] = ps * f3.x; acc[7] = ps * f3.y;
    }

    int i = beg;
    // 8-wide: two 4-batches of independent row loads in flight
    for (; i + 8 <= end; i += 8) {
        int   sI[8];
        float cI[8];
        #pragma unroll
        for (int q = 0; q < 8; q++) { sI[q] = g_adj[i + q]; cI[q] = g_p[i + q]; }
        uint4 rA[4], rB[4];
        #pragma unroll
        for (int q = 0; q < 4; q++)
            rA[q] = ((const uint4*)(xp16 + (size_t)sI[q] * Hd))[lane];
        #pragma unroll
        for (int q = 0; q < 4; q++)
            rB[q] = ((const uint4*)(xp16 + (size_t)sI[4 + q] * Hd))[lane];
        #pragma unroll
        for (int q = 0; q < 4; q++) {
            float cc = cI[q];
            den += cc;
            uint32_t* rw = (uint32_t*)&rA[q];
            #pragma unroll
            for (int h = 0; h < 4; h++) {
                float2 f = __half22float2(*(__half2*)&rw[h]);
                acc[h * 2]     = fmaf(cc, f.x, acc[h * 2]);
                acc[h * 2 + 1] = fmaf(cc, f.y, acc[h * 2 + 1]);
            }
        }
        #pragma unroll
        for (int q = 0; q < 4; q++) {
            float cc = cI[4 + q];
            den += cc;
            uint32_t* rw = (uint32_t*)&rB[q];
            #pragma unroll
            for (int h = 0; h < 4; h++) {
                float2 f = __half22float2(*(__half2*)&rw[h]);
                acc[h * 2]     = fmaf(cc, f.x, acc[h * 2]);
                acc[h * 2 + 1] = fmaf(cc, f.y, acc[h * 2 + 1]);
            }
        }
    }
    for (; i < end; i++) {
        int s = g_adj[i];
        float cc = g_p[i];
        den += cc;
        uint4 rv = ((const uint4*)(xp16 + (size_t)s * Hd))[lane];
        uint32_t* rw = (uint32_t*)&rv;
        #pragma unroll
        for (int h = 0; h < 4; h++) {
            float2 f = __half22float2(*(__half2*)&rw[h]);
            acc[h * 2]     = fmaf(cc, f.x, acc[h * 2]);
            acc[h * 2 + 1] = fmaf(cc, f.y, acc[h * 2 + 1]);
        }
    }

    float inv = 1.f / den;
    float4 b0 = ((const float4*)bias)[lane * 2];
    float4 b1 = ((const float4*)bias)[lane * 2 + 1];
    float bb[8] = {b0.x, b0.y, b0.z, b0.w, b1.x, b1.y, b1.z, b1.w};
    uint4 hs;
    uint32_t* hw = (uint32_t*)&hs;
    #pragma unroll
    for (int q = 0; q < 4; q++) {
        float v0 = fmaxf(fmaf(acc[q * 2], inv, bb[q * 2]), 0.f);
        float v1 = fmaxf(fmaf(acc[q * 2 + 1], inv, bb[q * 2 + 1]), 0.f);
        __half2 hh = __floats2half2_rn(v0, v1);
        hw[q] = *(uint32_t*)&hh;
    }
    *(uint4*)(oh + (size_t)w * Hd + 8 * lane) = hs;
}

// --------------- pooling: contiguous per-graph sum (batch sorted) -----------
__global__ __launch_bounds__(128) void k_pool_g(const float* __restrict__ hg,
                                                float* __restrict__ out)
{
    int g = blockIdx.x;
    int c = blockIdx.y * 128 + threadIdx.x;
    int beg = g_gstart[g], end = g_gstart[g + 1];
    float s = 0.f;
    for (int n = beg; n < end; n++) s += hg[(size_t)n * Hd + c];
    out[(size_t)g * (2 * Hd) + c] = s;
}

__global__ __launch_bounds__(256) void k_super(const float* __restrict__ Wf,
                                               const float* __restrict__ bf,
                                               float* __restrict__ out)
{
    __shared__ float s[Hd];
    int j = threadIdx.x;
    float sum = 0.f;
    for (int g = 0; g < Gg; g++) sum += out[(size_t)g * (2 * Hd) + j];
    s[j] = sum / (float)Gg;
    __syncthreads();
    float v = bf[j];
    #pragma unroll 8
    for (int c = 0; c < Hd; c++) v = fmaf(s[c], Wf[(size_t)j * Hd + c], v);
    v = fmaxf(v, 0.f);
    for (int g = 0; g < Gg; g++) out[(size_t)g * (2 * Hd) + Hd + j] = v;
}

// ------------------------------ launch --------------------------------------
extern "C" void kernel_launch(void* const* d_in, const int* in_sizes, int n_in,
                              void* d_out, int out_size)
{
    const float* x      = (const float*)d_in[0];
    const int*   ei32   = (const int*)d_in[1];
    const int*   b32    = (const int*)d_in[2];
    const float* W0     = (const float*)d_in[3];
    const float* a_src0 = (const float*)d_in[4];
    const float* a_dst0 = (const float*)d_in[5];
    const float* b0     = (const float*)d_in[6];
    const float* W1     = (const float*)d_in[7];
    const float* a_src1 = (const float*)d_in[8];
    const float* a_dst1 = (const float*)d_in[9];
    const float* b1     = (const float*)d_in[10];
    const float* W_ih   = (const float*)d_in[11];
    /* d_in[12] = W_hh: unused (h0 = 0) */
    const float* b_ih   = (const float*)d_in[13];
    const float* b_hh   = (const float*)d_in[14];
    const float* Wf     = (const float*)d_in[15];
    const float* bf     = (const float*)d_in[16];
    float*       out    = (float*)d_out;

    float *xp, *ssrc0, *sdst0, *ssrc1, *sdst1;
    __half *xp16, *ah, *bt0h, *bt1h, *bihh;
    cudaGetSymbolAddress((void**)&xp,    g_xp);
    cudaGetSymbolAddress((void**)&xp16,  g_xp16);
    cudaGetSymbolAddress((void**)&ssrc0, g_ssrc0);
    cudaGetSymbolAddress((void**)&sdst0, g_sdst0);
    cudaGetSymbolAddress((void**)&ssrc1, g_ssrc1);
    cudaGetSymbolAddress((void**)&sdst1, g_sdst1);
    cudaGetSymbolAddress((void**)&ah,    g_ah);
    cudaGetSymbolAddress((void**)&bt0h,  g_bt0h);
    cudaGetSymbolAddress((void**)&bt1h,  g_bt1h);
    cudaGetSymbolAddress((void**)&bihh,  g_bihh);

    const int SMEM  = 2 * BUF1;                          // 40960
    const int SMEMG = 2 * BUF1 + 2 * 128 * STSTR * 2;    // 107520
    cudaFuncSetAttribute(k_mm_f16, cudaFuncAttributeMaxDynamicSharedMemorySize, SMEM);
    cudaFuncSetAttribute(k_mm_gru, cudaFuncAttributeMaxDynamicSharedMemorySize, SMEMG);

    // one-time side stream + fork/join events (resource init only)
    static cudaStream_t s2 = nullptr;
    static cudaEvent_t evF = nullptr, evJ = nullptr;
    if (s2 == nullptr) {
        cudaStreamCreateWithFlags(&s2, cudaStreamNonBlocking);
        cudaEventCreateWithFlags(&evF, cudaEventDisableTiming);
        cudaEventCreateWithFlags(&evJ, cudaEventDisableTiming);
    }

    const int MT = (Nn + 127) / 128;   // 391
    dim3 blk(256);

    // ---- fork: CSR/decode branch on s2, weight/A-prep + L0 GEMM on main ----
    cudaEventRecord(evF, 0);
    cudaStreamWaitEvent(s2, evF, 0);

    // branch B (s2): index decode + CSR build + graph boundaries
    k_detect<<<1, 32, 0, s2>>>(ei32);
    k_decode_batch<<<(Nn + 255) / 256, blk, 0, s2>>>(b32);
    k_decode_count<<<(Ee + 255) / 256, blk, 0, s2>>>(ei32);
    k_scan_a<<<NSB, SCB, 0, s2>>>();
    k_scan_b<<<1, 128, 0, s2>>>();
    k_scan_c<<<NSB, SCB, 0, s2>>>();
    k_fill<<<(Ee + 255) / 256, blk, 0, s2>>>();
    k_gstart<<<1, Gg + 1, 0, s2>>>();
    cudaEventRecord(evJ, s2);

    // branch A (main): prep weights (+ zero scratch), convert x, L0 GEMM
    k_prep_w<<<(768 * 256 + 255) / 256, blk>>>(W0, W1, W_ih);
    k_split_x<<<(Nn * INC / 4 + 255) / 256, blk>>>(x, Nn * INC / 4);
    k_mm_f16<<<dim3(2, MT), blk, SMEM>>>(ah, bt0h, xp16,
                                         a_src0, a_dst0, ssrc0, sdst0, Nn, Hd, INC);

    // ---- join: everything below needs both branches ----
    cudaStreamWaitEvent(0, evJ, 0);

    // ---- GAT layer 0: edge weights + aggregate ----
    k_edgep<<<(Ee + 255) / 256, blk>>>(ssrc0, sdst0);
    k_gather<<<(Nn * 32 + 255) / 256, blk>>>(xp16, b0, ssrc0, sdst0, ah);

    // ---- GAT layer 1 (fp16) + fused attention dots ----
    k_mm_f16<<<dim3(2, MT), blk, SMEM>>>(ah, bt1h, xp16,
                                         a_src1, a_dst1, ssrc1, sdst1, Nn, Hd, Hd);
    k_edgep<<<(Ee + 255) / 256, blk>>>(ssrc1, sdst1);
    k_gather<<<(Nn * 32 + 255) / 256, blk>>>(xp16, b1, ssrc1, sdst1, ah);

    // ---- fused GRU GEMM + gates -> h (xp fp32) ----
    k_mm_gru<<<dim3(2, MT), blk, SMEMG>>>(ah, bihh, b_ih, b_hh, xp, Nn);

    // ---- pooling + super node ----
    k_pool_g<<<dim3(Gg, 2), 128>>>(xp, out);
    k_super<<<1, Hd>>>(Wf, bf, out);
}